// round 10
// baseline (speedup 1.0000x reference)
#include <cuda_runtime.h>
#include <cuda_bf16.h>
#include <mma.h>
#include <math.h>
#include <stdint.h>

using namespace nvcuda;

// ---------------- problem constants ----------------
constexpr int Bg   = 256;     // graphs
constexpr int NPG  = 400;     // nodes per graph
constexpr int Ntot = Bg * NPG;        // 102400
constexpr int EPG  = 8000;    // edges per graph
constexpr int Etot = Bg * EPG;        // 2048000
constexpr int CIN  = 400;
constexpr int H    = 64;
constexpr int H3   = 128;
constexpr int KEEP = 200;
constexpr int AT   = 512;     // agg kernel threads
constexpr int AW   = AT / 32; // 16 warps
#define BN_RS 0.99999500003749968f  /* rsqrt(1+1e-5) */

// ---------------- scratch (device globals; no allocation allowed) ----------------
__device__ float g_xw1[Ntot * H];
__device__ float g_h1 [Ntot * H];
__device__ float g_xw2[Ntot * H];
__device__ float g_h2 [Ntot * H];
__device__ float g_xw3[Ntot * H3];
__device__ float g_dis [Ntot];
__device__ float g_mask[Ntot];
__device__ float g_gate[Ntot];
__device__ float g_emb[Bg * 4 * H];   // [B, 256]
// prebuilt per-graph CSR buckets (built by agg1, reused by agg2)
__device__ unsigned short g_ebsrc[Etot];
__device__ float g_ebw[Etot];
__device__ int   g_eoff[Ntot];        // inclusive per-graph-local offsets
// split bf16 weights, row-major [KPAD][CO]
__device__ __nv_bfloat16 g_w1h[448 * 64];
__device__ __nv_bfloat16 g_w1l[448 * 64];
__device__ __nv_bfloat16 g_w2h[64 * 64];
__device__ __nv_bfloat16 g_w2l[64 * 64];
__device__ __nv_bfloat16 g_w3h[64 * 128];
__device__ __nv_bfloat16 g_w3l[64 * 128];

__device__ __forceinline__ uint32_t pack_bf2(__nv_bfloat16 a, __nv_bfloat16 b) {
    __nv_bfloat162 t = __halves2bfloat162(a, b);
    return *reinterpret_cast<uint32_t*>(&t);
}
__device__ __forceinline__ void cvt_split(float4 v, uint2& hi, uint2& lo) {
    __nv_bfloat16 h0 = __float2bfloat16(v.x);
    __nv_bfloat16 h1 = __float2bfloat16(v.y);
    __nv_bfloat16 h2 = __float2bfloat16(v.z);
    __nv_bfloat16 h3 = __float2bfloat16(v.w);
    hi = make_uint2(pack_bf2(h0, h1), pack_bf2(h2, h3));
    lo = make_uint2(pack_bf2(__float2bfloat16(v.x - __bfloat162float(h0)),
                             __float2bfloat16(v.y - __bfloat162float(h1))),
                    pack_bf2(__float2bfloat16(v.z - __bfloat162float(h2)),
                             __float2bfloat16(v.w - __bfloat162float(h3))));
}

// ---------------- all-weights bf16 split (single launch) ----------------
__global__ void wconv_all_kernel(const float* __restrict__ W1, const float* __restrict__ W2,
                                 const float* __restrict__ W3,
                                 __nv_bfloat16* __restrict__ w1h, __nv_bfloat16* __restrict__ w1l,
                                 __nv_bfloat16* __restrict__ w2h, __nv_bfloat16* __restrict__ w2l,
                                 __nv_bfloat16* __restrict__ w3h, __nv_bfloat16* __restrict__ w3l) {
    int i = blockIdx.x * 256 + threadIdx.x;
    const float* W; __nv_bfloat16 *hi, *lo; int idx; int kdim, co;
    if (i < 448 * 64)            { W = W1; hi = w1h; lo = w1l; idx = i;             kdim = 400; co = 64; }
    else if (i < 448*64 + 64*64) { W = W2; hi = w2h; lo = w2l; idx = i - 448*64;    kdim = 64;  co = 64; }
    else if (i < 448*64 + 64*64 + 64*128)
                                 { W = W3; hi = w3h; lo = w3l; idx = i - 448*64 - 64*64; kdim = 64; co = 128; }
    else return;
    int k = idx / co;
    float v = (k < kdim) ? W[idx] : 0.f;
    __nv_bfloat16 h = __float2bfloat16(v);
    hi[idx] = h;
    lo[idx] = __float2bfloat16(v - __bfloat162float(h));
}

// ---------------- wmma bf16x3 GEMM: out[M,CO] = X[M,KDIM] @ W[KDIM,CO] ----------------
// KCH>1: software-pipelined (register-staged next chunk, double-buffered smem).
template<int CO, int KDIM, bool SCALE>
__global__ void __launch_bounds__(256) wgemm_kernel(
        const float* __restrict__ X,
        const __nv_bfloat16* __restrict__ wh,
        const __nv_bfloat16* __restrict__ wl,
        const float* __restrict__ rowscale,
        float* __restrict__ out) {
    constexpr int KCH  = (KDIM + 63) / 64;
    constexpr int LDA  = 72;
    constexpr int LDB  = CO + 8;
    constexpr int NT   = CO / 16;
    constexpr int NBUF = (KCH > 1) ? 2 : 1;
    constexpr int ABUF = 2 * 128 * LDA;     // elems (hi+lo) per buffer
    constexpr int BBUF = 2 * 64 * LDB;
    constexpr int BUFE = ABUF + BBUF;

    extern __shared__ char smraw[];
    __nv_bfloat16* base = (__nv_bfloat16*)smraw;
    float* sOut = (float*)smraw;            // union for epilogue

    const int tid  = threadIdx.x;
    const int warp = tid >> 5;
    const int rb   = blockIdx.x * 128;

    wmma::fragment<wmma::accumulator, 16, 16, 16, float> acc[NT];
    #pragma unroll
    for (int t = 0; t < NT; t++) wmma::fill_fragment(acc[t], 0.f);

    auto do_mma = [&](int buf) {
        __nv_bfloat16* Ah = base + buf * BUFE;
        __nv_bfloat16* Al = Ah + 128 * LDA;
        __nv_bfloat16* Bh = Al + 128 * LDA;
        __nv_bfloat16* Bl = Bh + 64 * LDB;
        const __nv_bfloat16* arow_h = Ah + (warp * 16) * LDA;
        const __nv_bfloat16* arow_l = Al + (warp * 16) * LDA;
        #pragma unroll
        for (int k16 = 0; k16 < 4; k16++) {
            wmma::fragment<wmma::matrix_a, 16, 16, 16, __nv_bfloat16, wmma::row_major> fa_h, fa_l;
            wmma::load_matrix_sync(fa_h, arow_h + k16 * 16, LDA);
            wmma::load_matrix_sync(fa_l, arow_l + k16 * 16, LDA);
            #pragma unroll
            for (int t = 0; t < NT; t++) {
                wmma::fragment<wmma::matrix_b, 16, 16, 16, __nv_bfloat16, wmma::row_major> fb_h, fb_l;
                wmma::load_matrix_sync(fb_h, Bh + (k16 * 16) * LDB + t * 16, LDB);
                wmma::load_matrix_sync(fb_l, Bl + (k16 * 16) * LDB + t * 16, LDB);
                wmma::mma_sync(acc[t], fa_h, fb_h, acc[t]);
                wmma::mma_sync(acc[t], fa_h, fb_l, acc[t]);
                wmma::mma_sync(acc[t], fa_l, fb_h, acc[t]);
            }
        }
    };

    if constexpr (KCH == 1) {
        // ---- direct single-chunk path ----
        __nv_bfloat16* Ah = base;
        __nv_bfloat16* Al = Ah + 128 * LDA;
        __nv_bfloat16* Bh = Al + 128 * LDA;
        __nv_bfloat16* Bl = Bh + 64 * LDB;
        #pragma unroll 2
        for (int i = tid * 4; i < 128 * 64; i += 1024) {
            int r = i >> 6, c = i & 63;
            float4 v = *(const float4*)&X[(size_t)(rb + r) * KDIM + c];
            uint2 hi, lo;
            cvt_split(v, hi, lo);
            *(uint2*)&Ah[r * LDA + c] = hi;
            *(uint2*)&Al[r * LDA + c] = lo;
        }
        #pragma unroll 2
        for (int i = tid * 4; i < 64 * CO; i += 1024) {
            int r = i / CO, c = i & (CO - 1);
            *(uint2*)&Bh[r * LDB + c] = *(const uint2*)&wh[(size_t)r * CO + c];
            *(uint2*)&Bl[r * LDB + c] = *(const uint2*)&wl[(size_t)r * CO + c];
        }
        __syncthreads();
        do_mma(0);
    } else {
        // ---- pipelined path: register-stage next chunk during MMA ----
        float4 areg[8];
        uint2  bregh[CO / 16], bregl[CO / 16];
        auto load_chunk = [&](int ch) {
            const int kb = ch * 64;
            #pragma unroll
            for (int u = 0; u < 8; u++) {
                int i = tid * 4 + u * 1024;
                int r = i >> 6, c = i & 63;
                if ((KDIM & 63) == 0 || kb + c < KDIM)
                    areg[u] = *(const float4*)&X[(size_t)(rb + r) * KDIM + kb + c];
                else
                    areg[u] = make_float4(0.f, 0.f, 0.f, 0.f);
            }
            #pragma unroll
            for (int u = 0; u < CO / 16; u++) {
                int i = tid * 4 + u * 1024;
                int r = i / CO, c = i & (CO - 1);
                bregh[u] = *(const uint2*)&wh[(size_t)(kb + r) * CO + c];
                bregl[u] = *(const uint2*)&wl[(size_t)(kb + r) * CO + c];
            }
        };
        auto store_chunk = [&](int buf) {
            __nv_bfloat16* Ah = base + buf * BUFE;
            __nv_bfloat16* Al = Ah + 128 * LDA;
            __nv_bfloat16* Bh = Al + 128 * LDA;
            __nv_bfloat16* Bl = Bh + 64 * LDB;
            #pragma unroll
            for (int u = 0; u < 8; u++) {
                int i = tid * 4 + u * 1024;
                int r = i >> 6, c = i & 63;
                uint2 hi, lo;
                cvt_split(areg[u], hi, lo);
                *(uint2*)&Ah[r * LDA + c] = hi;
                *(uint2*)&Al[r * LDA + c] = lo;
            }
            #pragma unroll
            for (int u = 0; u < CO / 16; u++) {
                int i = tid * 4 + u * 1024;
                int r = i / CO, c = i & (CO - 1);
                *(uint2*)&Bh[r * LDB + c] = bregh[u];
                *(uint2*)&Bl[r * LDB + c] = bregl[u];
            }
        };
        load_chunk(0);
        store_chunk(0);
        __syncthreads();
        for (int ch = 0; ch < KCH; ch++) {
            if (ch + 1 < KCH) load_chunk(ch + 1);   // LDGs in flight during MMA
            do_mma(ch & 1);
            if (ch + 1 < KCH) {
                store_chunk((ch + 1) & 1);
                __syncthreads();
            }
        }
    }

    __syncthreads();
    #pragma unroll
    for (int t = 0; t < NT; t++)
        wmma::store_matrix_sync(sOut + (warp * 16) * LDB + t * 16, acc[t], LDB,
                                wmma::mem_row_major);
    __syncthreads();
    #pragma unroll 2
    for (int i = tid * 4; i < 128 * CO; i += 1024) {
        int r = i / CO, c = i & (CO - 1);
        float4 v = *(float4*)&sOut[r * LDB + c];
        float rs = 1.f;
        if (SCALE) rs = rowscale[rb + r];
        v.x *= rs; v.y *= rs; v.z *= rs; v.w *= rs;
        *(float4*)&out[(size_t)(rb + r) * CO + c] = v;
    }
}

constexpr int wg_smem(int CO, int KDIM) {
    int kch  = (KDIM + 63) / 64;
    int nbuf = (kch > 1) ? 2 : 1;
    int lda = 72, ldb = CO + 8;
    int ab = nbuf * (2 * 128 * lda + 2 * 64 * ldb) * 2;
    int os = 128 * ldb * 4;
    return ab > os ? ab : os;
}

// ---------------- shared gather helper: 4x-unrolled CSR edge accumulation ----------------
__device__ __forceinline__ void gather_row(const unsigned short* __restrict__ bsrc,
                                           const float* __restrict__ bw,
                                           const float* __restrict__ ysm,
                                           int e0, int e1, int lane,
                                           float& a0, float& a1) {
    int j = e0;
    for (; j + 4 <= e1; j += 4) {
        int s0 = bsrc[j], s1 = bsrc[j + 1], s2 = bsrc[j + 2], s3 = bsrc[j + 3];
        float w0 = bw[j], w1 = bw[j + 1], w2 = bw[j + 2], w3 = bw[j + 3];
        float y00 = ysm[s0 * H + lane],      y01 = ysm[s0 * H + lane + 32];
        float y10 = ysm[s1 * H + lane],      y11 = ysm[s1 * H + lane + 32];
        float y20 = ysm[s2 * H + lane],      y21 = ysm[s2 * H + lane + 32];
        float y30 = ysm[s3 * H + lane],      y31 = ysm[s3 * H + lane + 32];
        a0 = fmaf(w0, y00, a0); a1 = fmaf(w0, y01, a1);
        a0 = fmaf(w1, y10, a0); a1 = fmaf(w1, y11, a1);
        a0 = fmaf(w2, y20, a0); a1 = fmaf(w2, y21, a1);
        a0 = fmaf(w3, y30, a0); a1 = fmaf(w3, y31, a1);
    }
    for (; j < e1; j++) {
        int sl = bsrc[j];
        float w = bw[j];
        a0 = fmaf(w, ysm[sl * H + lane],      a0);
        a1 = fmaf(w, ysm[sl * H + lane + 32], a1);
    }
}

// ======================================================================
// agg1: fused degree/dis + CSR build + store + gather + bias/BN/ReLU
// ======================================================================
constexpr int SMEM_AGG64 = (NPG*H + NPG)*4 + (NPG + 512)*4 + EPG*2 + EPG*4;

__global__ void __launch_bounds__(AT) agg1_kernel(
                            const float* __restrict__ xw,
                            const int* __restrict__ src, const int* __restrict__ dstp,
                            const float* __restrict__ ew,
                            const float* __restrict__ bias, const float* __restrict__ gam,
                            const float* __restrict__ bet, float* __restrict__ out,
                            float* __restrict__ dis_out,
                            unsigned short* __restrict__ ebsrc_out,
                            float* __restrict__ ebw_out, int* __restrict__ eoff_out) {
    extern __shared__ float smf[];
    float* ysm = smf;
    float* dsm = ysm + NPG * H;
    int*   cn  = (int*)(dsm + NPG);
    int*   sc  = cn + NPG;
    unsigned short* bsrc = (unsigned short*)(sc + 512);
    float* bw  = (float*)(bsrc + EPG);

    const int g = blockIdx.x;
    const int nb = g * NPG;
    const int eb = g * EPG;
    const int tid = threadIdx.x;

    for (int i = tid; i < NPG; i += AT) { dsm[i] = 1.0f; cn[i] = 0; }
    __syncthreads();

    // pass 1: per-dst edge count + weighted degree
    for (int e = tid; e < EPG; e += AT) {
        int dl = dstp[eb + e] - nb;
        float w = ew[eb + e];
        atomicAdd(&cn[dl], 1);
        atomicAdd(&dsm[dl], w);
    }
    __syncthreads();
    for (int i = tid; i < NPG; i += AT) {
        float d = rsqrtf(dsm[i]);           // deg >= 1
        dsm[i] = d;
        dis_out[nb + i] = d;
    }
    __syncthreads();

    // ysm = dis * xW
    for (int i = tid * 4; i < NPG * H; i += AT * 4) {
        int node = i >> 6;
        float4 v = *(const float4*)&xw[(size_t)(nb + node) * H + (i & 63)];
        float d = dsm[node];
        v.x *= d; v.y *= d; v.z *= d; v.w *= d;
        *(float4*)&ysm[i] = v;
    }
    // inclusive scan of counts
    sc[tid] = (tid < NPG) ? cn[tid] : 0;
    __syncthreads();
    #pragma unroll
    for (int off = 1; off < 512; off <<= 1) {
        int v = sc[tid];
        int a = (tid >= off) ? sc[tid - off] : 0;
        __syncthreads();
        sc[tid] = v + a;
        __syncthreads();
    }
    for (int i = tid; i < NPG; i += AT) { cn[i] = 0; eoff_out[nb + i] = sc[i]; }
    __syncthreads();

    // scatter edges into buckets
    for (int e = tid; e < EPG; e += AT) {
        int sl = src[eb + e] - nb;
        int dl = dstp[eb + e] - nb;
        int pos = (dl ? sc[dl - 1] : 0) + atomicAdd(&cn[dl], 1);
        bsrc[pos] = (unsigned short)sl;
        bw[pos]   = ew[eb + e];
    }
    __syncthreads();

    // persist buckets for agg2
    for (int i = tid * 8; i < EPG; i += AT * 8)
        *(uint4*)&ebsrc_out[eb + i] = *(const uint4*)&bsrc[i];
    for (int i = tid * 4; i < EPG; i += AT * 4)
        *(float4*)&ebw_out[eb + i] = *(const float4*)&bw[i];

    // gather + epilogue
    const int lane = tid & 31;
    const int warp = tid >> 5;
    const float s0 = gam[lane] * BN_RS,      s1 = gam[lane + 32] * BN_RS;
    const float t0 = bet[lane],              t1 = bet[lane + 32];
    const float bb0 = bias[lane],            bb1 = bias[lane + 32];
    for (int dl = warp; dl < NPG; dl += AW) {
        int e0 = dl ? sc[dl - 1] : 0;
        int e1 = sc[dl];
        float a0 = ysm[dl * H + lane];
        float a1 = ysm[dl * H + lane + 32];
        gather_row(bsrc, bw, ysm, e0, e1, lane, a0, a1);
        float d = dsm[dl];
        float v0 = fmaf(d, a0, bb0);
        float v1 = fmaf(d, a1, bb1);
        v0 = fmaxf(fmaf(v0, s0, t0), 0.f);
        v1 = fmaxf(fmaf(v1, s1, t1), 0.f);
        size_t o = (size_t)(nb + dl) * H;
        out[o + lane] = v0;
        out[o + lane + 32] = v1;
    }
}

// ======================================================================
// agg2: reuse prebuilt CSR + dis; gather + bias/BN/ReLU + fused score +
//       fused per-graph top-k (bitonic in smem) -> mask/gate
// ======================================================================
__global__ void __launch_bounds__(AT) agg2_kernel(
                            const float* __restrict__ xw, const float* __restrict__ dis,
                            const unsigned short* __restrict__ ebsrc,
                            const float* __restrict__ ebw, const int* __restrict__ eoff,
                            const float* __restrict__ ew_p,   // pool vector
                            const float* __restrict__ bias, const float* __restrict__ gam,
                            const float* __restrict__ bet, float* __restrict__ out,
                            float* __restrict__ mask, float* __restrict__ gate) {
    extern __shared__ float smf[];
    float* ysm = smf;
    float* dsm = ysm + NPG * H;
    int*   cn  = (int*)(dsm + NPG);       // reused as score array
    int*   sc  = cn + NPG;
    unsigned short* bsrc = (unsigned short*)(sc + 512);
    float* bw  = (float*)(bsrc + EPG);
    float* ssc = (float*)cn;              // [NPG] scores

    const int g = blockIdx.x;
    const int nb = g * NPG;
    const int eb = g * EPG;
    const int tid = threadIdx.x;

    for (int i = tid; i < NPG; i += AT) {
        dsm[i] = dis[nb + i];
        sc[i]  = eoff[nb + i];
    }
    for (int i = tid * 8; i < EPG; i += AT * 8)
        *(uint4*)&bsrc[i] = *(const uint4*)&ebsrc[eb + i];
    for (int i = tid * 4; i < EPG; i += AT * 4)
        *(float4*)&bw[i] = *(const float4*)&ebw[eb + i];
    __syncthreads();

    for (int i = tid * 4; i < NPG * H; i += AT * 4) {
        int node = i >> 6;
        float4 v = *(const float4*)&xw[(size_t)(nb + node) * H + (i & 63)];
        float d = dsm[node];
        v.x *= d; v.y *= d; v.z *= d; v.w *= d;
        *(float4*)&ysm[i] = v;
    }
    __syncthreads();

    const int lane = tid & 31;
    const int warp = tid >> 5;
    const float s0 = gam[lane] * BN_RS,      s1 = gam[lane + 32] * BN_RS;
    const float t0 = bet[lane],              t1 = bet[lane + 32];
    const float bb0 = bias[lane],            bb1 = bias[lane + 32];
    const float p0 = ew_p[lane], p1 = ew_p[lane + 32];
    float pn = p0 * p0 + p1 * p1;
    #pragma unroll
    for (int o = 16; o; o >>= 1) pn += __shfl_xor_sync(0xffffffffu, pn, o);
    const float ipn = rsqrtf(pn);

    for (int dl = warp; dl < NPG; dl += AW) {
        int e0 = dl ? sc[dl - 1] : 0;
        int e1 = sc[dl];
        float a0 = ysm[dl * H + lane];
        float a1 = ysm[dl * H + lane + 32];
        gather_row(bsrc, bw, ysm, e0, e1, lane, a0, a1);
        float d = dsm[dl];
        float v0 = fmaf(d, a0, bb0);
        float v1 = fmaf(d, a1, bb1);
        v0 = fmaxf(fmaf(v0, s0, t0), 0.f);
        v1 = fmaxf(fmaf(v1, s1, t1), 0.f);
        size_t o = (size_t)(nb + dl) * H;
        out[o + lane] = v0;
        out[o + lane + 32] = v1;
        float dsc = v0 * p0 + v1 * p1;
        #pragma unroll
        for (int of = 16; of; of >>= 1) dsc += __shfl_xor_sync(0xffffffffu, dsc, of);
        if (lane == 0) ssc[dl] = tanhf(dsc * ipn);
    }
    __syncthreads();   // scores done; ysm now dead -> reuse for sort

    float* sortb = ysm;                       // [512]
    unsigned char* km = (unsigned char*)(ysm + 512);   // [NPG]
    int* cntp = (int*)(ysm + 1024);
    for (int i = tid; i < 512; i += AT) sortb[i] = (i < NPG) ? ssc[i] : -INFINITY;
    if (tid == 0) *cntp = 0;
    __syncthreads();
    // bitonic sort ascending, 512 elems, 1 elem/thread
    #pragma unroll
    for (int k = 2; k <= 512; k <<= 1) {
        #pragma unroll
        for (int j = k >> 1; j > 0; j >>= 1) {
            int ixj = tid ^ j;
            if (ixj > tid) {
                float a = sortb[tid], b = sortb[ixj];
                bool sw = ((tid & k) == 0) ? (a > b) : (a < b);
                if (sw) { sortb[tid] = b; sortb[ixj] = a; }
            }
            __syncthreads();
        }
    }
    float thr = sortb[512 - KEEP];     // 200th largest
    int local = 0;
    for (int i = tid; i < NPG; i += AT)
        if (ssc[i] > thr) local++;
    atomicAdd(cntp, local);
    __syncthreads();
    if (tid == 0) {   // tie-break: lowest index first (matches lax.top_k)
        int rem = KEEP - *cntp;
        for (int i = 0; i < NPG; i++) {
            unsigned char m = (ssc[i] > thr) ? 1 : 0;
            if (!m && ssc[i] == thr && rem > 0) { m = 1; rem--; }
            km[i] = m;
        }
    }
    __syncthreads();
    for (int i = tid; i < NPG; i += AT) {
        float m = km[i] ? 1.f : 0.f;
        mask[nb + i] = m;
        gate[nb + i] = m * ssc[i];
    }
}

// ======================================================================
// agg3: fused dis3 + masked CSR + gather + bias/BN/ReLU + mean/max readout
// ======================================================================
constexpr int SMEM_AGG3 = (NPG*H + 2*NPG)*4 + (NPG + 512)*4 + EPG*2 + EPG*4 + 2 * AW * 64 * 4;

__global__ void __launch_bounds__(AT) agg3_kernel(
                            const float* __restrict__ xw,
                            const float* __restrict__ mask,
                            const int* __restrict__ src, const int* __restrict__ dstp,
                            const float* __restrict__ ew,
                            const float* __restrict__ bias, const float* __restrict__ gam,
                            const float* __restrict__ bet, float* __restrict__ emb) {
    extern __shared__ float smf[];
    float* ysm = smf;
    float* dsm = ysm + NPG * H;
    float* msm = dsm + NPG;
    int*   cn  = (int*)(msm + NPG);
    int*   sc  = cn + NPG;
    unsigned short* bsrc = (unsigned short*)(sc + 512);
    float* bw   = (float*)(bsrc + EPG);
    float* psum = bw + EPG;              // [AW][64]
    float* pmax = psum + AW * 64;        // [AW][64]

    const int g = blockIdx.x;
    const int nb = g * NPG;
    const int eb = g * EPG;
    const int tid = threadIdx.x;

    for (int i = tid; i < NPG; i += AT) {
        float m = mask[nb + i];
        msm[i] = m;
        dsm[i] = m;          // degree init = self-loop weight (mask)
        cn[i] = 0;
    }
    __syncthreads();

    // pass 1: masked count + weighted degree
    for (int e = tid; e < EPG; e += AT) {
        int sl = src[eb + e] - nb;
        int dl = dstp[eb + e] - nb;
        if (msm[sl] != 0.f && msm[dl] != 0.f) {
            atomicAdd(&cn[dl], 1);
            atomicAdd(&dsm[dl], ew[eb + e]);
        }
    }
    __syncthreads();
    for (int i = tid; i < NPG; i += AT) {
        float v = dsm[i];
        dsm[i] = (v > 0.f) ? rsqrtf(fmaxf(v, 1e-12f)) : 0.f;
    }
    __syncthreads();

    sc[tid] = (tid < NPG) ? cn[tid] : 0;
    __syncthreads();
    #pragma unroll
    for (int off = 1; off < 512; off <<= 1) {
        int v = sc[tid];
        int a = (tid >= off) ? sc[tid - off] : 0;
        __syncthreads();
        sc[tid] = v + a;
        __syncthreads();
    }
    for (int i = tid; i < NPG; i += AT) cn[i] = 0;
    __syncthreads();
    for (int e = tid; e < EPG; e += AT) {
        int sl = src[eb + e] - nb;
        int dl = dstp[eb + e] - nb;
        if (msm[sl] != 0.f && msm[dl] != 0.f) {
            int pos = (dl ? sc[dl - 1] : 0) + atomicAdd(&cn[dl], 1);
            bsrc[pos] = (unsigned short)sl;
            bw[pos]   = ew[eb + e];
        }
    }

    const int lane = tid & 31;
    const int warp = tid >> 5;
    #pragma unroll
    for (int hf = 0; hf < 2; hf++) {
        __syncthreads();
        for (int i = tid * 4; i < NPG * H; i += AT * 4) {
            int node = i >> 6;
            float4 v = *(const float4*)&xw[(size_t)(nb + node) * H3 + hf * H + (i & 63)];
            float d = dsm[node];
            v.x *= d; v.y *= d; v.z *= d; v.w *= d;
            *(float4*)&ysm[i] = v;
        }
        __syncthreads();
        const int f0 = hf * H + lane, f1 = hf * H + lane + 32;
        const float s0 = gam[f0] * BN_RS, s1 = gam[f1] * BN_RS;
        const float t0 = bet[f0],         t1 = bet[f1];
        const float bb0 = bias[f0],       bb1 = bias[f1];
        float sum0 = 0.f, sum1 = 0.f, mx0 = -INFINITY, mx1 = -INFINITY;
        for (int dl = warp; dl < NPG; dl += AW) {
            if (msm[dl] == 0.f) continue;
            int e0 = dl ? sc[dl - 1] : 0;
            int e1 = sc[dl];
            float a0 = ysm[dl * H + lane];
            float a1 = ysm[dl * H + lane + 32];
            gather_row(bsrc, bw, ysm, e0, e1, lane, a0, a1);
            float d = dsm[dl];
            float v0 = fmaf(d, a0, bb0);
            float v1 = fmaf(d, a1, bb1);
            v0 = fmaxf(fmaf(v0, s0, t0), 0.f);
            v1 = fmaxf(fmaf(v1, s1, t1), 0.f);
            sum0 += v0; sum1 += v1;
            mx0 = fmaxf(mx0, v0); mx1 = fmaxf(mx1, v1);
        }
        psum[warp * 64 + lane]      = sum0;
        psum[warp * 64 + lane + 32] = sum1;
        pmax[warp * 64 + lane]      = mx0;
        pmax[warp * 64 + lane + 32] = mx1;
        __syncthreads();
        if (tid < 64) {   // deterministic fixed-order combine
            float s = 0.f, m = -INFINITY;
            #pragma unroll
            for (int w = 0; w < AW; w++) {
                s += psum[w * 64 + tid];
                m = fmaxf(m, pmax[w * 64 + tid]);
            }
            emb[g * 256 + hf * 64 + tid]       = s * (1.f / KEEP);
            emb[g * 256 + 128 + hf * 64 + tid] = m;
        }
    }
}

// ---------------- MLP head ----------------
__global__ void head_kernel(const float* __restrict__ emb,
                            const float* __restrict__ f1w, const float* __restrict__ f1b,
                            const float* __restrict__ gfc, const float* __restrict__ bfc,
                            const float* __restrict__ f2w, const float* __restrict__ f2b,
                            float* __restrict__ out) {
    __shared__ float z[64];
    const int g = blockIdx.x, j = threadIdx.x;
    float acc = f1b[j];
    const float* e = &emb[g * 256];
    #pragma unroll 8
    for (int k = 0; k < 256; k++)
        acc = fmaf(e[k], f1w[k * 64 + j], acc);
    acc = fmaf(acc, gfc[j] * BN_RS, bfc[j]);
    z[j] = fmaxf(acc, 0.f);
    __syncthreads();
    if (j < 2) {
        float o = f2b[j];
        for (int k = 0; k < 64; k++)
            o = fmaf(z[k], f2w[k * 2 + j], o);
        out[g * 2 + j] = o;
    }
}

// ---------------- launch ----------------
extern "C" void kernel_launch(void* const* d_in, const int* in_sizes, int n_in,
                              void* d_out, int out_size) {
    const float* x   = (const float*)d_in[0];
    const int*   ei  = (const int*)  d_in[1];
    const float* ew  = (const float*)d_in[2];
    const float* W1  = (const float*)d_in[4];
    const float* b1  = (const float*)d_in[5];
    const float* g1  = (const float*)d_in[6];
    const float* bt1 = (const float*)d_in[7];
    const float* W2  = (const float*)d_in[8];
    const float* b2  = (const float*)d_in[9];
    const float* g2  = (const float*)d_in[10];
    const float* bt2 = (const float*)d_in[11];
    const float* pp  = (const float*)d_in[12];
    const float* W3  = (const float*)d_in[13];
    const float* b3  = (const float*)d_in[14];
    const float* g3  = (const float*)d_in[15];
    const float* bt3 = (const float*)d_in[16];
    const float* f1w = (const float*)d_in[17];
    const float* f1b = (const float*)d_in[18];
    const float* gfc = (const float*)d_in[19];
    const float* bfc = (const float*)d_in[20];
    const float* f2w = (const float*)d_in[21];
    const float* f2b = (const float*)d_in[22];
    float* out = (float*)d_out;

    const int* src = ei;
    const int* dst = ei + Etot;

    float *p_xw1, *p_h1, *p_xw2, *p_h2, *p_xw3;
    float *p_dis, *p_mask, *p_gate, *p_emb, *p_ebw;
    unsigned short* p_ebsrc;
    int* p_eoff;
    __nv_bfloat16 *p_w1h, *p_w1l, *p_w2h, *p_w2l, *p_w3h, *p_w3l;
    cudaGetSymbolAddress((void**)&p_xw1,  g_xw1);
    cudaGetSymbolAddress((void**)&p_h1,   g_h1);
    cudaGetSymbolAddress((void**)&p_xw2,  g_xw2);
    cudaGetSymbolAddress((void**)&p_h2,   g_h2);
    cudaGetSymbolAddress((void**)&p_xw3,  g_xw3);
    cudaGetSymbolAddress((void**)&p_dis,  g_dis);
    cudaGetSymbolAddress((void**)&p_mask, g_mask);
    cudaGetSymbolAddress((void**)&p_gate, g_gate);
    cudaGetSymbolAddress((void**)&p_emb,  g_emb);
    cudaGetSymbolAddress((void**)&p_ebsrc,g_ebsrc);
    cudaGetSymbolAddress((void**)&p_ebw,  g_ebw);
    cudaGetSymbolAddress((void**)&p_eoff, g_eoff);
    cudaGetSymbolAddress((void**)&p_w1h,  g_w1h);
    cudaGetSymbolAddress((void**)&p_w1l,  g_w1l);
    cudaGetSymbolAddress((void**)&p_w2h,  g_w2h);
    cudaGetSymbolAddress((void**)&p_w2l,  g_w2l);
    cudaGetSymbolAddress((void**)&p_w3h,  g_w3h);
    cudaGetSymbolAddress((void**)&p_w3l,  g_w3l);

    constexpr int SM1 = wg_smem(64, 400);
    constexpr int SM2 = wg_smem(64, 64);
    constexpr int SM3 = wg_smem(128, 64);
    cudaFuncSetAttribute((const void*)wgemm_kernel<64, 400, false>,
                         cudaFuncAttributeMaxDynamicSharedMemorySize, SM1);
    cudaFuncSetAttribute((const void*)wgemm_kernel<64, 64, false>,
                         cudaFuncAttributeMaxDynamicSharedMemorySize, SM2);
    cudaFuncSetAttribute((const void*)wgemm_kernel<128, 64, true>,
                         cudaFuncAttributeMaxDynamicSharedMemorySize, SM3);
    cudaFuncSetAttribute(agg1_kernel, cudaFuncAttributeMaxDynamicSharedMemorySize, SMEM_AGG64);
    cudaFuncSetAttribute(agg2_kernel, cudaFuncAttributeMaxDynamicSharedMemorySize, SMEM_AGG64);
    cudaFuncSetAttribute(agg3_kernel, cudaFuncAttributeMaxDynamicSharedMemorySize, SMEM_AGG3);

    // 0: weight split
    wconv_all_kernel<<<(448*64 + 64*64 + 64*128 + 255) / 256, 256>>>(
        W1, W2, W3, p_w1h, p_w1l, p_w2h, p_w2l, p_w3h, p_w3l);

    // 1: GCN1 GEMM (pipelined)
    wgemm_kernel<64, 400, false><<<Ntot / 128, 256, SM1>>>(x, p_w1h, p_w1l, nullptr, p_xw1);
    // 2: GCN1 aggregation (fused degree + CSR build/persist)
    agg1_kernel<<<Bg, AT, SMEM_AGG64>>>(p_xw1, src, dst, ew, b1, g1, bt1, p_h1,
                                        p_dis, p_ebsrc, p_ebw, p_eoff);
    // 3: GCN2 GEMM
    wgemm_kernel<64, 64, false><<<Ntot / 128, 256, SM2>>>(p_h1, p_w2h, p_w2l, nullptr, p_xw2);
    // 4: GCN2 aggregation (reused CSR, fused score + topk -> mask/gate)
    agg2_kernel<<<Bg, AT, SMEM_AGG64>>>(p_xw2, p_dis, p_ebsrc, p_ebw, p_eoff, pp,
                                        b2, g2, bt2, p_h2, p_mask, p_gate);
    // 5: GCN3 GEMM (rows gated by score*mask)
    wgemm_kernel<128, 64, true><<<Ntot / 128, 256, SM3>>>(p_h2, p_w3h, p_w3l, p_gate, p_xw3);
    // 6: GCN3 aggregation (fused dis3 + masked CSR + readout)
    agg3_kernel<<<Bg, AT, SMEM_AGG3>>>(p_xw3, p_mask, src, dst, ew, b3, g3, bt3, p_emb);
    // 7: head
    head_kernel<<<Bg, 64>>>(p_emb, f1w, f1b, gfc, bfc, f2w, f2b, out);
}

// round 11
// speedup vs baseline: 1.0609x; 1.0609x over previous
#include <cuda_runtime.h>
#include <cuda_bf16.h>
#include <mma.h>
#include <math.h>
#include <stdint.h>

using namespace nvcuda;

// ---------------- problem constants ----------------
constexpr int Bg   = 256;     // graphs
constexpr int NPG  = 400;     // nodes per graph
constexpr int Ntot = Bg * NPG;        // 102400
constexpr int EPG  = 8000;    // edges per graph
constexpr int Etot = Bg * EPG;        // 2048000
constexpr int CIN  = 400;
constexpr int H    = 64;
constexpr int H3   = 128;
constexpr int KEEP = 200;
constexpr int AT   = 512;     // agg kernel threads
constexpr int AW   = AT / 32; // 16 warps
#define BN_RS 0.99999500003749968f  /* rsqrt(1+1e-5) */

// ---------------- scratch (device globals; no allocation allowed) ----------------
__device__ float g_xw1[Ntot * H];
__device__ float g_h1 [Ntot * H];
__device__ float g_xw2[Ntot * H];
__device__ float g_h2 [Ntot * H];
__device__ float g_xw3[Ntot * H3];
__device__ float g_dis [Ntot];
__device__ float g_mask[Ntot];
__device__ float g_gate[Ntot];
__device__ float g_emb[Bg * 4 * H];   // [B, 256]
// prebuilt per-graph CSR buckets (built by agg1, reused by agg2 AND agg3)
__device__ unsigned short g_ebsrc[Etot];
__device__ float g_ebw[Etot];
__device__ int   g_eoff[Ntot];        // inclusive per-graph-local offsets
// split bf16 weights, row-major [KPAD][CO]
__device__ __nv_bfloat16 g_w1h[448 * 64];
__device__ __nv_bfloat16 g_w1l[448 * 64];
__device__ __nv_bfloat16 g_w2h[64 * 64];
__device__ __nv_bfloat16 g_w2l[64 * 64];
__device__ __nv_bfloat16 g_w3h[64 * 128];
__device__ __nv_bfloat16 g_w3l[64 * 128];

__device__ __forceinline__ uint32_t pack_bf2(__nv_bfloat16 a, __nv_bfloat16 b) {
    __nv_bfloat162 t = __halves2bfloat162(a, b);
    return *reinterpret_cast<uint32_t*>(&t);
}

// ---------------- all-weights bf16 split (single launch) ----------------
__global__ void wconv_all_kernel(const float* __restrict__ W1, const float* __restrict__ W2,
                                 const float* __restrict__ W3,
                                 __nv_bfloat16* __restrict__ w1h, __nv_bfloat16* __restrict__ w1l,
                                 __nv_bfloat16* __restrict__ w2h, __nv_bfloat16* __restrict__ w2l,
                                 __nv_bfloat16* __restrict__ w3h, __nv_bfloat16* __restrict__ w3l) {
    int i = blockIdx.x * 256 + threadIdx.x;
    const float* W; __nv_bfloat16 *hi, *lo; int idx; int kdim, co;
    if (i < 448 * 64)            { W = W1; hi = w1h; lo = w1l; idx = i;             kdim = 400; co = 64; }
    else if (i < 448*64 + 64*64) { W = W2; hi = w2h; lo = w2l; idx = i - 448*64;    kdim = 64;  co = 64; }
    else if (i < 448*64 + 64*64 + 64*128)
                                 { W = W3; hi = w3h; lo = w3l; idx = i - 448*64 - 64*64; kdim = 64; co = 128; }
    else return;
    int k = idx / co;
    float v = (k < kdim) ? W[idx] : 0.f;
    __nv_bfloat16 h = __float2bfloat16(v);
    hi[idx] = h;
    lo[idx] = __float2bfloat16(v - __bfloat162float(h));
}

// ---------------- wmma bf16x3 GEMM: out[M,CO] = X[M,KDIM] @ W[KDIM,CO] ----------------
// (non-pipelined; the R10 pipelined variant regressed)
template<int CO, int KDIM, bool SCALE>
__global__ void __launch_bounds__(256) wgemm_kernel(
        const float* __restrict__ X,
        const __nv_bfloat16* __restrict__ wh,
        const __nv_bfloat16* __restrict__ wl,
        const float* __restrict__ rowscale,
        float* __restrict__ out) {
    constexpr int KCH = (KDIM + 63) / 64;
    constexpr int LDA = 72;
    constexpr int LDB = CO + 8;
    constexpr int NT  = CO / 16;

    extern __shared__ char smraw[];
    __nv_bfloat16* Ah = (__nv_bfloat16*)smraw;      // 128*LDA
    __nv_bfloat16* Al = Ah + 128 * LDA;
    __nv_bfloat16* Bh = Al + 128 * LDA;             // 64*LDB
    __nv_bfloat16* Bl = Bh + 64 * LDB;
    float* sOut = (float*)smraw;                    // union: 128*LDB floats

    const int tid  = threadIdx.x;
    const int warp = tid >> 5;
    const int rb   = blockIdx.x * 128;

    wmma::fragment<wmma::accumulator, 16, 16, 16, float> acc[NT];
    #pragma unroll
    for (int t = 0; t < NT; t++) wmma::fill_fragment(acc[t], 0.f);

    for (int ch = 0; ch < KCH; ch++) {
        const int kb = ch * 64;
        __syncthreads();
        // A chunk: 128x64 fp32 -> bf16 hi/lo
        #pragma unroll 2
        for (int i = tid * 4; i < 128 * 64; i += 1024) {
            int r = i >> 6, c = i & 63;
            float4 v = make_float4(0.f, 0.f, 0.f, 0.f);
            if ((KDIM & 63) == 0 || kb + c < KDIM)
                v = *(const float4*)&X[(size_t)(rb + r) * KDIM + kb + c];
            __nv_bfloat16 h0 = __float2bfloat16(v.x);
            __nv_bfloat16 h1 = __float2bfloat16(v.y);
            __nv_bfloat16 h2 = __float2bfloat16(v.z);
            __nv_bfloat16 h3 = __float2bfloat16(v.w);
            __nv_bfloat16 l0 = __float2bfloat16(v.x - __bfloat162float(h0));
            __nv_bfloat16 l1 = __float2bfloat16(v.y - __bfloat162float(h1));
            __nv_bfloat16 l2 = __float2bfloat16(v.z - __bfloat162float(h2));
            __nv_bfloat16 l3 = __float2bfloat16(v.w - __bfloat162float(h3));
            *(uint2*)&Ah[r * LDA + c] = make_uint2(pack_bf2(h0, h1), pack_bf2(h2, h3));
            *(uint2*)&Al[r * LDA + c] = make_uint2(pack_bf2(l0, l1), pack_bf2(l2, l3));
        }
        // B chunk: 64 x CO bf16 (pre-split)
        #pragma unroll 2
        for (int i = tid * 4; i < 64 * CO; i += 1024) {
            int r = i / CO, c = i & (CO - 1);
            *(uint2*)&Bh[r * LDB + c] = *(const uint2*)&wh[(size_t)(kb + r) * CO + c];
            *(uint2*)&Bl[r * LDB + c] = *(const uint2*)&wl[(size_t)(kb + r) * CO + c];
        }
        __syncthreads();

        const __nv_bfloat16* arow_h = Ah + (warp * 16) * LDA;
        const __nv_bfloat16* arow_l = Al + (warp * 16) * LDA;
        #pragma unroll
        for (int k16 = 0; k16 < 4; k16++) {
            wmma::fragment<wmma::matrix_a, 16, 16, 16, __nv_bfloat16, wmma::row_major> fa_h, fa_l;
            wmma::load_matrix_sync(fa_h, arow_h + k16 * 16, LDA);
            wmma::load_matrix_sync(fa_l, arow_l + k16 * 16, LDA);
            #pragma unroll
            for (int t = 0; t < NT; t++) {
                wmma::fragment<wmma::matrix_b, 16, 16, 16, __nv_bfloat16, wmma::row_major> fb_h, fb_l;
                wmma::load_matrix_sync(fb_h, Bh + (k16 * 16) * LDB + t * 16, LDB);
                wmma::load_matrix_sync(fb_l, Bl + (k16 * 16) * LDB + t * 16, LDB);
                wmma::mma_sync(acc[t], fa_h, fb_h, acc[t]);
                wmma::mma_sync(acc[t], fa_h, fb_l, acc[t]);
                wmma::mma_sync(acc[t], fa_l, fb_h, acc[t]);
            }
        }
    }
    __syncthreads();
    #pragma unroll
    for (int t = 0; t < NT; t++)
        wmma::store_matrix_sync(sOut + (warp * 16) * LDB + t * 16, acc[t], LDB,
                                wmma::mem_row_major);
    __syncthreads();
    #pragma unroll 2
    for (int i = tid * 4; i < 128 * CO; i += 1024) {
        int r = i / CO, c = i & (CO - 1);
        float4 v = *(float4*)&sOut[r * LDB + c];
        float rs = 1.f;
        if (SCALE) rs = rowscale[rb + r];
        v.x *= rs; v.y *= rs; v.z *= rs; v.w *= rs;
        *(float4*)&out[(size_t)(rb + r) * CO + c] = v;
    }
}

constexpr int wg_smem(int CO) {
    int lda = 72, ldb = CO + 8;
    int ab = (2 * 128 * lda + 2 * 64 * ldb) * 2;
    int os = 128 * ldb * 4;
    return ab > os ? ab : os;
}

// ---------------- shared gather helper: 4x-unrolled CSR edge accumulation ----------------
__device__ __forceinline__ void gather_row(const unsigned short* __restrict__ bsrc,
                                           const float* __restrict__ bw,
                                           const float* __restrict__ ysm,
                                           int e0, int e1, int lane,
                                           float& a0, float& a1) {
    int j = e0;
    for (; j + 4 <= e1; j += 4) {
        int s0 = bsrc[j], s1 = bsrc[j + 1], s2 = bsrc[j + 2], s3 = bsrc[j + 3];
        float w0 = bw[j], w1 = bw[j + 1], w2 = bw[j + 2], w3 = bw[j + 3];
        float y00 = ysm[s0 * H + lane],      y01 = ysm[s0 * H + lane + 32];
        float y10 = ysm[s1 * H + lane],      y11 = ysm[s1 * H + lane + 32];
        float y20 = ysm[s2 * H + lane],      y21 = ysm[s2 * H + lane + 32];
        float y30 = ysm[s3 * H + lane],      y31 = ysm[s3 * H + lane + 32];
        a0 = fmaf(w0, y00, a0); a1 = fmaf(w0, y01, a1);
        a0 = fmaf(w1, y10, a0); a1 = fmaf(w1, y11, a1);
        a0 = fmaf(w2, y20, a0); a1 = fmaf(w2, y21, a1);
        a0 = fmaf(w3, y30, a0); a1 = fmaf(w3, y31, a1);
    }
    for (; j < e1; j++) {
        int sl = bsrc[j];
        float w = bw[j];
        a0 = fmaf(w, ysm[sl * H + lane],      a0);
        a1 = fmaf(w, ysm[sl * H + lane + 32], a1);
    }
}

// ======================================================================
// agg1: CSR build (single atomic pass + rank trick) + bucket-summed degree
//       (no float atomics) + gather + bias/BN/ReLU; persists CSR + dis
// ======================================================================
constexpr int SMEM_AGG64 = (NPG*H + NPG)*4 + (NPG + 512)*4 + EPG*2 + EPG*4;
constexpr int EPT = (EPG + AT - 1) / AT;   // 16 edges max per thread

__global__ void __launch_bounds__(AT) agg1_kernel(
                            const float* __restrict__ xw,
                            const int* __restrict__ src, const int* __restrict__ dstp,
                            const float* __restrict__ ew,
                            const float* __restrict__ bias, const float* __restrict__ gam,
                            const float* __restrict__ bet, float* __restrict__ out,
                            float* __restrict__ dis_out,
                            unsigned short* __restrict__ ebsrc_out,
                            float* __restrict__ ebw_out, int* __restrict__ eoff_out) {
    extern __shared__ float smf[];
    float* ysm = smf;
    float* dsm = ysm + NPG * H;
    int*   cn  = (int*)(dsm + NPG);
    int*   sc  = cn + NPG;
    unsigned short* bsrc = (unsigned short*)(sc + 512);
    float* bw  = (float*)(bsrc + EPG);

    const int g = blockIdx.x;
    const int nb = g * NPG;
    const int eb = g * EPG;
    const int tid = threadIdx.x;
    const int lane = tid & 31;
    const int warp = tid >> 5;

    for (int i = tid; i < NPG; i += AT) cn[i] = 0;
    __syncthreads();

    // single atomic pass: claim per-dst ranks, pack (sl | dl<<9 | rank<<18)
    int pk[EPT];
    #pragma unroll
    for (int u = 0; u < EPT; u++) {
        int e = tid + u * AT;
        pk[u] = -1;
        if (e < EPG) {
            int sl = src[eb + e] - nb;
            int dl = dstp[eb + e] - nb;
            int r  = atomicAdd(&cn[dl], 1);
            pk[u] = sl | (dl << 9) | (r << 18);
        }
    }
    __syncthreads();

    // inclusive scan of counts
    sc[tid] = (tid < NPG) ? cn[tid] : 0;
    __syncthreads();
    #pragma unroll
    for (int off = 1; off < 512; off <<= 1) {
        int v = sc[tid];
        int a = (tid >= off) ? sc[tid - off] : 0;
        __syncthreads();
        sc[tid] = v + a;
        __syncthreads();
    }
    for (int i = tid; i < NPG; i += AT) eoff_out[nb + i] = sc[i];
    __syncthreads();

    // rank-directed scatter (no atomics)
    #pragma unroll
    for (int u = 0; u < EPT; u++) {
        int e = tid + u * AT;
        if (pk[u] >= 0) {
            int sl = pk[u] & 511;
            int dl = (pk[u] >> 9) & 511;
            int r  = pk[u] >> 18;
            int pos = (dl ? sc[dl - 1] : 0) + r;
            bsrc[pos] = (unsigned short)sl;
            bw[pos]   = ew[eb + e];
        }
    }
    __syncthreads();

    // degree via per-dst bucket sum (no float atomics, deterministic)
    for (int dl = warp; dl < NPG; dl += AW) {
        int e0 = dl ? sc[dl - 1] : 0;
        int e1 = sc[dl];
        float s = 0.f;
        for (int j = e0 + lane; j < e1; j += 32) s += bw[j];
        #pragma unroll
        for (int o = 16; o; o >>= 1) s += __shfl_xor_sync(0xffffffffu, s, o);
        if (lane == 0) {
            float d = rsqrtf(1.f + s);      // self-loop weight 1
            dsm[dl] = d;
            dis_out[nb + dl] = d;
        }
    }
    __syncthreads();

    // ysm = dis * xW
    for (int i = tid * 4; i < NPG * H; i += AT * 4) {
        int node = i >> 6;
        float4 v = *(const float4*)&xw[(size_t)(nb + node) * H + (i & 63)];
        float d = dsm[node];
        v.x *= d; v.y *= d; v.z *= d; v.w *= d;
        *(float4*)&ysm[i] = v;
    }
    // persist buckets for agg2/agg3
    for (int i = tid * 8; i < EPG; i += AT * 8)
        *(uint4*)&ebsrc_out[eb + i] = *(const uint4*)&bsrc[i];
    for (int i = tid * 4; i < EPG; i += AT * 4)
        *(float4*)&ebw_out[eb + i] = *(const float4*)&bw[i];
    __syncthreads();

    // gather + epilogue
    const float s0 = gam[lane] * BN_RS,      s1 = gam[lane + 32] * BN_RS;
    const float t0 = bet[lane],              t1 = bet[lane + 32];
    const float bb0 = bias[lane],            bb1 = bias[lane + 32];
    for (int dl = warp; dl < NPG; dl += AW) {
        int e0 = dl ? sc[dl - 1] : 0;
        int e1 = sc[dl];
        float a0 = ysm[dl * H + lane];
        float a1 = ysm[dl * H + lane + 32];
        gather_row(bsrc, bw, ysm, e0, e1, lane, a0, a1);
        float d = dsm[dl];
        float v0 = fmaf(d, a0, bb0);
        float v1 = fmaf(d, a1, bb1);
        v0 = fmaxf(fmaf(v0, s0, t0), 0.f);
        v1 = fmaxf(fmaf(v1, s1, t1), 0.f);
        size_t o = (size_t)(nb + dl) * H;
        out[o + lane] = v0;
        out[o + lane + 32] = v1;
    }
}

// ======================================================================
// agg2: reuse prebuilt CSR + dis; gather + bias/BN/ReLU + fused score +
//       fused per-graph top-k (bitonic in smem) -> mask/gate
// ======================================================================
__global__ void __launch_bounds__(AT) agg2_kernel(
                            const float* __restrict__ xw, const float* __restrict__ dis,
                            const unsigned short* __restrict__ ebsrc,
                            const float* __restrict__ ebw, const int* __restrict__ eoff,
                            const float* __restrict__ ew_p,   // pool vector
                            const float* __restrict__ bias, const float* __restrict__ gam,
                            const float* __restrict__ bet, float* __restrict__ out,
                            float* __restrict__ mask, float* __restrict__ gate) {
    extern __shared__ float smf[];
    float* ysm = smf;
    float* dsm = ysm + NPG * H;
    int*   cn  = (int*)(dsm + NPG);       // reused as score array
    int*   sc  = cn + NPG;
    unsigned short* bsrc = (unsigned short*)(sc + 512);
    float* bw  = (float*)(bsrc + EPG);
    float* ssc = (float*)cn;              // [NPG] scores

    const int g = blockIdx.x;
    const int nb = g * NPG;
    const int eb = g * EPG;
    const int tid = threadIdx.x;

    for (int i = tid; i < NPG; i += AT) {
        dsm[i] = dis[nb + i];
        sc[i]  = eoff[nb + i];
    }
    for (int i = tid * 8; i < EPG; i += AT * 8)
        *(uint4*)&bsrc[i] = *(const uint4*)&ebsrc[eb + i];
    for (int i = tid * 4; i < EPG; i += AT * 4)
        *(float4*)&bw[i] = *(const float4*)&ebw[eb + i];
    __syncthreads();

    for (int i = tid * 4; i < NPG * H; i += AT * 4) {
        int node = i >> 6;
        float4 v = *(const float4*)&xw[(size_t)(nb + node) * H + (i & 63)];
        float d = dsm[node];
        v.x *= d; v.y *= d; v.z *= d; v.w *= d;
        *(float4*)&ysm[i] = v;
    }
    __syncthreads();

    const int lane = tid & 31;
    const int warp = tid >> 5;
    const float s0 = gam[lane] * BN_RS,      s1 = gam[lane + 32] * BN_RS;
    const float t0 = bet[lane],              t1 = bet[lane + 32];
    const float bb0 = bias[lane],            bb1 = bias[lane + 32];
    const float p0 = ew_p[lane], p1 = ew_p[lane + 32];
    float pn = p0 * p0 + p1 * p1;
    #pragma unroll
    for (int o = 16; o; o >>= 1) pn += __shfl_xor_sync(0xffffffffu, pn, o);
    const float ipn = rsqrtf(pn);

    for (int dl = warp; dl < NPG; dl += AW) {
        int e0 = dl ? sc[dl - 1] : 0;
        int e1 = sc[dl];
        float a0 = ysm[dl * H + lane];
        float a1 = ysm[dl * H + lane + 32];
        gather_row(bsrc, bw, ysm, e0, e1, lane, a0, a1);
        float d = dsm[dl];
        float v0 = fmaf(d, a0, bb0);
        float v1 = fmaf(d, a1, bb1);
        v0 = fmaxf(fmaf(v0, s0, t0), 0.f);
        v1 = fmaxf(fmaf(v1, s1, t1), 0.f);
        size_t o = (size_t)(nb + dl) * H;
        out[o + lane] = v0;
        out[o + lane + 32] = v1;
        float dsc = v0 * p0 + v1 * p1;
        #pragma unroll
        for (int of = 16; of; of >>= 1) dsc += __shfl_xor_sync(0xffffffffu, dsc, of);
        if (lane == 0) ssc[dl] = tanhf(dsc * ipn);
    }
    __syncthreads();   // scores done; ysm now dead -> reuse for sort

    float* sortb = ysm;                                // [512]
    unsigned char* km = (unsigned char*)(ysm + 512);   // [NPG]
    int* cntp = (int*)(ysm + 1024);
    for (int i = tid; i < 512; i += AT) sortb[i] = (i < NPG) ? ssc[i] : -INFINITY;
    if (tid == 0) *cntp = 0;
    __syncthreads();
    // bitonic sort ascending, 512 elems, 1 elem/thread
    #pragma unroll
    for (int k = 2; k <= 512; k <<= 1) {
        #pragma unroll
        for (int j = k >> 1; j > 0; j >>= 1) {
            int ixj = tid ^ j;
            if (ixj > tid) {
                float a = sortb[tid], b = sortb[ixj];
                bool sw = ((tid & k) == 0) ? (a > b) : (a < b);
                if (sw) { sortb[tid] = b; sortb[ixj] = a; }
            }
            __syncthreads();
        }
    }
    float thr = sortb[512 - KEEP];     // 200th largest
    int local = 0;
    for (int i = tid; i < NPG; i += AT)
        if (ssc[i] > thr) local++;
    atomicAdd(cntp, local);
    __syncthreads();
    if (tid == 0) {   // tie-break: lowest index first (matches lax.top_k)
        int rem = KEEP - *cntp;
        for (int i = 0; i < NPG; i++) {
            unsigned char m = (ssc[i] > thr) ? 1 : 0;
            if (!m && ssc[i] == thr && rem > 0) { m = 1; rem--; }
            km[i] = m;
        }
    }
    __syncthreads();
    for (int i = tid; i < NPG; i += AT) {
        float m = km[i] ? 1.f : 0.f;
        mask[nb + i] = m;
        gate[nb + i] = m * ssc[i];
    }
}

// ======================================================================
// agg3: reuse prebuilt CSR; masked degree via bucket sum (no atomics, no
//       rebuild); gather needs no src-mask check (ysm==0 for dropped nodes);
//       fused bias/BN/ReLU + mean/max readout
// ======================================================================
constexpr int SMEM_AGG3 = (NPG*H + 2*NPG)*4 + (NPG + 512)*4 + EPG*2 + EPG*4 + 2 * AW * 64 * 4;

__global__ void __launch_bounds__(AT) agg3_kernel(
                            const float* __restrict__ xw,
                            const float* __restrict__ mask,
                            const unsigned short* __restrict__ ebsrc,
                            const float* __restrict__ ebw, const int* __restrict__ eoff,
                            const float* __restrict__ bias, const float* __restrict__ gam,
                            const float* __restrict__ bet, float* __restrict__ emb) {
    extern __shared__ float smf[];
    float* ysm = smf;
    float* dsm = ysm + NPG * H;
    float* msm = dsm + NPG;
    int*   cn  = (int*)(msm + NPG);      // layout parity (unused)
    int*   sc  = cn + NPG;
    unsigned short* bsrc = (unsigned short*)(sc + 512);
    float* bw   = (float*)(bsrc + EPG);
    float* psum = bw + EPG;              // [AW][64]
    float* pmax = psum + AW * 64;        // [AW][64]

    const int g = blockIdx.x;
    const int nb = g * NPG;
    const int eb = g * EPG;
    const int tid = threadIdx.x;
    const int lane = tid & 31;
    const int warp = tid >> 5;

    for (int i = tid; i < NPG; i += AT) {
        msm[i] = mask[nb + i];
        sc[i]  = eoff[nb + i];
    }
    for (int i = tid * 8; i < EPG; i += AT * 8)
        *(uint4*)&bsrc[i] = *(const uint4*)&ebsrc[eb + i];
    for (int i = tid * 4; i < EPG; i += AT * 4)
        *(float4*)&bw[i] = *(const float4*)&ebw[eb + i];
    __syncthreads();

    // masked degree via per-dst bucket sum (no atomics)
    for (int dl = warp; dl < NPG; dl += AW) {
        float d = 0.f;
        if (msm[dl] != 0.f) {
            int e0 = dl ? sc[dl - 1] : 0;
            int e1 = sc[dl];
            float s = 0.f;
            for (int j = e0 + lane; j < e1; j += 32) {
                int sl = bsrc[j];
                if (msm[sl] != 0.f) s += bw[j];
            }
            #pragma unroll
            for (int o = 16; o; o >>= 1) s += __shfl_xor_sync(0xffffffffu, s, o);
            d = rsqrtf(1.f + s);        // self-loop weight = mask = 1
        }
        if (lane == 0) dsm[dl] = d;
    }
    __syncthreads();

    #pragma unroll
    for (int hf = 0; hf < 2; hf++) {
        if (hf) __syncthreads();
        // ysm = dis3 * xw3 half; dropped nodes -> 0 (dis3=0 AND xw3 row gated to 0)
        for (int i = tid * 4; i < NPG * H; i += AT * 4) {
            int node = i >> 6;
            float4 v = *(const float4*)&xw[(size_t)(nb + node) * H3 + hf * H + (i & 63)];
            float d = dsm[node];
            v.x *= d; v.y *= d; v.z *= d; v.w *= d;
            *(float4*)&ysm[i] = v;
        }
        __syncthreads();
        const int f0 = hf * H + lane, f1 = hf * H + lane + 32;
        const float s0 = gam[f0] * BN_RS, s1 = gam[f1] * BN_RS;
        const float t0 = bet[f0],         t1 = bet[f1];
        const float bb0 = bias[f0],       bb1 = bias[f1];
        float sum0 = 0.f, sum1 = 0.f, mx0 = -INFINITY, mx1 = -INFINITY;
        for (int dl = warp; dl < NPG; dl += AW) {
            if (msm[dl] == 0.f) continue;   // dropped dsts contribute nothing
            int e0 = dl ? sc[dl - 1] : 0;
            int e1 = sc[dl];
            float a0 = ysm[dl * H + lane];
            float a1 = ysm[dl * H + lane + 32];
            gather_row(bsrc, bw, ysm, e0, e1, lane, a0, a1);  // masked srcs add 0
            float d = dsm[dl];
            float v0 = fmaf(d, a0, bb0);
            float v1 = fmaf(d, a1, bb1);
            v0 = fmaxf(fmaf(v0, s0, t0), 0.f);
            v1 = fmaxf(fmaf(v1, s1, t1), 0.f);
            sum0 += v0; sum1 += v1;
            mx0 = fmaxf(mx0, v0); mx1 = fmaxf(mx1, v1);
        }
        psum[warp * 64 + lane]      = sum0;
        psum[warp * 64 + lane + 32] = sum1;
        pmax[warp * 64 + lane]      = mx0;
        pmax[warp * 64 + lane + 32] = mx1;
        __syncthreads();
        if (tid < 64) {   // deterministic fixed-order combine
            float s = 0.f, m = -INFINITY;
            #pragma unroll
            for (int w = 0; w < AW; w++) {
                s += psum[w * 64 + tid];
                m = fmaxf(m, pmax[w * 64 + tid]);
            }
            emb[g * 256 + hf * 64 + tid]       = s * (1.f / KEEP);
            emb[g * 256 + 128 + hf * 64 + tid] = m;
        }
    }
}

// ---------------- MLP head ----------------
__global__ void head_kernel(const float* __restrict__ emb,
                            const float* __restrict__ f1w, const float* __restrict__ f1b,
                            const float* __restrict__ gfc, const float* __restrict__ bfc,
                            const float* __restrict__ f2w, const float* __restrict__ f2b,
                            float* __restrict__ out) {
    __shared__ float z[64];
    const int g = blockIdx.x, j = threadIdx.x;
    float acc = f1b[j];
    const float* e = &emb[g * 256];
    #pragma unroll 8
    for (int k = 0; k < 256; k++)
        acc = fmaf(e[k], f1w[k * 64 + j], acc);
    acc = fmaf(acc, gfc[j] * BN_RS, bfc[j]);
    z[j] = fmaxf(acc, 0.f);
    __syncthreads();
    if (j < 2) {
        float o = f2b[j];
        for (int k = 0; k < 64; k++)
            o = fmaf(z[k], f2w[k * 2 + j], o);
        out[g * 2 + j] = o;
    }
}

// ---------------- launch ----------------
extern "C" void kernel_launch(void* const* d_in, const int* in_sizes, int n_in,
                              void* d_out, int out_size) {
    const float* x   = (const float*)d_in[0];
    const int*   ei  = (const int*)  d_in[1];
    const float* ew  = (const float*)d_in[2];
    const float* W1  = (const float*)d_in[4];
    const float* b1  = (const float*)d_in[5];
    const float* g1  = (const float*)d_in[6];
    const float* bt1 = (const float*)d_in[7];
    const float* W2  = (const float*)d_in[8];
    const float* b2  = (const float*)d_in[9];
    const float* g2  = (const float*)d_in[10];
    const float* bt2 = (const float*)d_in[11];
    const float* pp  = (const float*)d_in[12];
    const float* W3  = (const float*)d_in[13];
    const float* b3  = (const float*)d_in[14];
    const float* g3  = (const float*)d_in[15];
    const float* bt3 = (const float*)d_in[16];
    const float* f1w = (const float*)d_in[17];
    const float* f1b = (const float*)d_in[18];
    const float* gfc = (const float*)d_in[19];
    const float* bfc = (const float*)d_in[20];
    const float* f2w = (const float*)d_in[21];
    const float* f2b = (const float*)d_in[22];
    float* out = (float*)d_out;

    const int* src = ei;
    const int* dst = ei + Etot;

    float *p_xw1, *p_h1, *p_xw2, *p_h2, *p_xw3;
    float *p_dis, *p_mask, *p_gate, *p_emb, *p_ebw;
    unsigned short* p_ebsrc;
    int* p_eoff;
    __nv_bfloat16 *p_w1h, *p_w1l, *p_w2h, *p_w2l, *p_w3h, *p_w3l;
    cudaGetSymbolAddress((void**)&p_xw1,  g_xw1);
    cudaGetSymbolAddress((void**)&p_h1,   g_h1);
    cudaGetSymbolAddress((void**)&p_xw2,  g_xw2);
    cudaGetSymbolAddress((void**)&p_h2,   g_h2);
    cudaGetSymbolAddress((void**)&p_xw3,  g_xw3);
    cudaGetSymbolAddress((void**)&p_dis,  g_dis);
    cudaGetSymbolAddress((void**)&p_mask, g_mask);
    cudaGetSymbolAddress((void**)&p_gate, g_gate);
    cudaGetSymbolAddress((void**)&p_emb,  g_emb);
    cudaGetSymbolAddress((void**)&p_ebsrc,g_ebsrc);
    cudaGetSymbolAddress((void**)&p_ebw,  g_ebw);
    cudaGetSymbolAddress((void**)&p_eoff, g_eoff);
    cudaGetSymbolAddress((void**)&p_w1h,  g_w1h);
    cudaGetSymbolAddress((void**)&p_w1l,  g_w1l);
    cudaGetSymbolAddress((void**)&p_w2h,  g_w2h);
    cudaGetSymbolAddress((void**)&p_w2l,  g_w2l);
    cudaGetSymbolAddress((void**)&p_w3h,  g_w3h);
    cudaGetSymbolAddress((void**)&p_w3l,  g_w3l);

    constexpr int SM1 = wg_smem(64);
    constexpr int SM3 = wg_smem(128);
    cudaFuncSetAttribute((const void*)wgemm_kernel<64, 400, false>,
                         cudaFuncAttributeMaxDynamicSharedMemorySize, SM1);
    cudaFuncSetAttribute((const void*)wgemm_kernel<64, 64, false>,
                         cudaFuncAttributeMaxDynamicSharedMemorySize, SM1);
    cudaFuncSetAttribute((const void*)wgemm_kernel<128, 64, true>,
                         cudaFuncAttributeMaxDynamicSharedMemorySize, SM3);
    cudaFuncSetAttribute(agg1_kernel, cudaFuncAttributeMaxDynamicSharedMemorySize, SMEM_AGG64);
    cudaFuncSetAttribute(agg2_kernel, cudaFuncAttributeMaxDynamicSharedMemorySize, SMEM_AGG64);
    cudaFuncSetAttribute(agg3_kernel, cudaFuncAttributeMaxDynamicSharedMemorySize, SMEM_AGG3);

    // 0: weight split
    wconv_all_kernel<<<(448*64 + 64*64 + 64*128 + 255) / 256, 256>>>(
        W1, W2, W3, p_w1h, p_w1l, p_w2h, p_w2l, p_w3h, p_w3l);

    // 1: GCN1 GEMM
    wgemm_kernel<64, 400, false><<<Ntot / 128, 256, SM1>>>(x, p_w1h, p_w1l, nullptr, p_xw1);
    // 2: GCN1 aggregation (atomic-light CSR build/persist + bucket degree)
    agg1_kernel<<<Bg, AT, SMEM_AGG64>>>(p_xw1, src, dst, ew, b1, g1, bt1, p_h1,
                                        p_dis, p_ebsrc, p_ebw, p_eoff);
    // 3: GCN2 GEMM
    wgemm_kernel<64, 64, false><<<Ntot / 128, 256, SM1>>>(p_h1, p_w2h, p_w2l, nullptr, p_xw2);
    // 4: GCN2 aggregation (reused CSR, fused score + topk -> mask/gate)
    agg2_kernel<<<Bg, AT, SMEM_AGG64>>>(p_xw2, p_dis, p_ebsrc, p_ebw, p_eoff, pp,
                                        b2, g2, bt2, p_h2, p_mask, p_gate);
    // 5: GCN3 GEMM (rows gated by score*mask)
    wgemm_kernel<128, 64, true><<<Ntot / 128, 256, SM3>>>(p_h2, p_w3h, p_w3l, p_gate, p_xw3);
    // 6: GCN3 aggregation (reused CSR, masked bucket degree + readout)
    agg3_kernel<<<Bg, AT, SMEM_AGG3>>>(p_xw3, p_mask, p_ebsrc, p_ebw, p_eoff,
                                       b3, g3, bt3, p_emb);
    // 7: head
    head_kernel<<<Bg, 64>>>(p_emb, f1w, f1b, gfc, bfc, f2w, f2b, out);
}

// round 12
// speedup vs baseline: 1.1576x; 1.0912x over previous
#include <cuda_runtime.h>
#include <cuda_bf16.h>
#include <mma.h>
#include <math.h>
#include <stdint.h>

using namespace nvcuda;

// ---------------- problem constants ----------------
constexpr int Bg   = 256;     // graphs
constexpr int NPG  = 400;     // nodes per graph
constexpr int Ntot = Bg * NPG;        // 102400
constexpr int EPG  = 8000;    // edges per graph
constexpr int Etot = Bg * EPG;        // 2048000
constexpr int CIN  = 400;
constexpr int H    = 64;
constexpr int H3   = 128;
constexpr int KEEP = 200;
constexpr int AT   = 512;     // agg kernel threads
constexpr int AW   = AT / 32; // 16 warps
#define BN_RS 0.99999500003749968f  /* rsqrt(1+1e-5) */

// ---------------- scratch (device globals; no allocation allowed) ----------------
__device__ float g_xw1[Ntot * H];
__device__ float g_h1 [Ntot * H];
__device__ float g_xw2[Ntot * H];
__device__ float g_h2 [Ntot * H];
__device__ float g_xw3[Ntot * H3];
__device__ float g_dis [Ntot];
__device__ float g_mask[Ntot];
__device__ float g_gate[Ntot];
__device__ float g_emb[Bg * 4 * H];   // [B, 256]
// prebuilt per-graph CSR buckets (built by agg1, reused by agg2 AND agg3)
__device__ unsigned short g_ebsrc[Etot];
__device__ float g_ebw[Etot];
__device__ int   g_eoff[Ntot];        // inclusive per-graph-local offsets
// split bf16 weights, row-major [KPAD][CO]
__device__ __nv_bfloat16 g_w1h[448 * 64];
__device__ __nv_bfloat16 g_w1l[448 * 64];
__device__ __nv_bfloat16 g_w2h[64 * 64];
__device__ __nv_bfloat16 g_w2l[64 * 64];
__device__ __nv_bfloat16 g_w3h[64 * 128];
__device__ __nv_bfloat16 g_w3l[64 * 128];

__device__ __forceinline__ uint32_t pack_bf2(__nv_bfloat16 a, __nv_bfloat16 b) {
    __nv_bfloat162 t = __halves2bfloat162(a, b);
    return *reinterpret_cast<uint32_t*>(&t);
}

// ---------------- all-weights bf16 split (single launch) ----------------
__global__ void wconv_all_kernel(const float* __restrict__ W1, const float* __restrict__ W2,
                                 const float* __restrict__ W3,
                                 __nv_bfloat16* __restrict__ w1h, __nv_bfloat16* __restrict__ w1l,
                                 __nv_bfloat16* __restrict__ w2h, __nv_bfloat16* __restrict__ w2l,
                                 __nv_bfloat16* __restrict__ w3h, __nv_bfloat16* __restrict__ w3l) {
    int i = blockIdx.x * 256 + threadIdx.x;
    const float* W; __nv_bfloat16 *hi, *lo; int idx; int kdim, co;
    if (i < 448 * 64)            { W = W1; hi = w1h; lo = w1l; idx = i;             kdim = 400; co = 64; }
    else if (i < 448*64 + 64*64) { W = W2; hi = w2h; lo = w2l; idx = i - 448*64;    kdim = 64;  co = 64; }
    else if (i < 448*64 + 64*64 + 64*128)
                                 { W = W3; hi = w3h; lo = w3l; idx = i - 448*64 - 64*64; kdim = 64; co = 128; }
    else return;
    int k = idx / co;
    float v = (k < kdim) ? W[idx] : 0.f;
    __nv_bfloat16 h = __float2bfloat16(v);
    hi[idx] = h;
    lo[idx] = __float2bfloat16(v - __bfloat162float(h));
}

// ---------------- wmma bf16x3 GEMM: out[M,CO] = X[M,KDIM] @ W[KDIM,CO] ----------------
template<int CO, int KDIM, bool SCALE>
__global__ void __launch_bounds__(256) wgemm_kernel(
        const float* __restrict__ X,
        const __nv_bfloat16* __restrict__ wh,
        const __nv_bfloat16* __restrict__ wl,
        const float* __restrict__ rowscale,
        float* __restrict__ out) {
    constexpr int KCH = (KDIM + 63) / 64;
    constexpr int LDA = 72;
    constexpr int LDB = CO + 8;
    constexpr int NT  = CO / 16;

    extern __shared__ char smraw[];
    __nv_bfloat16* Ah = (__nv_bfloat16*)smraw;      // 128*LDA
    __nv_bfloat16* Al = Ah + 128 * LDA;
    __nv_bfloat16* Bh = Al + 128 * LDA;             // 64*LDB
    __nv_bfloat16* Bl = Bh + 64 * LDB;
    float* sOut = (float*)smraw;                    // union: 128*LDB floats

    const int tid  = threadIdx.x;
    const int warp = tid >> 5;
    const int rb   = blockIdx.x * 128;

    wmma::fragment<wmma::accumulator, 16, 16, 16, float> acc[NT];
    #pragma unroll
    for (int t = 0; t < NT; t++) wmma::fill_fragment(acc[t], 0.f);

    for (int ch = 0; ch < KCH; ch++) {
        const int kb = ch * 64;
        __syncthreads();
        // A chunk: 128x64 fp32 -> bf16 hi/lo
        #pragma unroll 2
        for (int i = tid * 4; i < 128 * 64; i += 1024) {
            int r = i >> 6, c = i & 63;
            float4 v = make_float4(0.f, 0.f, 0.f, 0.f);
            if ((KDIM & 63) == 0 || kb + c < KDIM)
                v = *(const float4*)&X[(size_t)(rb + r) * KDIM + kb + c];
            __nv_bfloat16 h0 = __float2bfloat16(v.x);
            __nv_bfloat16 h1 = __float2bfloat16(v.y);
            __nv_bfloat16 h2 = __float2bfloat16(v.z);
            __nv_bfloat16 h3 = __float2bfloat16(v.w);
            __nv_bfloat16 l0 = __float2bfloat16(v.x - __bfloat162float(h0));
            __nv_bfloat16 l1 = __float2bfloat16(v.y - __bfloat162float(h1));
            __nv_bfloat16 l2 = __float2bfloat16(v.z - __bfloat162float(h2));
            __nv_bfloat16 l3 = __float2bfloat16(v.w - __bfloat162float(h3));
            *(uint2*)&Ah[r * LDA + c] = make_uint2(pack_bf2(h0, h1), pack_bf2(h2, h3));
            *(uint2*)&Al[r * LDA + c] = make_uint2(pack_bf2(l0, l1), pack_bf2(l2, l3));
        }
        // B chunk: 64 x CO bf16 (pre-split)
        #pragma unroll 2
        for (int i = tid * 4; i < 64 * CO; i += 1024) {
            int r = i / CO, c = i & (CO - 1);
            *(uint2*)&Bh[r * LDB + c] = *(const uint2*)&wh[(size_t)(kb + r) * CO + c];
            *(uint2*)&Bl[r * LDB + c] = *(const uint2*)&wl[(size_t)(kb + r) * CO + c];
        }
        __syncthreads();

        const __nv_bfloat16* arow_h = Ah + (warp * 16) * LDA;
        const __nv_bfloat16* arow_l = Al + (warp * 16) * LDA;
        #pragma unroll
        for (int k16 = 0; k16 < 4; k16++) {
            wmma::fragment<wmma::matrix_a, 16, 16, 16, __nv_bfloat16, wmma::row_major> fa_h, fa_l;
            wmma::load_matrix_sync(fa_h, arow_h + k16 * 16, LDA);
            wmma::load_matrix_sync(fa_l, arow_l + k16 * 16, LDA);
            #pragma unroll
            for (int t = 0; t < NT; t++) {
                wmma::fragment<wmma::matrix_b, 16, 16, 16, __nv_bfloat16, wmma::row_major> fb_h, fb_l;
                wmma::load_matrix_sync(fb_h, Bh + (k16 * 16) * LDB + t * 16, LDB);
                wmma::load_matrix_sync(fb_l, Bl + (k16 * 16) * LDB + t * 16, LDB);
                wmma::mma_sync(acc[t], fa_h, fb_h, acc[t]);
                wmma::mma_sync(acc[t], fa_h, fb_l, acc[t]);
                wmma::mma_sync(acc[t], fa_l, fb_h, acc[t]);
            }
        }
    }
    __syncthreads();
    #pragma unroll
    for (int t = 0; t < NT; t++)
        wmma::store_matrix_sync(sOut + (warp * 16) * LDB + t * 16, acc[t], LDB,
                                wmma::mem_row_major);
    __syncthreads();
    #pragma unroll 2
    for (int i = tid * 4; i < 128 * CO; i += 1024) {
        int r = i / CO, c = i & (CO - 1);
        float4 v = *(float4*)&sOut[r * LDB + c];
        float rs = 1.f;
        if (SCALE) rs = rowscale[rb + r];
        v.x *= rs; v.y *= rs; v.z *= rs; v.w *= rs;
        *(float4*)&out[(size_t)(rb + r) * CO + c] = v;
    }
}

constexpr int wg_smem(int CO) {
    int lda = 72, ldb = CO + 8;
    int ab = (2 * 128 * lda + 2 * 64 * ldb) * 2;
    int os = 128 * ldb * 4;
    return ab > os ? ab : os;
}

// ---------------- shared gather helper: 4x-unrolled CSR edge accumulation ----------------
// bsrc/bw may live in smem OR global (warp-uniform sequential reads either way).
__device__ __forceinline__ void gather_row(const unsigned short* __restrict__ bsrc,
                                           const float* __restrict__ bw,
                                           const float* __restrict__ ysm,
                                           int e0, int e1, int lane,
                                           float& a0, float& a1) {
    int j = e0;
    for (; j + 4 <= e1; j += 4) {
        int s0 = bsrc[j], s1 = bsrc[j + 1], s2 = bsrc[j + 2], s3 = bsrc[j + 3];
        float w0 = bw[j], w1 = bw[j + 1], w2 = bw[j + 2], w3 = bw[j + 3];
        float y00 = ysm[s0 * H + lane],      y01 = ysm[s0 * H + lane + 32];
        float y10 = ysm[s1 * H + lane],      y11 = ysm[s1 * H + lane + 32];
        float y20 = ysm[s2 * H + lane],      y21 = ysm[s2 * H + lane + 32];
        float y30 = ysm[s3 * H + lane],      y31 = ysm[s3 * H + lane + 32];
        a0 = fmaf(w0, y00, a0); a1 = fmaf(w0, y01, a1);
        a0 = fmaf(w1, y10, a0); a1 = fmaf(w1, y11, a1);
        a0 = fmaf(w2, y20, a0); a1 = fmaf(w2, y21, a1);
        a0 = fmaf(w3, y30, a0); a1 = fmaf(w3, y31, a1);
    }
    for (; j < e1; j++) {
        int sl = bsrc[j];
        float w = bw[j];
        a0 = fmaf(w, ysm[sl * H + lane],      a0);
        a1 = fmaf(w, ysm[sl * H + lane + 32], a1);
    }
}

// ======================================================================
// agg1: CSR build (single atomic pass + rank trick) + bucket-summed degree
//       + gather + bias/BN/ReLU; persists CSR + dis.  (1 CTA/SM, smem buckets)
// ======================================================================
constexpr int SMEM_AGG64 = (NPG*H + NPG)*4 + (NPG + 512)*4 + EPG*2 + EPG*4;
constexpr int EPT = (EPG + AT - 1) / AT;   // 16 edges max per thread

__global__ void __launch_bounds__(AT) agg1_kernel(
                            const float* __restrict__ xw,
                            const int* __restrict__ src, const int* __restrict__ dstp,
                            const float* __restrict__ ew,
                            const float* __restrict__ bias, const float* __restrict__ gam,
                            const float* __restrict__ bet, float* __restrict__ out,
                            float* __restrict__ dis_out,
                            unsigned short* __restrict__ ebsrc_out,
                            float* __restrict__ ebw_out, int* __restrict__ eoff_out) {
    extern __shared__ float smf[];
    float* ysm = smf;
    float* dsm = ysm + NPG * H;
    int*   cn  = (int*)(dsm + NPG);
    int*   sc  = cn + NPG;
    unsigned short* bsrc = (unsigned short*)(sc + 512);
    float* bw  = (float*)(bsrc + EPG);

    const int g = blockIdx.x;
    const int nb = g * NPG;
    const int eb = g * EPG;
    const int tid = threadIdx.x;
    const int lane = tid & 31;
    const int warp = tid >> 5;

    for (int i = tid; i < NPG; i += AT) cn[i] = 0;
    __syncthreads();

    // single atomic pass: claim per-dst ranks, pack (sl | dl<<9 | rank<<18)
    int pk[EPT];
    #pragma unroll
    for (int u = 0; u < EPT; u++) {
        int e = tid + u * AT;
        pk[u] = -1;
        if (e < EPG) {
            int sl = src[eb + e] - nb;
            int dl = dstp[eb + e] - nb;
            int r  = atomicAdd(&cn[dl], 1);
            pk[u] = sl | (dl << 9) | (r << 18);
        }
    }
    __syncthreads();

    // inclusive scan of counts
    sc[tid] = (tid < NPG) ? cn[tid] : 0;
    __syncthreads();
    #pragma unroll
    for (int off = 1; off < 512; off <<= 1) {
        int v = sc[tid];
        int a = (tid >= off) ? sc[tid - off] : 0;
        __syncthreads();
        sc[tid] = v + a;
        __syncthreads();
    }
    for (int i = tid; i < NPG; i += AT) eoff_out[nb + i] = sc[i];
    __syncthreads();

    // rank-directed scatter (no atomics)
    #pragma unroll
    for (int u = 0; u < EPT; u++) {
        int e = tid + u * AT;
        if (pk[u] >= 0) {
            int sl = pk[u] & 511;
            int dl = (pk[u] >> 9) & 511;
            int r  = pk[u] >> 18;
            int pos = (dl ? sc[dl - 1] : 0) + r;
            bsrc[pos] = (unsigned short)sl;
            bw[pos]   = ew[eb + e];
        }
    }
    __syncthreads();

    // degree via per-dst bucket sum (no float atomics, deterministic)
    for (int dl = warp; dl < NPG; dl += AW) {
        int e0 = dl ? sc[dl - 1] : 0;
        int e1 = sc[dl];
        float s = 0.f;
        for (int j = e0 + lane; j < e1; j += 32) s += bw[j];
        #pragma unroll
        for (int o = 16; o; o >>= 1) s += __shfl_xor_sync(0xffffffffu, s, o);
        if (lane == 0) {
            float d = rsqrtf(1.f + s);      // self-loop weight 1
            dsm[dl] = d;
            dis_out[nb + dl] = d;
        }
    }
    __syncthreads();

    // ysm = dis * xW
    for (int i = tid * 4; i < NPG * H; i += AT * 4) {
        int node = i >> 6;
        float4 v = *(const float4*)&xw[(size_t)(nb + node) * H + (i & 63)];
        float d = dsm[node];
        v.x *= d; v.y *= d; v.z *= d; v.w *= d;
        *(float4*)&ysm[i] = v;
    }
    // persist buckets for agg2/agg3
    for (int i = tid * 8; i < EPG; i += AT * 8)
        *(uint4*)&ebsrc_out[eb + i] = *(const uint4*)&bsrc[i];
    for (int i = tid * 4; i < EPG; i += AT * 4)
        *(float4*)&ebw_out[eb + i] = *(const float4*)&bw[i];
    __syncthreads();

    // gather + epilogue
    const float s0 = gam[lane] * BN_RS,      s1 = gam[lane + 32] * BN_RS;
    const float t0 = bet[lane],              t1 = bet[lane + 32];
    const float bb0 = bias[lane],            bb1 = bias[lane + 32];
    for (int dl = warp; dl < NPG; dl += AW) {
        int e0 = dl ? sc[dl - 1] : 0;
        int e1 = sc[dl];
        float a0 = ysm[dl * H + lane];
        float a1 = ysm[dl * H + lane + 32];
        gather_row(bsrc, bw, ysm, e0, e1, lane, a0, a1);
        float d = dsm[dl];
        float v0 = fmaf(d, a0, bb0);
        float v1 = fmaf(d, a1, bb1);
        v0 = fmaxf(fmaf(v0, s0, t0), 0.f);
        v1 = fmaxf(fmaf(v1, s1, t1), 0.f);
        size_t o = (size_t)(nb + dl) * H;
        out[o + lane] = v0;
        out[o + lane + 32] = v1;
    }
}

// ======================================================================
// agg2: CSR buckets read from GLOBAL (smem ~103KB -> 2 CTAs/SM, 1 wave);
//       gather + bias/BN/ReLU + fused score + fused top-k -> mask/gate
// ======================================================================
constexpr int SMEM_AGG2 = (NPG*H + 2*NPG)*4;

__global__ void __launch_bounds__(AT, 2) agg2_kernel(
                            const float* __restrict__ xw, const float* __restrict__ dis,
                            const unsigned short* __restrict__ ebsrc,
                            const float* __restrict__ ebw, const int* __restrict__ eoff,
                            const float* __restrict__ ew_p,   // pool vector
                            const float* __restrict__ bias, const float* __restrict__ gam,
                            const float* __restrict__ bet, float* __restrict__ out,
                            float* __restrict__ mask, float* __restrict__ gate) {
    extern __shared__ float smf[];
    float* ysm = smf;
    float* dsm = ysm + NPG * H;
    float* ssc = dsm + NPG;               // [NPG] scores

    const int g = blockIdx.x;
    const int nb = g * NPG;
    const int eb = g * EPG;
    const int tid = threadIdx.x;

    for (int i = tid; i < NPG; i += AT) dsm[i] = dis[nb + i];
    __syncthreads();

    for (int i = tid * 4; i < NPG * H; i += AT * 4) {
        int node = i >> 6;
        float4 v = *(const float4*)&xw[(size_t)(nb + node) * H + (i & 63)];
        float d = dsm[node];
        v.x *= d; v.y *= d; v.z *= d; v.w *= d;
        *(float4*)&ysm[i] = v;
    }
    __syncthreads();

    const int lane = tid & 31;
    const int warp = tid >> 5;
    const float s0 = gam[lane] * BN_RS,      s1 = gam[lane + 32] * BN_RS;
    const float t0 = bet[lane],              t1 = bet[lane + 32];
    const float bb0 = bias[lane],            bb1 = bias[lane + 32];
    const float p0 = ew_p[lane], p1 = ew_p[lane + 32];
    float pn = p0 * p0 + p1 * p1;
    #pragma unroll
    for (int o = 16; o; o >>= 1) pn += __shfl_xor_sync(0xffffffffu, pn, o);
    const float ipn = rsqrtf(pn);

    const unsigned short* gb = ebsrc + eb;
    const float* gw = ebw + eb;
    for (int dl = warp; dl < NPG; dl += AW) {
        int e1 = eoff[nb + dl];
        int e0 = dl ? eoff[nb + dl - 1] : 0;
        float a0 = ysm[dl * H + lane];
        float a1 = ysm[dl * H + lane + 32];
        gather_row(gb, gw, ysm, e0, e1, lane, a0, a1);
        float d = dsm[dl];
        float v0 = fmaf(d, a0, bb0);
        float v1 = fmaf(d, a1, bb1);
        v0 = fmaxf(fmaf(v0, s0, t0), 0.f);
        v1 = fmaxf(fmaf(v1, s1, t1), 0.f);
        size_t o = (size_t)(nb + dl) * H;
        out[o + lane] = v0;
        out[o + lane + 32] = v1;
        float dsc = v0 * p0 + v1 * p1;
        #pragma unroll
        for (int of = 16; of; of >>= 1) dsc += __shfl_xor_sync(0xffffffffu, dsc, of);
        if (lane == 0) ssc[dl] = tanhf(dsc * ipn);
    }
    __syncthreads();   // scores done; ysm now dead -> reuse for sort

    float* sortb = ysm;                                // [512]
    unsigned char* km = (unsigned char*)(ysm + 512);   // [NPG]
    int* cntp = (int*)(ysm + 1024);
    for (int i = tid; i < 512; i += AT) sortb[i] = (i < NPG) ? ssc[i] : -INFINITY;
    if (tid == 0) *cntp = 0;
    __syncthreads();
    // bitonic sort ascending, 512 elems, 1 elem/thread
    #pragma unroll
    for (int k = 2; k <= 512; k <<= 1) {
        #pragma unroll
        for (int j = k >> 1; j > 0; j >>= 1) {
            int ixj = tid ^ j;
            if (ixj > tid) {
                float a = sortb[tid], b = sortb[ixj];
                bool sw = ((tid & k) == 0) ? (a > b) : (a < b);
                if (sw) { sortb[tid] = b; sortb[ixj] = a; }
            }
            __syncthreads();
        }
    }
    float thr = sortb[512 - KEEP];     // 200th largest
    int local = 0;
    for (int i = tid; i < NPG; i += AT)
        if (ssc[i] > thr) local++;
    atomicAdd(cntp, local);
    __syncthreads();
    if (tid == 0) {   // tie-break: lowest index first (matches lax.top_k)
        int rem = KEEP - *cntp;
        for (int i = 0; i < NPG; i++) {
            unsigned char m = (ssc[i] > thr) ? 1 : 0;
            if (!m && ssc[i] == thr && rem > 0) { m = 1; rem--; }
            km[i] = m;
        }
    }
    __syncthreads();
    for (int i = tid; i < NPG; i += AT) {
        float m = km[i] ? 1.f : 0.f;
        mask[nb + i] = m;
        gate[nb + i] = m * ssc[i];
    }
}

// ======================================================================
// agg3: CSR buckets read from GLOBAL (smem ~111KB -> 2 CTAs/SM, 1 wave);
//       masked bucket degree + gather + bias/BN/ReLU + mean/max readout
// ======================================================================
constexpr int SMEM_AGG3 = (NPG*H + 2*NPG)*4 + 2 * AW * 64 * 4;

__global__ void __launch_bounds__(AT, 2) agg3_kernel(
                            const float* __restrict__ xw,
                            const float* __restrict__ mask,
                            const unsigned short* __restrict__ ebsrc,
                            const float* __restrict__ ebw, const int* __restrict__ eoff,
                            const float* __restrict__ bias, const float* __restrict__ gam,
                            const float* __restrict__ bet, float* __restrict__ emb) {
    extern __shared__ float smf[];
    float* ysm = smf;
    float* dsm = ysm + NPG * H;
    float* msm = dsm + NPG;
    float* psum = msm + NPG;             // [AW][64]
    float* pmax = psum + AW * 64;        // [AW][64]

    const int g = blockIdx.x;
    const int nb = g * NPG;
    const int eb = g * EPG;
    const int tid = threadIdx.x;
    const int lane = tid & 31;
    const int warp = tid >> 5;

    for (int i = tid; i < NPG; i += AT) msm[i] = mask[nb + i];
    __syncthreads();

    const unsigned short* gb = ebsrc + eb;
    const float* gw = ebw + eb;

    // masked degree via per-dst bucket sum (no atomics)
    for (int dl = warp; dl < NPG; dl += AW) {
        float d = 0.f;
        if (msm[dl] != 0.f) {
            int e1 = eoff[nb + dl];
            int e0 = dl ? eoff[nb + dl - 1] : 0;
            float s = 0.f;
            for (int j = e0 + lane; j < e1; j += 32) {
                int sl = gb[j];
                if (msm[sl] != 0.f) s += gw[j];
            }
            #pragma unroll
            for (int o = 16; o; o >>= 1) s += __shfl_xor_sync(0xffffffffu, s, o);
            d = rsqrtf(1.f + s);        // self-loop weight = mask = 1
        }
        if (lane == 0) dsm[dl] = d;
    }
    __syncthreads();

    #pragma unroll
    for (int hf = 0; hf < 2; hf++) {
        if (hf) __syncthreads();
        // ysm = dis3 * xw3 half; dropped nodes -> 0 (dis3=0 AND xw3 row gated to 0)
        for (int i = tid * 4; i < NPG * H; i += AT * 4) {
            int node = i >> 6;
            float4 v = *(const float4*)&xw[(size_t)(nb + node) * H3 + hf * H + (i & 63)];
            float d = dsm[node];
            v.x *= d; v.y *= d; v.z *= d; v.w *= d;
            *(float4*)&ysm[i] = v;
        }
        __syncthreads();
        const int f0 = hf * H + lane, f1 = hf * H + lane + 32;
        const float s0 = gam[f0] * BN_RS, s1 = gam[f1] * BN_RS;
        const float t0 = bet[f0],         t1 = bet[f1];
        const float bb0 = bias[f0],       bb1 = bias[f1];
        float sum0 = 0.f, sum1 = 0.f, mx0 = -INFINITY, mx1 = -INFINITY;
        for (int dl = warp; dl < NPG; dl += AW) {
            if (msm[dl] == 0.f) continue;   // dropped dsts contribute nothing
            int e1 = eoff[nb + dl];
            int e0 = dl ? eoff[nb + dl - 1] : 0;
            float a0 = ysm[dl * H + lane];
            float a1 = ysm[dl * H + lane + 32];
            gather_row(gb, gw, ysm, e0, e1, lane, a0, a1);  // masked srcs add 0
            float d = dsm[dl];
            float v0 = fmaf(d, a0, bb0);
            float v1 = fmaf(d, a1, bb1);
            v0 = fmaxf(fmaf(v0, s0, t0), 0.f);
            v1 = fmaxf(fmaf(v1, s1, t1), 0.f);
            sum0 += v0; sum1 += v1;
            mx0 = fmaxf(mx0, v0); mx1 = fmaxf(mx1, v1);
        }
        psum[warp * 64 + lane]      = sum0;
        psum[warp * 64 + lane + 32] = sum1;
        pmax[warp * 64 + lane]      = mx0;
        pmax[warp * 64 + lane + 32] = mx1;
        __syncthreads();
        if (tid < 64) {   // deterministic fixed-order combine
            float s = 0.f, m = -INFINITY;
            #pragma unroll
            for (int w = 0; w < AW; w++) {
                s += psum[w * 64 + tid];
                m = fmaxf(m, pmax[w * 64 + tid]);
            }
            emb[g * 256 + hf * 64 + tid]       = s * (1.f / KEEP);
            emb[g * 256 + 128 + hf * 64 + tid] = m;
        }
    }
}

// ---------------- MLP head ----------------
__global__ void head_kernel(const float* __restrict__ emb,
                            const float* __restrict__ f1w, const float* __restrict__ f1b,
                            const float* __restrict__ gfc, const float* __restrict__ bfc,
                            const float* __restrict__ f2w, const float* __restrict__ f2b,
                            float* __restrict__ out) {
    __shared__ float z[64];
    const int g = blockIdx.x, j = threadIdx.x;
    float acc = f1b[j];
    const float* e = &emb[g * 256];
    #pragma unroll 8
    for (int k = 0; k < 256; k++)
        acc = fmaf(e[k], f1w[k * 64 + j], acc);
    acc = fmaf(acc, gfc[j] * BN_RS, bfc[j]);
    z[j] = fmaxf(acc, 0.f);
    __syncthreads();
    if (j < 2) {
        float o = f2b[j];
        for (int k = 0; k < 64; k++)
            o = fmaf(z[k], f2w[k * 2 + j], o);
        out[g * 2 + j] = o;
    }
}

// ---------------- launch ----------------
extern "C" void kernel_launch(void* const* d_in, const int* in_sizes, int n_in,
                              void* d_out, int out_size) {
    const float* x   = (const float*)d_in[0];
    const int*   ei  = (const int*)  d_in[1];
    const float* ew  = (const float*)d_in[2];
    const float* W1  = (const float*)d_in[4];
    const float* b1  = (const float*)d_in[5];
    const float* g1  = (const float*)d_in[6];
    const float* bt1 = (const float*)d_in[7];
    const float* W2  = (const float*)d_in[8];
    const float* b2  = (const float*)d_in[9];
    const float* g2  = (const float*)d_in[10];
    const float* bt2 = (const float*)d_in[11];
    const float* pp  = (const float*)d_in[12];
    const float* W3  = (const float*)d_in[13];
    const float* b3  = (const float*)d_in[14];
    const float* g3  = (const float*)d_in[15];
    const float* bt3 = (const float*)d_in[16];
    const float* f1w = (const float*)d_in[17];
    const float* f1b = (const float*)d_in[18];
    const float* gfc = (const float*)d_in[19];
    const float* bfc = (const float*)d_in[20];
    const float* f2w = (const float*)d_in[21];
    const float* f2b = (const float*)d_in[22];
    float* out = (float*)d_out;

    const int* src = ei;
    const int* dst = ei + Etot;

    float *p_xw1, *p_h1, *p_xw2, *p_h2, *p_xw3;
    float *p_dis, *p_mask, *p_gate, *p_emb, *p_ebw;
    unsigned short* p_ebsrc;
    int* p_eoff;
    __nv_bfloat16 *p_w1h, *p_w1l, *p_w2h, *p_w2l, *p_w3h, *p_w3l;
    cudaGetSymbolAddress((void**)&p_xw1,  g_xw1);
    cudaGetSymbolAddress((void**)&p_h1,   g_h1);
    cudaGetSymbolAddress((void**)&p_xw2,  g_xw2);
    cudaGetSymbolAddress((void**)&p_h2,   g_h2);
    cudaGetSymbolAddress((void**)&p_xw3,  g_xw3);
    cudaGetSymbolAddress((void**)&p_dis,  g_dis);
    cudaGetSymbolAddress((void**)&p_mask, g_mask);
    cudaGetSymbolAddress((void**)&p_gate, g_gate);
    cudaGetSymbolAddress((void**)&p_emb,  g_emb);
    cudaGetSymbolAddress((void**)&p_ebsrc,g_ebsrc);
    cudaGetSymbolAddress((void**)&p_ebw,  g_ebw);
    cudaGetSymbolAddress((void**)&p_eoff, g_eoff);
    cudaGetSymbolAddress((void**)&p_w1h,  g_w1h);
    cudaGetSymbolAddress((void**)&p_w1l,  g_w1l);
    cudaGetSymbolAddress((void**)&p_w2h,  g_w2h);
    cudaGetSymbolAddress((void**)&p_w2l,  g_w2l);
    cudaGetSymbolAddress((void**)&p_w3h,  g_w3h);
    cudaGetSymbolAddress((void**)&p_w3l,  g_w3l);

    constexpr int SM1 = wg_smem(64);
    constexpr int SM3 = wg_smem(128);
    cudaFuncSetAttribute((const void*)wgemm_kernel<64, 400, false>,
                         cudaFuncAttributeMaxDynamicSharedMemorySize, SM1);
    cudaFuncSetAttribute((const void*)wgemm_kernel<64, 64, false>,
                         cudaFuncAttributeMaxDynamicSharedMemorySize, SM1);
    cudaFuncSetAttribute((const void*)wgemm_kernel<128, 64, true>,
                         cudaFuncAttributeMaxDynamicSharedMemorySize, SM3);
    cudaFuncSetAttribute(agg1_kernel, cudaFuncAttributeMaxDynamicSharedMemorySize, SMEM_AGG64);
    cudaFuncSetAttribute(agg2_kernel, cudaFuncAttributeMaxDynamicSharedMemorySize, SMEM_AGG2);
    cudaFuncSetAttribute(agg3_kernel, cudaFuncAttributeMaxDynamicSharedMemorySize, SMEM_AGG3);

    // 0: weight split
    wconv_all_kernel<<<(448*64 + 64*64 + 64*128 + 255) / 256, 256>>>(
        W1, W2, W3, p_w1h, p_w1l, p_w2h, p_w2l, p_w3h, p_w3l);

    // 1: GCN1 GEMM
    wgemm_kernel<64, 400, false><<<Ntot / 128, 256, SM1>>>(x, p_w1h, p_w1l, nullptr, p_xw1);
    // 2: GCN1 aggregation (atomic-light CSR build/persist + bucket degree)
    agg1_kernel<<<Bg, AT, SMEM_AGG64>>>(p_xw1, src, dst, ew, b1, g1, bt1, p_h1,
                                        p_dis, p_ebsrc, p_ebw, p_eoff);
    // 3: GCN2 GEMM
    wgemm_kernel<64, 64, false><<<Ntot / 128, 256, SM1>>>(p_h1, p_w2h, p_w2l, nullptr, p_xw2);
    // 4: GCN2 aggregation (global CSR, 2 CTAs/SM; fused score + topk)
    agg2_kernel<<<Bg, AT, SMEM_AGG2>>>(p_xw2, p_dis, p_ebsrc, p_ebw, p_eoff, pp,
                                       b2, g2, bt2, p_h2, p_mask, p_gate);
    // 5: GCN3 GEMM (rows gated by score*mask)
    wgemm_kernel<128, 64, true><<<Ntot / 128, 256, SM3>>>(p_h2, p_w3h, p_w3l, p_gate, p_xw3);
    // 6: GCN3 aggregation (global CSR, 2 CTAs/SM; masked degree + readout)
    agg3_kernel<<<Bg, AT, SMEM_AGG3>>>(p_xw3, p_mask, p_ebsrc, p_ebw, p_eoff,
                                       b3, g3, bt3, p_emb);
    // 7: head
    head_kernel<<<Bg, 64>>>(p_emb, f1w, f1b, gfc, bfc, f2w, f2b, out);
}

// round 13
// speedup vs baseline: 1.1998x; 1.0365x over previous
#include <cuda_runtime.h>
#include <cuda_bf16.h>
#include <mma.h>
#include <math.h>
#include <stdint.h>

using namespace nvcuda;

// ---------------- problem constants ----------------
constexpr int Bg   = 256;     // graphs
constexpr int NPG  = 400;     // nodes per graph
constexpr int Ntot = Bg * NPG;        // 102400
constexpr int EPG  = 8000;    // edges per graph
constexpr int Etot = Bg * EPG;        // 2048000
constexpr int CIN  = 400;
constexpr int H    = 64;
constexpr int H3   = 128;
constexpr int KEEP = 200;
constexpr int AT   = 512;     // agg kernel threads
constexpr int AW   = AT / 32; // 16 warps
#define BN_RS 0.99999500003749968f  /* rsqrt(1+1e-5) */

// ---------------- scratch (device globals; no allocation allowed) ----------------
__device__ float g_xw1[Ntot * H];
__device__ float g_h1 [Ntot * H];
__device__ float g_xw2[Ntot * H];
__device__ float g_h2 [Ntot * H];
__device__ float g_xw3[Ntot * H3];
__device__ float g_dis [Ntot];
__device__ float g_mask[Ntot];
__device__ float g_gate[Ntot];
__device__ float g_emb[Bg * 4 * H];   // [B, 256]
// prebuilt per-graph CSR buckets (built by agg1, reused by agg2 AND agg3)
__device__ unsigned short g_ebsrc[Etot];
__device__ float g_ebw[Etot];
__device__ int   g_eoff[Ntot];        // inclusive per-graph-local offsets
// split bf16 weights, row-major [KPAD][CO]
__device__ __nv_bfloat16 g_w1h[448 * 64];
__device__ __nv_bfloat16 g_w1l[448 * 64];
__device__ __nv_bfloat16 g_w2h[64 * 64];
__device__ __nv_bfloat16 g_w2l[64 * 64];
__device__ __nv_bfloat16 g_w3h[64 * 128];
__device__ __nv_bfloat16 g_w3l[64 * 128];

__device__ __forceinline__ uint32_t pack_bf2(__nv_bfloat16 a, __nv_bfloat16 b) {
    __nv_bfloat162 t = __halves2bfloat162(a, b);
    return *reinterpret_cast<uint32_t*>(&t);
}

// ---------------- all-weights bf16 split (single launch) ----------------
__global__ void wconv_all_kernel(const float* __restrict__ W1, const float* __restrict__ W2,
                                 const float* __restrict__ W3,
                                 __nv_bfloat16* __restrict__ w1h, __nv_bfloat16* __restrict__ w1l,
                                 __nv_bfloat16* __restrict__ w2h, __nv_bfloat16* __restrict__ w2l,
                                 __nv_bfloat16* __restrict__ w3h, __nv_bfloat16* __restrict__ w3l) {
    int i = blockIdx.x * 256 + threadIdx.x;
    const float* W; __nv_bfloat16 *hi, *lo; int idx; int kdim, co;
    if (i < 448 * 64)            { W = W1; hi = w1h; lo = w1l; idx = i;             kdim = 400; co = 64; }
    else if (i < 448*64 + 64*64) { W = W2; hi = w2h; lo = w2l; idx = i - 448*64;    kdim = 64;  co = 64; }
    else if (i < 448*64 + 64*64 + 64*128)
                                 { W = W3; hi = w3h; lo = w3l; idx = i - 448*64 - 64*64; kdim = 64; co = 128; }
    else return;
    int k = idx / co;
    float v = (k < kdim) ? W[idx] : 0.f;
    __nv_bfloat16 h = __float2bfloat16(v);
    hi[idx] = h;
    lo[idx] = __float2bfloat16(v - __bfloat162float(h));
}

// ---------------- wmma bf16x3 GEMM: out[M,CO] = X[M,KDIM] @ W[KDIM,CO] ----------------
template<int CO, int KDIM, bool SCALE>
__global__ void __launch_bounds__(256) wgemm_kernel(
        const float* __restrict__ X,
        const __nv_bfloat16* __restrict__ wh,
        const __nv_bfloat16* __restrict__ wl,
        const float* __restrict__ rowscale,
        float* __restrict__ out) {
    constexpr int KCH = (KDIM + 63) / 64;
    constexpr int LDA = 72;
    constexpr int LDB = CO + 8;
    constexpr int NT  = CO / 16;

    extern __shared__ char smraw[];
    __nv_bfloat16* Ah = (__nv_bfloat16*)smraw;      // 128*LDA
    __nv_bfloat16* Al = Ah + 128 * LDA;
    __nv_bfloat16* Bh = Al + 128 * LDA;             // 64*LDB
    __nv_bfloat16* Bl = Bh + 64 * LDB;
    float* sOut = (float*)smraw;                    // union: 128*LDB floats

    const int tid  = threadIdx.x;
    const int warp = tid >> 5;
    const int rb   = blockIdx.x * 128;

    wmma::fragment<wmma::accumulator, 16, 16, 16, float> acc[NT];
    #pragma unroll
    for (int t = 0; t < NT; t++) wmma::fill_fragment(acc[t], 0.f);

    for (int ch = 0; ch < KCH; ch++) {
        const int kb = ch * 64;
        __syncthreads();
        // A chunk: 128x64 fp32 -> bf16 hi/lo
        #pragma unroll 2
        for (int i = tid * 4; i < 128 * 64; i += 1024) {
            int r = i >> 6, c = i & 63;
            float4 v = make_float4(0.f, 0.f, 0.f, 0.f);
            if ((KDIM & 63) == 0 || kb + c < KDIM)
                v = *(const float4*)&X[(size_t)(rb + r) * KDIM + kb + c];
            __nv_bfloat16 h0 = __float2bfloat16(v.x);
            __nv_bfloat16 h1 = __float2bfloat16(v.y);
            __nv_bfloat16 h2 = __float2bfloat16(v.z);
            __nv_bfloat16 h3 = __float2bfloat16(v.w);
            __nv_bfloat16 l0 = __float2bfloat16(v.x - __bfloat162float(h0));
            __nv_bfloat16 l1 = __float2bfloat16(v.y - __bfloat162float(h1));
            __nv_bfloat16 l2 = __float2bfloat16(v.z - __bfloat162float(h2));
            __nv_bfloat16 l3 = __float2bfloat16(v.w - __bfloat162float(h3));
            *(uint2*)&Ah[r * LDA + c] = make_uint2(pack_bf2(h0, h1), pack_bf2(h2, h3));
            *(uint2*)&Al[r * LDA + c] = make_uint2(pack_bf2(l0, l1), pack_bf2(l2, l3));
        }
        // B chunk: 64 x CO bf16 (pre-split)
        #pragma unroll 2
        for (int i = tid * 4; i < 64 * CO; i += 1024) {
            int r = i / CO, c = i & (CO - 1);
            *(uint2*)&Bh[r * LDB + c] = *(const uint2*)&wh[(size_t)(kb + r) * CO + c];
            *(uint2*)&Bl[r * LDB + c] = *(const uint2*)&wl[(size_t)(kb + r) * CO + c];
        }
        __syncthreads();

        const __nv_bfloat16* arow_h = Ah + (warp * 16) * LDA;
        const __nv_bfloat16* arow_l = Al + (warp * 16) * LDA;
        #pragma unroll
        for (int k16 = 0; k16 < 4; k16++) {
            wmma::fragment<wmma::matrix_a, 16, 16, 16, __nv_bfloat16, wmma::row_major> fa_h, fa_l;
            wmma::load_matrix_sync(fa_h, arow_h + k16 * 16, LDA);
            wmma::load_matrix_sync(fa_l, arow_l + k16 * 16, LDA);
            #pragma unroll
            for (int t = 0; t < NT; t++) {
                wmma::fragment<wmma::matrix_b, 16, 16, 16, __nv_bfloat16, wmma::row_major> fb_h, fb_l;
                wmma::load_matrix_sync(fb_h, Bh + (k16 * 16) * LDB + t * 16, LDB);
                wmma::load_matrix_sync(fb_l, Bl + (k16 * 16) * LDB + t * 16, LDB);
                wmma::mma_sync(acc[t], fa_h, fb_h, acc[t]);
                wmma::mma_sync(acc[t], fa_h, fb_l, acc[t]);
                wmma::mma_sync(acc[t], fa_l, fb_h, acc[t]);
            }
        }
    }
    __syncthreads();
    #pragma unroll
    for (int t = 0; t < NT; t++)
        wmma::store_matrix_sync(sOut + (warp * 16) * LDB + t * 16, acc[t], LDB,
                                wmma::mem_row_major);
    __syncthreads();
    #pragma unroll 2
    for (int i = tid * 4; i < 128 * CO; i += 1024) {
        int r = i / CO, c = i & (CO - 1);
        float4 v = *(float4*)&sOut[r * LDB + c];
        float rs = 1.f;
        if (SCALE) rs = rowscale[rb + r];
        v.x *= rs; v.y *= rs; v.z *= rs; v.w *= rs;
        *(float4*)&out[(size_t)(rb + r) * CO + c] = v;
    }
}

constexpr int wg_smem(int CO) {
    int lda = 72, ldb = CO + 8;
    int ab = (2 * 128 * lda + 2 * 64 * ldb) * 2;
    int os = 128 * ldb * 4;
    return ab > os ? ab : os;
}

// ---------------- shared gather helper: 4x-unrolled CSR edge accumulation ----------------
// bsrc/bw may live in smem OR global (warp-uniform sequential reads either way).
__device__ __forceinline__ void gather_row(const unsigned short* __restrict__ bsrc,
                                           const float* __restrict__ bw,
                                           const float* __restrict__ ysm,
                                           int e0, int e1, int lane,
                                           float& a0, float& a1) {
    int j = e0;
    for (; j + 4 <= e1; j += 4) {
        int s0 = bsrc[j], s1 = bsrc[j + 1], s2 = bsrc[j + 2], s3 = bsrc[j + 3];
        float w0 = bw[j], w1 = bw[j + 1], w2 = bw[j + 2], w3 = bw[j + 3];
        float y00 = ysm[s0 * H + lane],      y01 = ysm[s0 * H + lane + 32];
        float y10 = ysm[s1 * H + lane],      y11 = ysm[s1 * H + lane + 32];
        float y20 = ysm[s2 * H + lane],      y21 = ysm[s2 * H + lane + 32];
        float y30 = ysm[s3 * H + lane],      y31 = ysm[s3 * H + lane + 32];
        a0 = fmaf(w0, y00, a0); a1 = fmaf(w0, y01, a1);
        a0 = fmaf(w1, y10, a0); a1 = fmaf(w1, y11, a1);
        a0 = fmaf(w2, y20, a0); a1 = fmaf(w2, y21, a1);
        a0 = fmaf(w3, y30, a0); a1 = fmaf(w3, y31, a1);
    }
    for (; j < e1; j++) {
        int sl = bsrc[j];
        float w = bw[j];
        a0 = fmaf(w, ysm[sl * H + lane],      a0);
        a1 = fmaf(w, ysm[sl * H + lane + 32], a1);
    }
}

// ======================================================================
// agg1: CSR build in smem (bucket region UNIONed with ysm) -> persist to
//       global -> reload region as ysm -> gather from GLOBAL CSR.
//       smem ~105KB -> 2 CTAs/SM, single wave.
// ======================================================================
constexpr int SMEM_AGG1 = NPG*H*4 + NPG*4 + NPG*4 + 512*4;
constexpr int EPT = (EPG + AT - 1) / AT;   // 16 edges max per thread

__global__ void __launch_bounds__(AT, 2) agg1_kernel(
                            const float* __restrict__ xw,
                            const int* __restrict__ src, const int* __restrict__ dstp,
                            const float* __restrict__ ew,
                            const float* __restrict__ bias, const float* __restrict__ gam,
                            const float* __restrict__ bet, float* __restrict__ out,
                            float* __restrict__ dis_out,
                            unsigned short* __restrict__ ebsrc_out,
                            float* __restrict__ ebw_out, int* __restrict__ eoff_out) {
    extern __shared__ float smf[];
    float* ysm = smf;                         // [NPG*H]; FIRST used as bucket space
    float* dsm = ysm + NPG * H;
    int*   cn  = (int*)(dsm + NPG);
    int*   sc  = cn + NPG;
    // bucket union inside ysm region: bw first (4B aligned), bsrc after
    float* bw  = ysm;                         // [EPG] 32000B
    unsigned short* bsrc = (unsigned short*)(ysm + EPG);  // [EPG] 16000B  (total 48KB < 102.4KB)

    const int g = blockIdx.x;
    const int nb = g * NPG;
    const int eb = g * EPG;
    const int tid = threadIdx.x;
    const int lane = tid & 31;
    const int warp = tid >> 5;

    for (int i = tid; i < NPG; i += AT) cn[i] = 0;
    __syncthreads();

    // single atomic pass: claim per-dst ranks, pack (sl | dl<<9 | rank<<18)
    int pk[EPT];
    #pragma unroll
    for (int u = 0; u < EPT; u++) {
        int e = tid + u * AT;
        pk[u] = -1;
        if (e < EPG) {
            int sl = src[eb + e] - nb;
            int dl = dstp[eb + e] - nb;
            int r  = atomicAdd(&cn[dl], 1);
            pk[u] = sl | (dl << 9) | (r << 18);
        }
    }
    __syncthreads();

    // inclusive scan of counts
    sc[tid] = (tid < NPG) ? cn[tid] : 0;
    __syncthreads();
    #pragma unroll
    for (int off = 1; off < 512; off <<= 1) {
        int v = sc[tid];
        int a = (tid >= off) ? sc[tid - off] : 0;
        __syncthreads();
        sc[tid] = v + a;
        __syncthreads();
    }
    for (int i = tid; i < NPG; i += AT) eoff_out[nb + i] = sc[i];
    __syncthreads();

    // rank-directed scatter into smem buckets (no atomics)
    #pragma unroll
    for (int u = 0; u < EPT; u++) {
        int e = tid + u * AT;
        if (pk[u] >= 0) {
            int sl = pk[u] & 511;
            int dl = (pk[u] >> 9) & 511;
            int r  = pk[u] >> 18;
            int pos = (dl ? sc[dl - 1] : 0) + r;
            bsrc[pos] = (unsigned short)sl;
            bw[pos]   = ew[eb + e];
        }
    }
    __syncthreads();

    // degree via per-dst bucket sum (deterministic, no float atomics)
    for (int dl = warp; dl < NPG; dl += AW) {
        int e0 = dl ? sc[dl - 1] : 0;
        int e1 = sc[dl];
        float s = 0.f;
        for (int j = e0 + lane; j < e1; j += 32) s += bw[j];
        #pragma unroll
        for (int o = 16; o; o >>= 1) s += __shfl_xor_sync(0xffffffffu, s, o);
        if (lane == 0) {
            float d = rsqrtf(1.f + s);      // self-loop weight 1
            dsm[dl] = d;
            dis_out[nb + dl] = d;
        }
    }
    __syncthreads();

    // persist buckets to global (coalesced) BEFORE overwriting region with ysm
    for (int i = tid * 8; i < EPG; i += AT * 8)
        *(uint4*)&ebsrc_out[eb + i] = *(const uint4*)&bsrc[i];
    for (int i = tid * 4; i < EPG; i += AT * 4)
        *(float4*)&ebw_out[eb + i] = *(const float4*)&bw[i];
    __syncthreads();

    // now reuse region as ysm = dis * xW
    for (int i = tid * 4; i < NPG * H; i += AT * 4) {
        int node = i >> 6;
        float4 v = *(const float4*)&xw[(size_t)(nb + node) * H + (i & 63)];
        float d = dsm[node];
        v.x *= d; v.y *= d; v.z *= d; v.w *= d;
        *(float4*)&ysm[i] = v;
    }
    __syncthreads();

    // gather from GLOBAL CSR (same-block writes visible after __syncthreads)
    const unsigned short* gb = ebsrc_out + eb;
    const float* gw = ebw_out + eb;
    const float s0 = gam[lane] * BN_RS,      s1 = gam[lane + 32] * BN_RS;
    const float t0 = bet[lane],              t1 = bet[lane + 32];
    const float bb0 = bias[lane],            bb1 = bias[lane + 32];
    for (int dl = warp; dl < NPG; dl += AW) {
        int e0 = dl ? sc[dl - 1] : 0;
        int e1 = sc[dl];
        float a0 = ysm[dl * H + lane];
        float a1 = ysm[dl * H + lane + 32];
        gather_row(gb, gw, ysm, e0, e1, lane, a0, a1);
        float d = dsm[dl];
        float v0 = fmaf(d, a0, bb0);
        float v1 = fmaf(d, a1, bb1);
        v0 = fmaxf(fmaf(v0, s0, t0), 0.f);
        v1 = fmaxf(fmaf(v1, s1, t1), 0.f);
        size_t o = (size_t)(nb + dl) * H;
        out[o + lane] = v0;
        out[o + lane + 32] = v1;
    }
}

// ======================================================================
// agg2: CSR buckets read from GLOBAL (2 CTAs/SM, 1 wave);
//       gather + bias/BN/ReLU + fused score + fused top-k -> mask/gate
// ======================================================================
constexpr int SMEM_AGG2 = (NPG*H + 2*NPG)*4;

__global__ void __launch_bounds__(AT, 2) agg2_kernel(
                            const float* __restrict__ xw, const float* __restrict__ dis,
                            const unsigned short* __restrict__ ebsrc,
                            const float* __restrict__ ebw, const int* __restrict__ eoff,
                            const float* __restrict__ ew_p,   // pool vector
                            const float* __restrict__ bias, const float* __restrict__ gam,
                            const float* __restrict__ bet, float* __restrict__ out,
                            float* __restrict__ mask, float* __restrict__ gate) {
    extern __shared__ float smf[];
    float* ysm = smf;
    float* dsm = ysm + NPG * H;
    float* ssc = dsm + NPG;               // [NPG] scores

    const int g = blockIdx.x;
    const int nb = g * NPG;
    const int eb = g * EPG;
    const int tid = threadIdx.x;

    for (int i = tid; i < NPG; i += AT) dsm[i] = dis[nb + i];
    __syncthreads();

    for (int i = tid * 4; i < NPG * H; i += AT * 4) {
        int node = i >> 6;
        float4 v = *(const float4*)&xw[(size_t)(nb + node) * H + (i & 63)];
        float d = dsm[node];
        v.x *= d; v.y *= d; v.z *= d; v.w *= d;
        *(float4*)&ysm[i] = v;
    }
    __syncthreads();

    const int lane = tid & 31;
    const int warp = tid >> 5;
    const float s0 = gam[lane] * BN_RS,      s1 = gam[lane + 32] * BN_RS;
    const float t0 = bet[lane],              t1 = bet[lane + 32];
    const float bb0 = bias[lane],            bb1 = bias[lane + 32];
    const float p0 = ew_p[lane], p1 = ew_p[lane + 32];
    float pn = p0 * p0 + p1 * p1;
    #pragma unroll
    for (int o = 16; o; o >>= 1) pn += __shfl_xor_sync(0xffffffffu, pn, o);
    const float ipn = rsqrtf(pn);

    const unsigned short* gb = ebsrc + eb;
    const float* gw = ebw + eb;
    for (int dl = warp; dl < NPG; dl += AW) {
        int e1 = eoff[nb + dl];
        int e0 = dl ? eoff[nb + dl - 1] : 0;
        float a0 = ysm[dl * H + lane];
        float a1 = ysm[dl * H + lane + 32];
        gather_row(gb, gw, ysm, e0, e1, lane, a0, a1);
        float d = dsm[dl];
        float v0 = fmaf(d, a0, bb0);
        float v1 = fmaf(d, a1, bb1);
        v0 = fmaxf(fmaf(v0, s0, t0), 0.f);
        v1 = fmaxf(fmaf(v1, s1, t1), 0.f);
        size_t o = (size_t)(nb + dl) * H;
        out[o + lane] = v0;
        out[o + lane + 32] = v1;
        float dsc = v0 * p0 + v1 * p1;
        #pragma unroll
        for (int of = 16; of; of >>= 1) dsc += __shfl_xor_sync(0xffffffffu, dsc, of);
        if (lane == 0) ssc[dl] = tanhf(dsc * ipn);
    }
    __syncthreads();   // scores done; ysm now dead -> reuse for sort

    float* sortb = ysm;                                // [512]
    unsigned char* km = (unsigned char*)(ysm + 512);   // [NPG]
    int* cntp = (int*)(ysm + 1024);
    for (int i = tid; i < 512; i += AT) sortb[i] = (i < NPG) ? ssc[i] : -INFINITY;
    if (tid == 0) *cntp = 0;
    __syncthreads();
    // bitonic sort ascending, 512 elems, 1 elem/thread
    #pragma unroll
    for (int k = 2; k <= 512; k <<= 1) {
        #pragma unroll
        for (int j = k >> 1; j > 0; j >>= 1) {
            int ixj = tid ^ j;
            if (ixj > tid) {
                float a = sortb[tid], b = sortb[ixj];
                bool sw = ((tid & k) == 0) ? (a > b) : (a < b);
                if (sw) { sortb[tid] = b; sortb[ixj] = a; }
            }
            __syncthreads();
        }
    }
    float thr = sortb[512 - KEEP];     // 200th largest
    int local = 0;
    for (int i = tid; i < NPG; i += AT)
        if (ssc[i] > thr) local++;
    atomicAdd(cntp, local);
    __syncthreads();
    if (tid == 0) {   // tie-break: lowest index first (matches lax.top_k)
        int rem = KEEP - *cntp;
        for (int i = 0; i < NPG; i++) {
            unsigned char m = (ssc[i] > thr) ? 1 : 0;
            if (!m && ssc[i] == thr && rem > 0) { m = 1; rem--; }
            km[i] = m;
        }
    }
    __syncthreads();
    for (int i = tid; i < NPG; i += AT) {
        float m = km[i] ? 1.f : 0.f;
        mask[nb + i] = m;
        gate[nb + i] = m * ssc[i];
    }
}

// ======================================================================
// agg3: CSR buckets read from GLOBAL (2 CTAs/SM, 1 wave);
//       masked bucket degree + gather + bias/BN/ReLU + mean/max readout
// ======================================================================
constexpr int SMEM_AGG3 = (NPG*H + 2*NPG)*4 + 2 * AW * 64 * 4;

__global__ void __launch_bounds__(AT, 2) agg3_kernel(
                            const float* __restrict__ xw,
                            const float* __restrict__ mask,
                            const unsigned short* __restrict__ ebsrc,
                            const float* __restrict__ ebw, const int* __restrict__ eoff,
                            const float* __restrict__ bias, const float* __restrict__ gam,
                            const float* __restrict__ bet, float* __restrict__ emb) {
    extern __shared__ float smf[];
    float* ysm = smf;
    float* dsm = ysm + NPG * H;
    float* msm = dsm + NPG;
    float* psum = msm + NPG;             // [AW][64]
    float* pmax = psum + AW * 64;        // [AW][64]

    const int g = blockIdx.x;
    const int nb = g * NPG;
    const int eb = g * EPG;
    const int tid = threadIdx.x;
    const int lane = tid & 31;
    const int warp = tid >> 5;

    for (int i = tid; i < NPG; i += AT) msm[i] = mask[nb + i];
    __syncthreads();

    const unsigned short* gb = ebsrc + eb;
    const float* gw = ebw + eb;

    // masked degree via per-dst bucket sum (no atomics)
    for (int dl = warp; dl < NPG; dl += AW) {
        float d = 0.f;
        if (msm[dl] != 0.f) {
            int e1 = eoff[nb + dl];
            int e0 = dl ? eoff[nb + dl - 1] : 0;
            float s = 0.f;
            for (int j = e0 + lane; j < e1; j += 32) {
                int sl = gb[j];
                if (msm[sl] != 0.f) s += gw[j];
            }
            #pragma unroll
            for (int o = 16; o; o >>= 1) s += __shfl_xor_sync(0xffffffffu, s, o);
            d = rsqrtf(1.f + s);        // self-loop weight = mask = 1
        }
        if (lane == 0) dsm[dl] = d;
    }
    __syncthreads();

    #pragma unroll
    for (int hf = 0; hf < 2; hf++) {
        if (hf) __syncthreads();
        // ysm = dis3 * xw3 half; dropped nodes -> 0 (dis3=0 AND xw3 row gated to 0)
        for (int i = tid * 4; i < NPG * H; i += AT * 4) {
            int node = i >> 6;
            float4 v = *(const float4*)&xw[(size_t)(nb + node) * H3 + hf * H + (i & 63)];
            float d = dsm[node];
            v.x *= d; v.y *= d; v.z *= d; v.w *= d;
            *(float4*)&ysm[i] = v;
        }
        __syncthreads();
        const int f0 = hf * H + lane, f1 = hf * H + lane + 32;
        const float s0 = gam[f0] * BN_RS, s1 = gam[f1] * BN_RS;
        const float t0 = bet[f0],         t1 = bet[f1];
        const float bb0 = bias[f0],       bb1 = bias[f1];
        float sum0 = 0.f, sum1 = 0.f, mx0 = -INFINITY, mx1 = -INFINITY;
        for (int dl = warp; dl < NPG; dl += AW) {
            if (msm[dl] == 0.f) continue;   // dropped dsts contribute nothing
            int e1 = eoff[nb + dl];
            int e0 = dl ? eoff[nb + dl - 1] : 0;
            float a0 = ysm[dl * H + lane];
            float a1 = ysm[dl * H + lane + 32];
            gather_row(gb, gw, ysm, e0, e1, lane, a0, a1);  // masked srcs add 0
            float d = dsm[dl];
            float v0 = fmaf(d, a0, bb0);
            float v1 = fmaf(d, a1, bb1);
            v0 = fmaxf(fmaf(v0, s0, t0), 0.f);
            v1 = fmaxf(fmaf(v1, s1, t1), 0.f);
            sum0 += v0; sum1 += v1;
            mx0 = fmaxf(mx0, v0); mx1 = fmaxf(mx1, v1);
        }
        psum[warp * 64 + lane]      = sum0;
        psum[warp * 64 + lane + 32] = sum1;
        pmax[warp * 64 + lane]      = mx0;
        pmax[warp * 64 + lane + 32] = mx1;
        __syncthreads();
        if (tid < 64) {   // deterministic fixed-order combine
            float s = 0.f, m = -INFINITY;
            #pragma unroll
            for (int w = 0; w < AW; w++) {
                s += psum[w * 64 + tid];
                m = fmaxf(m, pmax[w * 64 + tid]);
            }
            emb[g * 256 + hf * 64 + tid]       = s * (1.f / KEEP);
            emb[g * 256 + 128 + hf * 64 + tid] = m;
        }
    }
}

// ---------------- MLP head ----------------
__global__ void head_kernel(const float* __restrict__ emb,
                            const float* __restrict__ f1w, const float* __restrict__ f1b,
                            const float* __restrict__ gfc, const float* __restrict__ bfc,
                            const float* __restrict__ f2w, const float* __restrict__ f2b,
                            float* __restrict__ out) {
    __shared__ float z[64];
    const int g = blockIdx.x, j = threadIdx.x;
    float acc = f1b[j];
    const float* e = &emb[g * 256];
    #pragma unroll 8
    for (int k = 0; k < 256; k++)
        acc = fmaf(e[k], f1w[k * 64 + j], acc);
    acc = fmaf(acc, gfc[j] * BN_RS, bfc[j]);
    z[j] = fmaxf(acc, 0.f);
    __syncthreads();
    if (j < 2) {
        float o = f2b[j];
        for (int k = 0; k < 64; k++)
            o = fmaf(z[k], f2w[k * 2 + j], o);
        out[g * 2 + j] = o;
    }
}

// ---------------- launch ----------------
extern "C" void kernel_launch(void* const* d_in, const int* in_sizes, int n_in,
                              void* d_out, int out_size) {
    const float* x   = (const float*)d_in[0];
    const int*   ei  = (const int*)  d_in[1];
    const float* ew  = (const float*)d_in[2];
    const float* W1  = (const float*)d_in[4];
    const float* b1  = (const float*)d_in[5];
    const float* g1  = (const float*)d_in[6];
    const float* bt1 = (const float*)d_in[7];
    const float* W2  = (const float*)d_in[8];
    const float* b2  = (const float*)d_in[9];
    const float* g2  = (const float*)d_in[10];
    const float* bt2 = (const float*)d_in[11];
    const float* pp  = (const float*)d_in[12];
    const float* W3  = (const float*)d_in[13];
    const float* b3  = (const float*)d_in[14];
    const float* g3  = (const float*)d_in[15];
    const float* bt3 = (const float*)d_in[16];
    const float* f1w = (const float*)d_in[17];
    const float* f1b = (const float*)d_in[18];
    const float* gfc = (const float*)d_in[19];
    const float* bfc = (const float*)d_in[20];
    const float* f2w = (const float*)d_in[21];
    const float* f2b = (const float*)d_in[22];
    float* out = (float*)d_out;

    const int* src = ei;
    const int* dst = ei + Etot;

    float *p_xw1, *p_h1, *p_xw2, *p_h2, *p_xw3;
    float *p_dis, *p_mask, *p_gate, *p_emb, *p_ebw;
    unsigned short* p_ebsrc;
    int* p_eoff;
    __nv_bfloat16 *p_w1h, *p_w1l, *p_w2h, *p_w2l, *p_w3h, *p_w3l;
    cudaGetSymbolAddress((void**)&p_xw1,  g_xw1);
    cudaGetSymbolAddress((void**)&p_h1,   g_h1);
    cudaGetSymbolAddress((void**)&p_xw2,  g_xw2);
    cudaGetSymbolAddress((void**)&p_h2,   g_h2);
    cudaGetSymbolAddress((void**)&p_xw3,  g_xw3);
    cudaGetSymbolAddress((void**)&p_dis,  g_dis);
    cudaGetSymbolAddress((void**)&p_mask, g_mask);
    cudaGetSymbolAddress((void**)&p_gate, g_gate);
    cudaGetSymbolAddress((void**)&p_emb,  g_emb);
    cudaGetSymbolAddress((void**)&p_ebsrc,g_ebsrc);
    cudaGetSymbolAddress((void**)&p_ebw,  g_ebw);
    cudaGetSymbolAddress((void**)&p_eoff, g_eoff);
    cudaGetSymbolAddress((void**)&p_w1h,  g_w1h);
    cudaGetSymbolAddress((void**)&p_w1l,  g_w1l);
    cudaGetSymbolAddress((void**)&p_w2h,  g_w2h);
    cudaGetSymbolAddress((void**)&p_w2l,  g_w2l);
    cudaGetSymbolAddress((void**)&p_w3h,  g_w3h);
    cudaGetSymbolAddress((void**)&p_w3l,  g_w3l);

    constexpr int SM1 = wg_smem(64);
    constexpr int SM3 = wg_smem(128);
    cudaFuncSetAttribute((const void*)wgemm_kernel<64, 400, false>,
                         cudaFuncAttributeMaxDynamicSharedMemorySize, SM1);
    cudaFuncSetAttribute((const void*)wgemm_kernel<64, 64, false>,
                         cudaFuncAttributeMaxDynamicSharedMemorySize, SM1);
    cudaFuncSetAttribute((const void*)wgemm_kernel<128, 64, true>,
                         cudaFuncAttributeMaxDynamicSharedMemorySize, SM3);
    cudaFuncSetAttribute(agg1_kernel, cudaFuncAttributeMaxDynamicSharedMemorySize, SMEM_AGG1);
    cudaFuncSetAttribute(agg2_kernel, cudaFuncAttributeMaxDynamicSharedMemorySize, SMEM_AGG2);
    cudaFuncSetAttribute(agg3_kernel, cudaFuncAttributeMaxDynamicSharedMemorySize, SMEM_AGG3);

    // 0: weight split
    wconv_all_kernel<<<(448*64 + 64*64 + 64*128 + 255) / 256, 256>>>(
        W1, W2, W3, p_w1h, p_w1l, p_w2h, p_w2l, p_w3h, p_w3l);

    // 1: GCN1 GEMM
    wgemm_kernel<64, 400, false><<<Ntot / 128, 256, SM1>>>(x, p_w1h, p_w1l, nullptr, p_xw1);
    // 2: GCN1 aggregation (2 CTAs/SM; smem-union CSR build + global-CSR gather)
    agg1_kernel<<<Bg, AT, SMEM_AGG1>>>(p_xw1, src, dst, ew, b1, g1, bt1, p_h1,
                                       p_dis, p_ebsrc, p_ebw, p_eoff);
    // 3: GCN2 GEMM
    wgemm_kernel<64, 64, false><<<Ntot / 128, 256, SM1>>>(p_h1, p_w2h, p_w2l, nullptr, p_xw2);
    // 4: GCN2 aggregation (global CSR, 2 CTAs/SM; fused score + topk)
    agg2_kernel<<<Bg, AT, SMEM_AGG2>>>(p_xw2, p_dis, p_ebsrc, p_ebw, p_eoff, pp,
                                       b2, g2, bt2, p_h2, p_mask, p_gate);
    // 5: GCN3 GEMM (rows gated by score*mask)
    wgemm_kernel<128, 64, true><<<Ntot / 128, 256, SM3>>>(p_h2, p_w3h, p_w3l, p_gate, p_xw3);
    // 6: GCN3 aggregation (global CSR, 2 CTAs/SM; masked degree + readout)
    agg3_kernel<<<Bg, AT, SMEM_AGG3>>>(p_xw3, p_mask, p_ebsrc, p_ebw, p_eoff,
                                       b3, g3, bt3, p_emb);
    // 7: head
    head_kernel<<<Bg, 64>>>(p_emb, f1w, f1b, gfc, bfc, f2w, f2b, out);
}

// round 15
// speedup vs baseline: 1.2955x; 1.0797x over previous
#include <cuda_runtime.h>
#include <cuda_bf16.h>
#include <mma.h>
#include <math.h>
#include <stdint.h>

using namespace nvcuda;

// ---------------- problem constants ----------------
constexpr int Bg   = 256;     // graphs
constexpr int NPG  = 400;     // nodes per graph
constexpr int Ntot = Bg * NPG;        // 102400
constexpr int EPG  = 8000;    // edges per graph
constexpr int Etot = Bg * EPG;        // 2048000
constexpr int CIN  = 400;
constexpr int H    = 64;
constexpr int H3   = 128;
constexpr int KEEP = 200;
constexpr int AT   = 512;     // agg kernel threads
constexpr int AW   = AT / 32; // 16 warps
#define BN_RS 0.99999500003749968f  /* rsqrt(1+1e-5) */

// ---------------- scratch (device globals; no allocation allowed) ----------------
__device__ float g_xw1[Ntot * H];
__device__ float g_h1 [Ntot * H];
__device__ float g_xw2[Ntot * H];
__device__ float g_h2 [Ntot * H];
__device__ float g_xw3[Ntot * H3];
__device__ float g_dis [Ntot];
__device__ float g_mask[Ntot];
__device__ float g_gate[Ntot];
// prebuilt per-graph CSR buckets (built by agg1, reused by agg2 AND agg3)
__device__ unsigned short g_ebsrc[Etot];
__device__ float g_ebw[Etot];
__device__ int   g_eoff[Ntot];        // inclusive per-graph-local offsets
// split bf16 weights, row-major [KPAD][CO]
__device__ __nv_bfloat16 g_w1h[448 * 64];
__device__ __nv_bfloat16 g_w1l[448 * 64];
__device__ __nv_bfloat16 g_w2h[64 * 64];
__device__ __nv_bfloat16 g_w2l[64 * 64];
__device__ __nv_bfloat16 g_w3h[64 * 128];
__device__ __nv_bfloat16 g_w3l[64 * 128];

__device__ __forceinline__ uint32_t pack_bf2(__nv_bfloat16 a, __nv_bfloat16 b) {
    __nv_bfloat162 t = __halves2bfloat162(a, b);
    return *reinterpret_cast<uint32_t*>(&t);
}

// ---------------- all-weights bf16 split (single launch) ----------------
__global__ void wconv_all_kernel(const float* __restrict__ W1, const float* __restrict__ W2,
                                 const float* __restrict__ W3,
                                 __nv_bfloat16* __restrict__ w1h, __nv_bfloat16* __restrict__ w1l,
                                 __nv_bfloat16* __restrict__ w2h, __nv_bfloat16* __restrict__ w2l,
                                 __nv_bfloat16* __restrict__ w3h, __nv_bfloat16* __restrict__ w3l) {
    int i = blockIdx.x * 256 + threadIdx.x;
    const float* W; __nv_bfloat16 *hi, *lo; int idx; int kdim, co;
    if (i < 448 * 64)            { W = W1; hi = w1h; lo = w1l; idx = i;             kdim = 400; co = 64; }
    else if (i < 448*64 + 64*64) { W = W2; hi = w2h; lo = w2l; idx = i - 448*64;    kdim = 64;  co = 64; }
    else if (i < 448*64 + 64*64 + 64*128)
                                 { W = W3; hi = w3h; lo = w3l; idx = i - 448*64 - 64*64; kdim = 64; co = 128; }
    else return;
    int k = idx / co;
    float v = (k < kdim) ? W[idx] : 0.f;
    __nv_bfloat16 h = __float2bfloat16(v);
    hi[idx] = h;
    lo[idx] = __float2bfloat16(v - __bfloat162float(h));
}

// ---------------- wmma bf16x3 GEMM: out[M,CO] = X[M,KDIM] @ W[KDIM,CO] ----------------
// A-chunk loads batched (MLP=8) before the convert/store phase.
template<int CO, int KDIM, bool SCALE>
__global__ void __launch_bounds__(256) wgemm_kernel(
        const float* __restrict__ X,
        const __nv_bfloat16* __restrict__ wh,
        const __nv_bfloat16* __restrict__ wl,
        const float* __restrict__ rowscale,
        float* __restrict__ out) {
    constexpr int KCH = (KDIM + 63) / 64;
    constexpr int LDA = 72;
    constexpr int LDB = CO + 8;
    constexpr int NT  = CO / 16;

    extern __shared__ char smraw[];
    __nv_bfloat16* Ah = (__nv_bfloat16*)smraw;      // 128*LDA
    __nv_bfloat16* Al = Ah + 128 * LDA;
    __nv_bfloat16* Bh = Al + 128 * LDA;             // 64*LDB
    __nv_bfloat16* Bl = Bh + 64 * LDB;
    float* sOut = (float*)smraw;                    // union: 128*LDB floats

    const int tid  = threadIdx.x;
    const int warp = tid >> 5;
    const int rb   = blockIdx.x * 128;

    wmma::fragment<wmma::accumulator, 16, 16, 16, float> acc[NT];
    #pragma unroll
    for (int t = 0; t < NT; t++) wmma::fill_fragment(acc[t], 0.f);

    for (int ch = 0; ch < KCH; ch++) {
        const int kb = ch * 64;
        __syncthreads();
        // A chunk: batch ALL 8 LDG.128s first (amortize DRAM latency), then convert
        {
            float4 v[8];
            #pragma unroll
            for (int u = 0; u < 8; u++) {
                int i = tid * 4 + u * 1024;
                int r = i >> 6, c = i & 63;
                if ((KDIM & 63) == 0 || kb + c < KDIM)
                    v[u] = *(const float4*)&X[(size_t)(rb + r) * KDIM + kb + c];
                else
                    v[u] = make_float4(0.f, 0.f, 0.f, 0.f);
            }
            #pragma unroll
            for (int u = 0; u < 8; u++) {
                int i = tid * 4 + u * 1024;
                int r = i >> 6, c = i & 63;
                __nv_bfloat16 h0 = __float2bfloat16(v[u].x);
                __nv_bfloat16 h1 = __float2bfloat16(v[u].y);
                __nv_bfloat16 h2 = __float2bfloat16(v[u].z);
                __nv_bfloat16 h3 = __float2bfloat16(v[u].w);
                __nv_bfloat16 l0 = __float2bfloat16(v[u].x - __bfloat162float(h0));
                __nv_bfloat16 l1 = __float2bfloat16(v[u].y - __bfloat162float(h1));
                __nv_bfloat16 l2 = __float2bfloat16(v[u].z - __bfloat162float(h2));
                __nv_bfloat16 l3 = __float2bfloat16(v[u].w - __bfloat162float(h3));
                *(uint2*)&Ah[r * LDA + c] = make_uint2(pack_bf2(h0, h1), pack_bf2(h2, h3));
                *(uint2*)&Al[r * LDA + c] = make_uint2(pack_bf2(l0, l1), pack_bf2(l2, l3));
            }
        }
        // B chunk: 64 x CO bf16 (pre-split; L2-resident after first CTAs)
        #pragma unroll 2
        for (int i = tid * 4; i < 64 * CO; i += 1024) {
            int r = i / CO, c = i & (CO - 1);
            *(uint2*)&Bh[r * LDB + c] = *(const uint2*)&wh[(size_t)(kb + r) * CO + c];
            *(uint2*)&Bl[r * LDB + c] = *(const uint2*)&wl[(size_t)(kb + r) * CO + c];
        }
        __syncthreads();

        const __nv_bfloat16* arow_h = Ah + (warp * 16) * LDA;
        const __nv_bfloat16* arow_l = Al + (warp * 16) * LDA;
        #pragma unroll
        for (int k16 = 0; k16 < 4; k16++) {
            wmma::fragment<wmma::matrix_a, 16, 16, 16, __nv_bfloat16, wmma::row_major> fa_h, fa_l;
            wmma::load_matrix_sync(fa_h, arow_h + k16 * 16, LDA);
            wmma::load_matrix_sync(fa_l, arow_l + k16 * 16, LDA);
            #pragma unroll
            for (int t = 0; t < NT; t++) {
                wmma::fragment<wmma::matrix_b, 16, 16, 16, __nv_bfloat16, wmma::row_major> fb_h, fb_l;
                wmma::load_matrix_sync(fb_h, Bh + (k16 * 16) * LDB + t * 16, LDB);
                wmma::load_matrix_sync(fb_l, Bl + (k16 * 16) * LDB + t * 16, LDB);
                wmma::mma_sync(acc[t], fa_h, fb_h, acc[t]);
                wmma::mma_sync(acc[t], fa_h, fb_l, acc[t]);
                wmma::mma_sync(acc[t], fa_l, fb_h, acc[t]);
            }
        }
    }
    __syncthreads();
    #pragma unroll
    for (int t = 0; t < NT; t++)
        wmma::store_matrix_sync(sOut + (warp * 16) * LDB + t * 16, acc[t], LDB,
                                wmma::mem_row_major);
    __syncthreads();
    #pragma unroll 2
    for (int i = tid * 4; i < 128 * CO; i += 1024) {
        int r = i / CO, c = i & (CO - 1);
        float4 v = *(float4*)&sOut[r * LDB + c];
        float rs = 1.f;
        if (SCALE) rs = rowscale[rb + r];
        v.x *= rs; v.y *= rs; v.z *= rs; v.w *= rs;
        *(float4*)&out[(size_t)(rb + r) * CO + c] = v;
    }
}

constexpr int wg_smem(int CO) {
    int lda = 72, ldb = CO + 8;
    int ab = (2 * 128 * lda + 2 * 64 * ldb) * 2;
    int os = 128 * ldb * 4;
    return ab > os ? ab : os;
}

// ---------------- shared gather helper: 4x-unrolled CSR edge accumulation ----------------
__device__ __forceinline__ void gather_row(const unsigned short* __restrict__ bsrc,
                                           const float* __restrict__ bw,
                                           const float* __restrict__ ysm,
                                           int e0, int e1, int lane,
                                           float& a0, float& a1) {
    int j = e0;
    for (; j + 4 <= e1; j += 4) {
        int s0 = bsrc[j], s1 = bsrc[j + 1], s2 = bsrc[j + 2], s3 = bsrc[j + 3];
        float w0 = bw[j], w1 = bw[j + 1], w2 = bw[j + 2], w3 = bw[j + 3];
        float y00 = ysm[s0 * H + lane],      y01 = ysm[s0 * H + lane + 32];
        float y10 = ysm[s1 * H + lane],      y11 = ysm[s1 * H + lane + 32];
        float y20 = ysm[s2 * H + lane],      y21 = ysm[s2 * H + lane + 32];
        float y30 = ysm[s3 * H + lane],      y31 = ysm[s3 * H + lane + 32];
        a0 = fmaf(w0, y00, a0); a1 = fmaf(w0, y01, a1);
        a0 = fmaf(w1, y10, a0); a1 = fmaf(w1, y11, a1);
        a0 = fmaf(w2, y20, a0); a1 = fmaf(w2, y21, a1);
        a0 = fmaf(w3, y30, a0); a1 = fmaf(w3, y31, a1);
    }
    for (; j < e1; j++) {
        int sl = bsrc[j];
        float w = bw[j];
        a0 = fmaf(w, ysm[sl * H + lane],      a0);
        a1 = fmaf(w, ysm[sl * H + lane + 32], a1);
    }
}

// ======================================================================
// agg1: CSR build in smem (bucket region UNIONed with ysm) -> persist to
//       global -> reload region as ysm -> gather from GLOBAL CSR.
//       smem ~105KB -> 2 CTAs/SM, single wave.
// ======================================================================
constexpr int SMEM_AGG1 = NPG*H*4 + NPG*4 + NPG*4 + 512*4;
constexpr int EPT = (EPG + AT - 1) / AT;   // 16 edges max per thread

__global__ void __launch_bounds__(AT, 2) agg1_kernel(
                            const float* __restrict__ xw,
                            const int* __restrict__ src, const int* __restrict__ dstp,
                            const float* __restrict__ ew,
                            const float* __restrict__ bias, const float* __restrict__ gam,
                            const float* __restrict__ bet, float* __restrict__ out,
                            float* __restrict__ dis_out,
                            unsigned short* __restrict__ ebsrc_out,
                            float* __restrict__ ebw_out, int* __restrict__ eoff_out) {
    extern __shared__ float smf[];
    float* ysm = smf;                         // [NPG*H]; FIRST used as bucket space
    float* dsm = ysm + NPG * H;
    int*   cn  = (int*)(dsm + NPG);
    int*   sc  = cn + NPG;
    float* bw  = ysm;                         // [EPG] 32000B
    unsigned short* bsrc = (unsigned short*)(ysm + EPG);  // [EPG] 16000B

    const int g = blockIdx.x;
    const int nb = g * NPG;
    const int eb = g * EPG;
    const int tid = threadIdx.x;
    const int lane = tid & 31;
    const int warp = tid >> 5;

    for (int i = tid; i < NPG; i += AT) cn[i] = 0;
    __syncthreads();

    // single atomic pass: claim per-dst ranks, pack (sl | dl<<9 | rank<<18)
    int pk[EPT];
    #pragma unroll
    for (int u = 0; u < EPT; u++) {
        int e = tid + u * AT;
        pk[u] = -1;
        if (e < EPG) {
            int sl = src[eb + e] - nb;
            int dl = dstp[eb + e] - nb;
            int r  = atomicAdd(&cn[dl], 1);
            pk[u] = sl | (dl << 9) | (r << 18);
        }
    }
    __syncthreads();

    // inclusive scan of counts
    sc[tid] = (tid < NPG) ? cn[tid] : 0;
    __syncthreads();
    #pragma unroll
    for (int off = 1; off < 512; off <<= 1) {
        int v = sc[tid];
        int a = (tid >= off) ? sc[tid - off] : 0;
        __syncthreads();
        sc[tid] = v + a;
        __syncthreads();
    }
    for (int i = tid; i < NPG; i += AT) eoff_out[nb + i] = sc[i];
    __syncthreads();

    // rank-directed scatter into smem buckets (no atomics)
    #pragma unroll
    for (int u = 0; u < EPT; u++) {
        int e = tid + u * AT;
        if (pk[u] >= 0) {
            int sl = pk[u] & 511;
            int dl = (pk[u] >> 9) & 511;
            int r  = pk[u] >> 18;
            int pos = (dl ? sc[dl - 1] : 0) + r;
            bsrc[pos] = (unsigned short)sl;
            bw[pos]   = ew[eb + e];
        }
    }
    __syncthreads();

    // degree via per-dst bucket sum (deterministic, no float atomics)
    for (int dl = warp; dl < NPG; dl += AW) {
        int e0 = dl ? sc[dl - 1] : 0;
        int e1 = sc[dl];
        float s = 0.f;
        for (int j = e0 + lane; j < e1; j += 32) s += bw[j];
        #pragma unroll
        for (int o = 16; o; o >>= 1) s += __shfl_xor_sync(0xffffffffu, s, o);
        if (lane == 0) {
            float d = rsqrtf(1.f + s);      // self-loop weight 1
            dsm[dl] = d;
            dis_out[nb + dl] = d;
        }
    }
    __syncthreads();

    // persist buckets to global (coalesced) BEFORE overwriting region with ysm
    for (int i = tid * 8; i < EPG; i += AT * 8)
        *(uint4*)&ebsrc_out[eb + i] = *(const uint4*)&bsrc[i];
    for (int i = tid * 4; i < EPG; i += AT * 4)
        *(float4*)&ebw_out[eb + i] = *(const float4*)&bw[i];
    __syncthreads();

    // now reuse region as ysm = dis * xW
    for (int i = tid * 4; i < NPG * H; i += AT * 4) {
        int node = i >> 6;
        float4 v = *(const float4*)&xw[(size_t)(nb + node) * H + (i & 63)];
        float d = dsm[node];
        v.x *= d; v.y *= d; v.z *= d; v.w *= d;
        *(float4*)&ysm[i] = v;
    }
    __syncthreads();

    // gather from GLOBAL CSR
    const unsigned short* gb = ebsrc_out + eb;
    const float* gw = ebw_out + eb;
    const float s0 = gam[lane] * BN_RS,      s1 = gam[lane + 32] * BN_RS;
    const float t0 = bet[lane],              t1 = bet[lane + 32];
    const float bb0 = bias[lane],            bb1 = bias[lane + 32];
    for (int dl = warp; dl < NPG; dl += AW) {
        int e0 = dl ? sc[dl - 1] : 0;
        int e1 = sc[dl];
        float a0 = ysm[dl * H + lane];
        float a1 = ysm[dl * H + lane + 32];
        gather_row(gb, gw, ysm, e0, e1, lane, a0, a1);
        float d = dsm[dl];
        float v0 = fmaf(d, a0, bb0);
        float v1 = fmaf(d, a1, bb1);
        v0 = fmaxf(fmaf(v0, s0, t0), 0.f);
        v1 = fmaxf(fmaf(v1, s1, t1), 0.f);
        size_t o = (size_t)(nb + dl) * H;
        out[o + lane] = v0;
        out[o + lane + 32] = v1;
    }
}

// ======================================================================
// agg2: CSR buckets read from GLOBAL (2 CTAs/SM, 1 wave);
//       gather + bias/BN/ReLU + fused score + fused top-k -> mask/gate
// ======================================================================
constexpr int SMEM_AGG2 = (NPG*H + 2*NPG)*4;

__global__ void __launch_bounds__(AT, 2) agg2_kernel(
                            const float* __restrict__ xw, const float* __restrict__ dis,
                            const unsigned short* __restrict__ ebsrc,
                            const float* __restrict__ ebw, const int* __restrict__ eoff,
                            const float* __restrict__ ew_p,   // pool vector
                            const float* __restrict__ bias, const float* __restrict__ gam,
                            const float* __restrict__ bet, float* __restrict__ out,
                            float* __restrict__ mask, float* __restrict__ gate) {
    extern __shared__ float smf[];
    float* ysm = smf;
    float* dsm = ysm + NPG * H;
    float* ssc = dsm + NPG;               // [NPG] scores

    const int g = blockIdx.x;
    const int nb = g * NPG;
    const int eb = g * EPG;
    const int tid = threadIdx.x;

    for (int i = tid; i < NPG; i += AT) dsm[i] = dis[nb + i];
    __syncthreads();

    for (int i = tid * 4; i < NPG * H; i += AT * 4) {
        int node = i >> 6;
        float4 v = *(const float4*)&xw[(size_t)(nb + node) * H + (i & 63)];
        float d = dsm[node];
        v.x *= d; v.y *= d; v.z *= d; v.w *= d;
        *(float4*)&ysm[i] = v;
    }
    __syncthreads();

    const int lane = tid & 31;
    const int warp = tid >> 5;
    const float s0 = gam[lane] * BN_RS,      s1 = gam[lane + 32] * BN_RS;
    const float t0 = bet[lane],              t1 = bet[lane + 32];
    const float bb0 = bias[lane],            bb1 = bias[lane + 32];
    const float p0 = ew_p[lane], p1 = ew_p[lane + 32];
    float pn = p0 * p0 + p1 * p1;
    #pragma unroll
    for (int o = 16; o; o >>= 1) pn += __shfl_xor_sync(0xffffffffu, pn, o);
    const float ipn = rsqrtf(pn);

    const unsigned short* gb = ebsrc + eb;
    const float* gw = ebw + eb;
    for (int dl = warp; dl < NPG; dl += AW) {
        int e1 = eoff[nb + dl];
        int e0 = dl ? eoff[nb + dl - 1] : 0;
        float a0 = ysm[dl * H + lane];
        float a1 = ysm[dl * H + lane + 32];
        gather_row(gb, gw, ysm, e0, e1, lane, a0, a1);
        float d = dsm[dl];
        float v0 = fmaf(d, a0, bb0);
        float v1 = fmaf(d, a1, bb1);
        v0 = fmaxf(fmaf(v0, s0, t0), 0.f);
        v1 = fmaxf(fmaf(v1, s1, t1), 0.f);
        size_t o = (size_t)(nb + dl) * H;
        out[o + lane] = v0;
        out[o + lane + 32] = v1;
        float dsc = v0 * p0 + v1 * p1;
        #pragma unroll
        for (int of = 16; of; of >>= 1) dsc += __shfl_xor_sync(0xffffffffu, dsc, of);
        if (lane == 0) ssc[dl] = tanhf(dsc * ipn);
    }
    __syncthreads();   // scores done; ysm now dead -> reuse for sort

    float* sortb = ysm;                                // [512]
    unsigned char* km = (unsigned char*)(ysm + 512);   // [NPG]
    int* cntp = (int*)(ysm + 1024);
    for (int i = tid; i < 512; i += AT) sortb[i] = (i < NPG) ? ssc[i] : -INFINITY;
    if (tid == 0) *cntp = 0;
    __syncthreads();
    // bitonic sort ascending, 512 elems, 1 elem/thread
    #pragma unroll
    for (int k = 2; k <= 512; k <<= 1) {
        #pragma unroll
        for (int j = k >> 1; j > 0; j >>= 1) {
            int ixj = tid ^ j;
            if (ixj > tid) {
                float a = sortb[tid], b = sortb[ixj];
                bool sw = ((tid & k) == 0) ? (a > b) : (a < b);
                if (sw) { sortb[tid] = b; sortb[ixj] = a; }
            }
            __syncthreads();
        }
    }
    float thr = sortb[512 - KEEP];     // 200th largest
    int local = 0;
    for (int i = tid; i < NPG; i += AT)
        if (ssc[i] > thr) local++;
    atomicAdd(cntp, local);
    __syncthreads();
    if (tid == 0) {   // tie-break: lowest index first (matches lax.top_k)
        int rem = KEEP - *cntp;
        for (int i = 0; i < NPG; i++) {
            unsigned char m = (ssc[i] > thr) ? 1 : 0;
            if (!m && ssc[i] == thr && rem > 0) { m = 1; rem--; }
            km[i] = m;
        }
    }
    __syncthreads();
    for (int i = tid; i < NPG; i += AT) {
        float m = km[i] ? 1.f : 0.f;
        mask[nb + i] = m;
        gate[nb + i] = m * ssc[i];
    }
}

// ======================================================================
// agg3: global CSR (2 CTAs/SM); masked bucket degree + gather + BN/ReLU +
//       mean/max readout + FUSED MLP head -> out[g*2..]
// ======================================================================
constexpr int SMEM_AGG3 = (NPG*H + 2*NPG)*4 + 2 * AW * 64 * 4;

__global__ void __launch_bounds__(AT, 2) agg3_kernel(
                            const float* __restrict__ xw,
                            const float* __restrict__ mask,
                            const unsigned short* __restrict__ ebsrc,
                            const float* __restrict__ ebw, const int* __restrict__ eoff,
                            const float* __restrict__ bias, const float* __restrict__ gam,
                            const float* __restrict__ bet,
                            const float* __restrict__ f1w, const float* __restrict__ f1b,
                            const float* __restrict__ gfc, const float* __restrict__ bfc,
                            const float* __restrict__ f2w, const float* __restrict__ f2b,
                            float* __restrict__ outp) {
    extern __shared__ float smf[];
    float* ysm = smf;
    float* dsm = ysm + NPG * H;
    float* msm = dsm + NPG;
    float* psum = msm + NPG;             // [AW][64]
    float* pmax = psum + AW * 64;        // [AW][64]

    const int g = blockIdx.x;
    const int nb = g * NPG;
    const int eb = g * EPG;
    const int tid = threadIdx.x;
    const int lane = tid & 31;
    const int warp = tid >> 5;

    for (int i = tid; i < NPG; i += AT) msm[i] = mask[nb + i];
    __syncthreads();

    const unsigned short* gb = ebsrc + eb;
    const float* gw = ebw + eb;

    // masked degree via per-dst bucket sum (no atomics)
    for (int dl = warp; dl < NPG; dl += AW) {
        float d = 0.f;
        if (msm[dl] != 0.f) {
            int e1 = eoff[nb + dl];
            int e0 = dl ? eoff[nb + dl - 1] : 0;
            float s = 0.f;
            for (int j = e0 + lane; j < e1; j += 32) {
                int sl = gb[j];
                if (msm[sl] != 0.f) s += gw[j];
            }
            #pragma unroll
            for (int o = 16; o; o >>= 1) s += __shfl_xor_sync(0xffffffffu, s, o);
            d = rsqrtf(1.f + s);        // self-loop weight = mask = 1
        }
        if (lane == 0) dsm[dl] = d;
    }
    __syncthreads();

    float hmean[2], hmax[2];
    #pragma unroll
    for (int hf = 0; hf < 2; hf++) {
        if (hf) __syncthreads();
        // ysm = dis3 * xw3 half; dropped nodes -> 0 (dis3=0 AND xw3 row gated to 0)
        for (int i = tid * 4; i < NPG * H; i += AT * 4) {
            int node = i >> 6;
            float4 v = *(const float4*)&xw[(size_t)(nb + node) * H3 + hf * H + (i & 63)];
            float d = dsm[node];
            v.x *= d; v.y *= d; v.z *= d; v.w *= d;
            *(float4*)&ysm[i] = v;
        }
        __syncthreads();
        const int f0 = hf * H + lane, f1 = hf * H + lane + 32;
        const float s0 = gam[f0] * BN_RS, s1 = gam[f1] * BN_RS;
        const float t0 = bet[f0],         t1 = bet[f1];
        const float bb0 = bias[f0],       bb1 = bias[f1];
        float sum0 = 0.f, sum1 = 0.f, mx0 = -INFINITY, mx1 = -INFINITY;
        for (int dl = warp; dl < NPG; dl += AW) {
            if (msm[dl] == 0.f) continue;   // dropped dsts contribute nothing
            int e1 = eoff[nb + dl];
            int e0 = dl ? eoff[nb + dl - 1] : 0;
            float a0 = ysm[dl * H + lane];
            float a1 = ysm[dl * H + lane + 32];
            gather_row(gb, gw, ysm, e0, e1, lane, a0, a1);  // masked srcs add 0
            float d = dsm[dl];
            float v0 = fmaf(d, a0, bb0);
            float v1 = fmaf(d, a1, bb1);
            v0 = fmaxf(fmaf(v0, s0, t0), 0.f);
            v1 = fmaxf(fmaf(v1, s1, t1), 0.f);
            sum0 += v0; sum1 += v1;
            mx0 = fmaxf(mx0, v0); mx1 = fmaxf(mx1, v1);
        }
        psum[warp * 64 + lane]      = sum0;
        psum[warp * 64 + lane + 32] = sum1;
        pmax[warp * 64 + lane]      = mx0;
        pmax[warp * 64 + lane + 32] = mx1;
        __syncthreads();
        if (tid < 64) {   // deterministic fixed-order combine, kept in registers
            float s = 0.f, m = -INFINITY;
            #pragma unroll
            for (int w = 0; w < AW; w++) {
                s += psum[w * 64 + tid];
                m = fmaxf(m, pmax[w * 64 + tid]);
            }
            hmean[hf] = s * (1.f / KEEP);
            hmax[hf]  = m;
        }
    }
    __syncthreads();   // partial arrays now dead

    // ---- fused MLP head ----
    float* semb = psum;          // [256] emb = [mean0|mean1|max0|max1]
    float* zz   = pmax;          // [64]
    if (tid < 64) {
        semb[tid]       = hmean[0];
        semb[64 + tid]  = hmean[1];
        semb[128 + tid] = hmax[0];
        semb[192 + tid] = hmax[1];
    }
    __syncthreads();
    if (tid < 64) {
        float acc = f1b[tid];
        #pragma unroll 8
        for (int k = 0; k < 256; k++)
            acc = fmaf(semb[k], f1w[k * 64 + tid], acc);
        acc = fmaf(acc, gfc[tid] * BN_RS, bfc[tid]);
        zz[tid] = fmaxf(acc, 0.f);
    }
    __syncthreads();
    if (tid < 2) {
        float o = f2b[tid];
        #pragma unroll 8
        for (int k = 0; k < 64; k++)
            o = fmaf(zz[k], f2w[k * 2 + tid], o);
        outp[g * 2 + tid] = o;
    }
}

// ---------------- launch ----------------
extern "C" void kernel_launch(void* const* d_in, const int* in_sizes, int n_in,
                              void* d_out, int out_size) {
    const float* x   = (const float*)d_in[0];
    const int*   ei  = (const int*)  d_in[1];
    const float* ew  = (const float*)d_in[2];
    const float* W1  = (const float*)d_in[4];
    const float* b1  = (const float*)d_in[5];
    const float* g1  = (const float*)d_in[6];
    const float* bt1 = (const float*)d_in[7];
    const float* W2  = (const float*)d_in[8];
    const float* b2  = (const float*)d_in[9];
    const float* g2  = (const float*)d_in[10];
    const float* bt2 = (const float*)d_in[11];
    const float* pp  = (const float*)d_in[12];
    const float* W3  = (const float*)d_in[13];
    const float* b3  = (const float*)d_in[14];
    const float* g3  = (const float*)d_in[15];
    const float* bt3 = (const float*)d_in[16];
    const float* f1w = (const float*)d_in[17];
    const float* f1b = (const float*)d_in[18];
    const float* gfc = (const float*)d_in[19];
    const float* bfc = (const float*)d_in[20];
    const float* f2w = (const float*)d_in[21];
    const float* f2b = (const float*)d_in[22];
    float* out = (float*)d_out;

    const int* src = ei;
    const int* dst = ei + Etot;

    float *p_xw1, *p_h1, *p_xw2, *p_h2, *p_xw3;
    float *p_dis, *p_mask, *p_gate, *p_ebw;
    unsigned short* p_ebsrc;
    int* p_eoff;
    __nv_bfloat16 *p_w1h, *p_w1l, *p_w2h, *p_w2l, *p_w3h, *p_w3l;
    cudaGetSymbolAddress((void**)&p_xw1,  g_xw1);
    cudaGetSymbolAddress((void**)&p_h1,   g_h1);
    cudaGetSymbolAddress((void**)&p_xw2,  g_xw2);
    cudaGetSymbolAddress((void**)&p_h2,   g_h2);
    cudaGetSymbolAddress((void**)&p_xw3,  g_xw3);
    cudaGetSymbolAddress((void**)&p_dis,  g_dis);
    cudaGetSymbolAddress((void**)&p_mask, g_mask);
    cudaGetSymbolAddress((void**)&p_gate, g_gate);
    cudaGetSymbolAddress((void**)&p_ebsrc,g_ebsrc);
    cudaGetSymbolAddress((void**)&p_ebw,  g_ebw);
    cudaGetSymbolAddress((void**)&p_eoff, g_eoff);
    cudaGetSymbolAddress((void**)&p_w1h,  g_w1h);
    cudaGetSymbolAddress((void**)&p_w1l,  g_w1l);
    cudaGetSymbolAddress((void**)&p_w2h,  g_w2h);
    cudaGetSymbolAddress((void**)&p_w2l,  g_w2l);
    cudaGetSymbolAddress((void**)&p_w3h,  g_w3h);
    cudaGetSymbolAddress((void**)&p_w3l,  g_w3l);

    constexpr int SM1 = wg_smem(64);
    constexpr int SM3 = wg_smem(128);
    cudaFuncSetAttribute((const void*)wgemm_kernel<64, 400, false>,
                         cudaFuncAttributeMaxDynamicSharedMemorySize, SM1);
    cudaFuncSetAttribute((const void*)wgemm_kernel<64, 64, false>,
                         cudaFuncAttributeMaxDynamicSharedMemorySize, SM1);
    cudaFuncSetAttribute((const void*)wgemm_kernel<128, 64, true>,
                         cudaFuncAttributeMaxDynamicSharedMemorySize, SM3);
    cudaFuncSetAttribute(agg1_kernel, cudaFuncAttributeMaxDynamicSharedMemorySize, SMEM_AGG1);
    cudaFuncSetAttribute(agg2_kernel, cudaFuncAttributeMaxDynamicSharedMemorySize, SMEM_AGG2);
    cudaFuncSetAttribute(agg3_kernel, cudaFuncAttributeMaxDynamicSharedMemorySize, SMEM_AGG3);

    // 0: weight split
    wconv_all_kernel<<<(448*64 + 64*64 + 64*128 + 255) / 256, 256>>>(
        W1, W2, W3, p_w1h, p_w1l, p_w2h, p_w2l, p_w3h, p_w3l);

    // 1: GCN1 GEMM (batched A loads)
    wgemm_kernel<64, 400, false><<<Ntot / 128, 256, SM1>>>(x, p_w1h, p_w1l, nullptr, p_xw1);
    // 2: GCN1 aggregation (2 CTAs/SM; smem-union CSR build + global-CSR gather)
    agg1_kernel<<<Bg, AT, SMEM_AGG1>>>(p_xw1, src, dst, ew, b1, g1, bt1, p_h1,
                                       p_dis, p_ebsrc, p_ebw, p_eoff);
    // 3: GCN2 GEMM
    wgemm_kernel<64, 64, false><<<Ntot / 128, 256, SM1>>>(p_h1, p_w2h, p_w2l, nullptr, p_xw2);
    // 4: GCN2 aggregation (global CSR; fused score + topk)
    agg2_kernel<<<Bg, AT, SMEM_AGG2>>>(p_xw2, p_dis, p_ebsrc, p_ebw, p_eoff, pp,
                                       b2, g2, bt2, p_h2, p_mask, p_gate);
    // 5: GCN3 GEMM (rows gated by score*mask)
    wgemm_kernel<128, 64, true><<<Ntot / 128, 256, SM3>>>(p_h2, p_w3h, p_w3l, p_gate, p_xw3);
    // 6: GCN3 aggregation + readout + FUSED head
    agg3_kernel<<<Bg, AT, SMEM_AGG3>>>(p_xw3, p_mask, p_ebsrc, p_ebw, p_eoff,
                                       b3, g3, bt3, f1w, f1b, gfc, bfc, f2w, f2b, out);
}

// round 16
// speedup vs baseline: 1.3334x; 1.0293x over previous
#include <cuda_runtime.h>
#include <cuda_bf16.h>
#include <mma.h>
#include <math.h>
#include <stdint.h>

using namespace nvcuda;

// ---------------- problem constants ----------------
constexpr int Bg   = 256;     // graphs
constexpr int NPG  = 400;     // nodes per graph
constexpr int Ntot = Bg * NPG;        // 102400
constexpr int EPG  = 8000;    // edges per graph
constexpr int Etot = Bg * EPG;        // 2048000
constexpr int CIN  = 400;
constexpr int H    = 64;
constexpr int H3   = 128;
constexpr int KEEP = 200;
constexpr int AT   = 512;     // agg kernel threads
constexpr int AW   = AT / 32; // 16 warps
#define BN_RS 0.99999500003749968f  /* rsqrt(1+1e-5) */

// ---------------- scratch (device globals; no allocation allowed) ----------------
__device__ float g_xw1[Ntot * H];
__device__ float g_h1 [Ntot * H];
__device__ float g_xw2[Ntot * H];
__device__ float g_h2 [Ntot * H];
__device__ float g_xw3[Ntot * H3];
__device__ float g_dis [Ntot];
__device__ float g_dis3[Ntot];
__device__ float g_mask[Ntot];
__device__ float g_gate[Ntot];
// prebuilt per-graph CSR buckets (built by agg1, reused by agg2)
__device__ unsigned short g_ebsrc[Etot];
__device__ float g_ebw[Etot];
__device__ int   g_eoff[Ntot];        // inclusive per-graph-local offsets
// compacted layer-3 CSR (built by agg2; only surviving edges)
__device__ unsigned short g_eb3src[Etot];
__device__ float g_eb3w[Etot];
__device__ int   g_eoff3[Ntot];
// split bf16 weights, row-major [KPAD][CO]
__device__ __nv_bfloat16 g_w1h[448 * 64];
__device__ __nv_bfloat16 g_w1l[448 * 64];
__device__ __nv_bfloat16 g_w2h[64 * 64];
__device__ __nv_bfloat16 g_w2l[64 * 64];
__device__ __nv_bfloat16 g_w3h[64 * 128];
__device__ __nv_bfloat16 g_w3l[64 * 128];

__device__ __forceinline__ uint32_t pack_bf2(__nv_bfloat16 a, __nv_bfloat16 b) {
    __nv_bfloat162 t = __halves2bfloat162(a, b);
    return *reinterpret_cast<uint32_t*>(&t);
}

// ---------------- all-weights bf16 split (single launch) ----------------
__global__ void wconv_all_kernel(const float* __restrict__ W1, const float* __restrict__ W2,
                                 const float* __restrict__ W3,
                                 __nv_bfloat16* __restrict__ w1h, __nv_bfloat16* __restrict__ w1l,
                                 __nv_bfloat16* __restrict__ w2h, __nv_bfloat16* __restrict__ w2l,
                                 __nv_bfloat16* __restrict__ w3h, __nv_bfloat16* __restrict__ w3l) {
    int i = blockIdx.x * 256 + threadIdx.x;
    const float* W; __nv_bfloat16 *hi, *lo; int idx; int kdim, co;
    if (i < 448 * 64)            { W = W1; hi = w1h; lo = w1l; idx = i;             kdim = 400; co = 64; }
    else if (i < 448*64 + 64*64) { W = W2; hi = w2h; lo = w2l; idx = i - 448*64;    kdim = 64;  co = 64; }
    else if (i < 448*64 + 64*64 + 64*128)
                                 { W = W3; hi = w3h; lo = w3l; idx = i - 448*64 - 64*64; kdim = 64; co = 128; }
    else return;
    int k = idx / co;
    float v = (k < kdim) ? W[idx] : 0.f;
    __nv_bfloat16 h = __float2bfloat16(v);
    hi[idx] = h;
    lo[idx] = __float2bfloat16(v - __bfloat162float(h));
}

// ---------------- wmma bf16x3 GEMM: out[M,CO] = X[M,KDIM] @ W[KDIM,CO] ----------------
// A-chunk loads batched (MLP=8) before the convert/store phase.
template<int CO, int KDIM, bool SCALE>
__global__ void __launch_bounds__(256) wgemm_kernel(
        const float* __restrict__ X,
        const __nv_bfloat16* __restrict__ wh,
        const __nv_bfloat16* __restrict__ wl,
        const float* __restrict__ rowscale,
        float* __restrict__ out) {
    constexpr int KCH = (KDIM + 63) / 64;
    constexpr int LDA = 72;
    constexpr int LDB = CO + 8;
    constexpr int NT  = CO / 16;

    extern __shared__ char smraw[];
    __nv_bfloat16* Ah = (__nv_bfloat16*)smraw;      // 128*LDA
    __nv_bfloat16* Al = Ah + 128 * LDA;
    __nv_bfloat16* Bh = Al + 128 * LDA;             // 64*LDB
    __nv_bfloat16* Bl = Bh + 64 * LDB;
    float* sOut = (float*)smraw;                    // union: 128*LDB floats

    const int tid  = threadIdx.x;
    const int warp = tid >> 5;
    const int rb   = blockIdx.x * 128;

    wmma::fragment<wmma::accumulator, 16, 16, 16, float> acc[NT];
    #pragma unroll
    for (int t = 0; t < NT; t++) wmma::fill_fragment(acc[t], 0.f);

    for (int ch = 0; ch < KCH; ch++) {
        const int kb = ch * 64;
        __syncthreads();
        // A chunk: batch ALL 8 LDG.128s first (amortize DRAM latency), then convert
        {
            float4 v[8];
            #pragma unroll
            for (int u = 0; u < 8; u++) {
                int i = tid * 4 + u * 1024;
                int r = i >> 6, c = i & 63;
                if ((KDIM & 63) == 0 || kb + c < KDIM)
                    v[u] = *(const float4*)&X[(size_t)(rb + r) * KDIM + kb + c];
                else
                    v[u] = make_float4(0.f, 0.f, 0.f, 0.f);
            }
            #pragma unroll
            for (int u = 0; u < 8; u++) {
                int i = tid * 4 + u * 1024;
                int r = i >> 6, c = i & 63;
                __nv_bfloat16 h0 = __float2bfloat16(v[u].x);
                __nv_bfloat16 h1 = __float2bfloat16(v[u].y);
                __nv_bfloat16 h2 = __float2bfloat16(v[u].z);
                __nv_bfloat16 h3 = __float2bfloat16(v[u].w);
                __nv_bfloat16 l0 = __float2bfloat16(v[u].x - __bfloat162float(h0));
                __nv_bfloat16 l1 = __float2bfloat16(v[u].y - __bfloat162float(h1));
                __nv_bfloat16 l2 = __float2bfloat16(v[u].z - __bfloat162float(h2));
                __nv_bfloat16 l3 = __float2bfloat16(v[u].w - __bfloat162float(h3));
                *(uint2*)&Ah[r * LDA + c] = make_uint2(pack_bf2(h0, h1), pack_bf2(h2, h3));
                *(uint2*)&Al[r * LDA + c] = make_uint2(pack_bf2(l0, l1), pack_bf2(l2, l3));
            }
        }
        // B chunk: 64 x CO bf16 (pre-split; L2-resident after first CTAs)
        #pragma unroll 2
        for (int i = tid * 4; i < 64 * CO; i += 1024) {
            int r = i / CO, c = i & (CO - 1);
            *(uint2*)&Bh[r * LDB + c] = *(const uint2*)&wh[(size_t)(kb + r) * CO + c];
            *(uint2*)&Bl[r * LDB + c] = *(const uint2*)&wl[(size_t)(kb + r) * CO + c];
        }
        __syncthreads();

        const __nv_bfloat16* arow_h = Ah + (warp * 16) * LDA;
        const __nv_bfloat16* arow_l = Al + (warp * 16) * LDA;
        #pragma unroll
        for (int k16 = 0; k16 < 4; k16++) {
            wmma::fragment<wmma::matrix_a, 16, 16, 16, __nv_bfloat16, wmma::row_major> fa_h, fa_l;
            wmma::load_matrix_sync(fa_h, arow_h + k16 * 16, LDA);
            wmma::load_matrix_sync(fa_l, arow_l + k16 * 16, LDA);
            #pragma unroll
            for (int t = 0; t < NT; t++) {
                wmma::fragment<wmma::matrix_b, 16, 16, 16, __nv_bfloat16, wmma::row_major> fb_h, fb_l;
                wmma::load_matrix_sync(fb_h, Bh + (k16 * 16) * LDB + t * 16, LDB);
                wmma::load_matrix_sync(fb_l, Bl + (k16 * 16) * LDB + t * 16, LDB);
                wmma::mma_sync(acc[t], fa_h, fb_h, acc[t]);
                wmma::mma_sync(acc[t], fa_h, fb_l, acc[t]);
                wmma::mma_sync(acc[t], fa_l, fb_h, acc[t]);
            }
        }
    }
    __syncthreads();
    #pragma unroll
    for (int t = 0; t < NT; t++)
        wmma::store_matrix_sync(sOut + (warp * 16) * LDB + t * 16, acc[t], LDB,
                                wmma::mem_row_major);
    __syncthreads();
    #pragma unroll 2
    for (int i = tid * 4; i < 128 * CO; i += 1024) {
        int r = i / CO, c = i & (CO - 1);
        float4 v = *(float4*)&sOut[r * LDB + c];
        float rs = 1.f;
        if (SCALE) rs = rowscale[rb + r];
        v.x *= rs; v.y *= rs; v.z *= rs; v.w *= rs;
        *(float4*)&out[(size_t)(rb + r) * CO + c] = v;
    }
}

constexpr int wg_smem(int CO) {
    int lda = 72, ldb = CO + 8;
    int ab = (2 * 128 * lda + 2 * 64 * ldb) * 2;
    int os = 128 * ldb * 4;
    return ab > os ? ab : os;
}

// ---------------- shared gather helper: 4x-unrolled CSR edge accumulation ----------------
__device__ __forceinline__ void gather_row(const unsigned short* __restrict__ bsrc,
                                           const float* __restrict__ bw,
                                           const float* __restrict__ ysm,
                                           int e0, int e1, int lane,
                                           float& a0, float& a1) {
    int j = e0;
    for (; j + 4 <= e1; j += 4) {
        int s0 = bsrc[j], s1 = bsrc[j + 1], s2 = bsrc[j + 2], s3 = bsrc[j + 3];
        float w0 = bw[j], w1 = bw[j + 1], w2 = bw[j + 2], w3 = bw[j + 3];
        float y00 = ysm[s0 * H + lane],      y01 = ysm[s0 * H + lane + 32];
        float y10 = ysm[s1 * H + lane],      y11 = ysm[s1 * H + lane + 32];
        float y20 = ysm[s2 * H + lane],      y21 = ysm[s2 * H + lane + 32];
        float y30 = ysm[s3 * H + lane],      y31 = ysm[s3 * H + lane + 32];
        a0 = fmaf(w0, y00, a0); a1 = fmaf(w0, y01, a1);
        a0 = fmaf(w1, y10, a0); a1 = fmaf(w1, y11, a1);
        a0 = fmaf(w2, y20, a0); a1 = fmaf(w2, y21, a1);
        a0 = fmaf(w3, y30, a0); a1 = fmaf(w3, y31, a1);
    }
    for (; j < e1; j++) {
        int sl = bsrc[j];
        float w = bw[j];
        a0 = fmaf(w, ysm[sl * H + lane],      a0);
        a1 = fmaf(w, ysm[sl * H + lane + 32], a1);
    }
}

// ======================================================================
// agg1: CSR build in smem (bucket region UNIONed with ysm) -> persist to
//       global -> reload region as ysm -> gather from GLOBAL CSR.
// ======================================================================
constexpr int SMEM_AGG1 = NPG*H*4 + NPG*4 + NPG*4 + 512*4;
constexpr int EPT = (EPG + AT - 1) / AT;   // 16 edges max per thread

__global__ void __launch_bounds__(AT, 2) agg1_kernel(
                            const float* __restrict__ xw,
                            const int* __restrict__ src, const int* __restrict__ dstp,
                            const float* __restrict__ ew,
                            const float* __restrict__ bias, const float* __restrict__ gam,
                            const float* __restrict__ bet, float* __restrict__ out,
                            float* __restrict__ dis_out,
                            unsigned short* __restrict__ ebsrc_out,
                            float* __restrict__ ebw_out, int* __restrict__ eoff_out) {
    extern __shared__ float smf[];
    float* ysm = smf;                         // [NPG*H]; FIRST used as bucket space
    float* dsm = ysm + NPG * H;
    int*   cn  = (int*)(dsm + NPG);
    int*   sc  = cn + NPG;
    float* bw  = ysm;                         // [EPG] 32000B
    unsigned short* bsrc = (unsigned short*)(ysm + EPG);  // [EPG] 16000B

    const int g = blockIdx.x;
    const int nb = g * NPG;
    const int eb = g * EPG;
    const int tid = threadIdx.x;
    const int lane = tid & 31;
    const int warp = tid >> 5;

    for (int i = tid; i < NPG; i += AT) cn[i] = 0;
    __syncthreads();

    // single atomic pass: claim per-dst ranks, pack (sl | dl<<9 | rank<<18)
    int pk[EPT];
    #pragma unroll
    for (int u = 0; u < EPT; u++) {
        int e = tid + u * AT;
        pk[u] = -1;
        if (e < EPG) {
            int sl = src[eb + e] - nb;
            int dl = dstp[eb + e] - nb;
            int r  = atomicAdd(&cn[dl], 1);
            pk[u] = sl | (dl << 9) | (r << 18);
        }
    }
    __syncthreads();

    // inclusive scan of counts
    sc[tid] = (tid < NPG) ? cn[tid] : 0;
    __syncthreads();
    #pragma unroll
    for (int off = 1; off < 512; off <<= 1) {
        int v = sc[tid];
        int a = (tid >= off) ? sc[tid - off] : 0;
        __syncthreads();
        sc[tid] = v + a;
        __syncthreads();
    }
    for (int i = tid; i < NPG; i += AT) eoff_out[nb + i] = sc[i];
    __syncthreads();

    // rank-directed scatter into smem buckets (no atomics)
    #pragma unroll
    for (int u = 0; u < EPT; u++) {
        int e = tid + u * AT;
        if (pk[u] >= 0) {
            int sl = pk[u] & 511;
            int dl = (pk[u] >> 9) & 511;
            int r  = pk[u] >> 18;
            int pos = (dl ? sc[dl - 1] : 0) + r;
            bsrc[pos] = (unsigned short)sl;
            bw[pos]   = ew[eb + e];
        }
    }
    __syncthreads();

    // degree via per-dst bucket sum (deterministic, no float atomics)
    for (int dl = warp; dl < NPG; dl += AW) {
        int e0 = dl ? sc[dl - 1] : 0;
        int e1 = sc[dl];
        float s = 0.f;
        for (int j = e0 + lane; j < e1; j += 32) s += bw[j];
        #pragma unroll
        for (int o = 16; o; o >>= 1) s += __shfl_xor_sync(0xffffffffu, s, o);
        if (lane == 0) {
            float d = rsqrtf(1.f + s);      // self-loop weight 1
            dsm[dl] = d;
            dis_out[nb + dl] = d;
        }
    }
    __syncthreads();

    // persist buckets to global (coalesced) BEFORE overwriting region with ysm
    for (int i = tid * 8; i < EPG; i += AT * 8)
        *(uint4*)&ebsrc_out[eb + i] = *(const uint4*)&bsrc[i];
    for (int i = tid * 4; i < EPG; i += AT * 4)
        *(float4*)&ebw_out[eb + i] = *(const float4*)&bw[i];
    __syncthreads();

    // now reuse region as ysm = dis * xW
    for (int i = tid * 4; i < NPG * H; i += AT * 4) {
        int node = i >> 6;
        float4 v = *(const float4*)&xw[(size_t)(nb + node) * H + (i & 63)];
        float d = dsm[node];
        v.x *= d; v.y *= d; v.z *= d; v.w *= d;
        *(float4*)&ysm[i] = v;
    }
    __syncthreads();

    // gather from GLOBAL CSR
    const unsigned short* gb = ebsrc_out + eb;
    const float* gw = ebw_out + eb;
    const float s0 = gam[lane] * BN_RS,      s1 = gam[lane + 32] * BN_RS;
    const float t0 = bet[lane],              t1 = bet[lane + 32];
    const float bb0 = bias[lane],            bb1 = bias[lane + 32];
    for (int dl = warp; dl < NPG; dl += AW) {
        int e0 = dl ? sc[dl - 1] : 0;
        int e1 = sc[dl];
        float a0 = ysm[dl * H + lane];
        float a1 = ysm[dl * H + lane + 32];
        gather_row(gb, gw, ysm, e0, e1, lane, a0, a1);
        float d = dsm[dl];
        float v0 = fmaf(d, a0, bb0);
        float v1 = fmaf(d, a1, bb1);
        v0 = fmaxf(fmaf(v0, s0, t0), 0.f);
        v1 = fmaxf(fmaf(v1, s1, t1), 0.f);
        size_t o = (size_t)(nb + dl) * H;
        out[o + lane] = v0;
        out[o + lane + 32] = v1;
    }
}

// ======================================================================
// agg2: gather + bias/BN/ReLU + fused score + fused top-k -> mask/gate
//       + COMPACTED layer-3 CSR build (surviving edges only) + dis3
// ======================================================================
constexpr int SMEM_AGG2 = (NPG*H + 2*NPG)*4;

__global__ void __launch_bounds__(AT, 2) agg2_kernel(
                            const float* __restrict__ xw, const float* __restrict__ dis,
                            const unsigned short* __restrict__ ebsrc,
                            const float* __restrict__ ebw, const int* __restrict__ eoff,
                            const float* __restrict__ ew_p,   // pool vector
                            const float* __restrict__ bias, const float* __restrict__ gam,
                            const float* __restrict__ bet, float* __restrict__ out,
                            float* __restrict__ mask, float* __restrict__ gate,
                            unsigned short* __restrict__ eb3src_out,
                            float* __restrict__ eb3w_out, int* __restrict__ eoff3_out,
                            float* __restrict__ dis3_out) {
    extern __shared__ float smf[];
    float* ysm = smf;
    float* dsm = ysm + NPG * H;
    float* ssc = dsm + NPG;               // [NPG] scores

    const int g = blockIdx.x;
    const int nb = g * NPG;
    const int eb = g * EPG;
    const int tid = threadIdx.x;

    for (int i = tid; i < NPG; i += AT) dsm[i] = dis[nb + i];
    __syncthreads();

    for (int i = tid * 4; i < NPG * H; i += AT * 4) {
        int node = i >> 6;
        float4 v = *(const float4*)&xw[(size_t)(nb + node) * H + (i & 63)];
        float d = dsm[node];
        v.x *= d; v.y *= d; v.z *= d; v.w *= d;
        *(float4*)&ysm[i] = v;
    }
    __syncthreads();

    const int lane = tid & 31;
    const int warp = tid >> 5;
    const float s0 = gam[lane] * BN_RS,      s1 = gam[lane + 32] * BN_RS;
    const float t0 = bet[lane],              t1 = bet[lane + 32];
    const float bb0 = bias[lane],            bb1 = bias[lane + 32];
    const float p0 = ew_p[lane], p1 = ew_p[lane + 32];
    float pn = p0 * p0 + p1 * p1;
    #pragma unroll
    for (int o = 16; o; o >>= 1) pn += __shfl_xor_sync(0xffffffffu, pn, o);
    const float ipn = rsqrtf(pn);

    const unsigned short* gb = ebsrc + eb;
    const float* gw = ebw + eb;
    for (int dl = warp; dl < NPG; dl += AW) {
        int e1 = eoff[nb + dl];
        int e0 = dl ? eoff[nb + dl - 1] : 0;
        float a0 = ysm[dl * H + lane];
        float a1 = ysm[dl * H + lane + 32];
        gather_row(gb, gw, ysm, e0, e1, lane, a0, a1);
        float d = dsm[dl];
        float v0 = fmaf(d, a0, bb0);
        float v1 = fmaf(d, a1, bb1);
        v0 = fmaxf(fmaf(v0, s0, t0), 0.f);
        v1 = fmaxf(fmaf(v1, s1, t1), 0.f);
        size_t o = (size_t)(nb + dl) * H;
        out[o + lane] = v0;
        out[o + lane + 32] = v1;
        float dsc = v0 * p0 + v1 * p1;
        #pragma unroll
        for (int of = 16; of; of >>= 1) dsc += __shfl_xor_sync(0xffffffffu, dsc, of);
        if (lane == 0) ssc[dl] = tanhf(dsc * ipn);
    }
    __syncthreads();   // scores done; ysm now dead -> reuse

    float* sortb = ysm;                                // [512]
    unsigned char* km = (unsigned char*)(ysm + 512);   // [NPG] (100 floats)
    int* cntp = (int*)(ysm + 1024);
    for (int i = tid; i < 512; i += AT) sortb[i] = (i < NPG) ? ssc[i] : -INFINITY;
    if (tid == 0) *cntp = 0;
    __syncthreads();
    // bitonic sort ascending, 512 elems, 1 elem/thread
    #pragma unroll
    for (int k = 2; k <= 512; k <<= 1) {
        #pragma unroll
        for (int j = k >> 1; j > 0; j >>= 1) {
            int ixj = tid ^ j;
            if (ixj > tid) {
                float a = sortb[tid], b = sortb[ixj];
                bool sw = ((tid & k) == 0) ? (a > b) : (a < b);
                if (sw) { sortb[tid] = b; sortb[ixj] = a; }
            }
            __syncthreads();
        }
    }
    float thr = sortb[512 - KEEP];     // 200th largest
    int local = 0;
    for (int i = tid; i < NPG; i += AT)
        if (ssc[i] > thr) local++;
    atomicAdd(cntp, local);
    __syncthreads();
    if (tid == 0) {   // tie-break: lowest index first (matches lax.top_k)
        int rem = KEEP - *cntp;
        for (int i = 0; i < NPG; i++) {
            unsigned char m = (ssc[i] > thr) ? 1 : 0;
            if (!m && ssc[i] == thr && rem > 0) { m = 1; rem--; }
            km[i] = m;
        }
    }
    __syncthreads();
    for (int i = tid; i < NPG; i += AT) {
        float m = km[i] ? 1.f : 0.f;
        mask[nb + i] = m;
        gate[nb + i] = m * ssc[i];
    }

    // ---- compacted layer-3 CSR build ----
    int*   cn3  = (int*)(ysm + 2048);      // [512]
    float* deg3 = ysm + 2688;              // [NPG]
    __syncthreads();
    // phase A: surviving count + degree per dst
    for (int dl = warp; dl < NPG; dl += AW) {
        int cnt = 0; float s = 0.f;
        if (km[dl]) {
            int e1 = eoff[nb + dl];
            int e0 = dl ? eoff[nb + dl - 1] : 0;
            for (int j = e0 + lane; j < e1; j += 32) {
                if (km[gb[j]]) { cnt++; s += gw[j]; }
            }
        }
        #pragma unroll
        for (int o = 16; o; o >>= 1) {
            cnt += __shfl_xor_sync(0xffffffffu, cnt, o);
            s   += __shfl_xor_sync(0xffffffffu, s,   o);
        }
        if (lane == 0) { cn3[dl] = cnt; deg3[dl] = s; }
    }
    if (tid >= NPG && tid < 512) cn3[tid] = 0;
    __syncthreads();
    // inclusive scan cn3
    #pragma unroll
    for (int off = 1; off < 512; off <<= 1) {
        int v = cn3[tid];
        int a = (tid >= off) ? cn3[tid - off] : 0;
        __syncthreads();
        cn3[tid] = v + a;
        __syncthreads();
    }
    for (int i = tid; i < NPG; i += AT) {
        eoff3_out[nb + i] = cn3[i];
        dis3_out[nb + i]  = km[i] ? rsqrtf(1.f + deg3[i]) : 0.f;
    }
    __syncthreads();
    // phase B: ballot compaction into global compacted CSR
    unsigned short* c3s = eb3src_out + eb;
    float* c3w = eb3w_out + eb;
    for (int dl = warp; dl < NPG; dl += AW) {
        if (!km[dl]) continue;
        int e1 = eoff[nb + dl];
        int e0 = dl ? eoff[nb + dl - 1] : 0;
        int pos = dl ? cn3[dl - 1] : 0;
        for (int j0 = e0; j0 < e1; j0 += 32) {
            int j = j0 + lane;
            bool act = false; int sl = 0; float w = 0.f;
            if (j < e1) {
                sl = gb[j]; w = gw[j];
                act = (km[sl] != 0);
            }
            unsigned m = __ballot_sync(0xffffffffu, act);
            int off = __popc(m & ((1u << lane) - 1u));
            if (act) { c3s[pos + off] = (unsigned short)sl; c3w[pos + off] = w; }
            pos += __popc(m);
        }
    }
}

// ======================================================================
// agg3: COMPACTED CSR (surviving edges only); no degree pass, no mask
//       array; gather + BN/ReLU + mean/max readout + FUSED MLP head
// ======================================================================
constexpr int SMEM_AGG3 = (NPG*H + NPG)*4 + 2 * AW * 64 * 4;

__global__ void __launch_bounds__(AT, 2) agg3_kernel(
                            const float* __restrict__ xw,
                            const float* __restrict__ dis3,
                            const unsigned short* __restrict__ eb3src,
                            const float* __restrict__ eb3w, const int* __restrict__ eoff3,
                            const float* __restrict__ bias, const float* __restrict__ gam,
                            const float* __restrict__ bet,
                            const float* __restrict__ f1w, const float* __restrict__ f1b,
                            const float* __restrict__ gfc, const float* __restrict__ bfc,
                            const float* __restrict__ f2w, const float* __restrict__ f2b,
                            float* __restrict__ outp) {
    extern __shared__ float smf[];
    float* ysm = smf;
    float* dsm = ysm + NPG * H;
    float* psum = dsm + NPG;             // [AW][64]
    float* pmax = psum + AW * 64;        // [AW][64]

    const int g = blockIdx.x;
    const int nb = g * NPG;
    const int eb = g * EPG;
    const int tid = threadIdx.x;
    const int lane = tid & 31;
    const int warp = tid >> 5;

    for (int i = tid; i < NPG; i += AT) dsm[i] = dis3[nb + i];   // 0 => dropped
    __syncthreads();

    const unsigned short* gb = eb3src + eb;
    const float* gw = eb3w + eb;

    float hmean[2], hmax[2];
    #pragma unroll
    for (int hf = 0; hf < 2; hf++) {
        if (hf) __syncthreads();
        // ysm = dis3 * xw3 half; dropped nodes -> 0 (dis3=0 AND xw3 row gated to 0)
        for (int i = tid * 4; i < NPG * H; i += AT * 4) {
            int node = i >> 6;
            float4 v = *(const float4*)&xw[(size_t)(nb + node) * H3 + hf * H + (i & 63)];
            float d = dsm[node];
            v.x *= d; v.y *= d; v.z *= d; v.w *= d;
            *(float4*)&ysm[i] = v;
        }
        __syncthreads();
        const int f0 = hf * H + lane, f1 = hf * H + lane + 32;
        const float s0 = gam[f0] * BN_RS, s1 = gam[f1] * BN_RS;
        const float t0 = bet[f0],         t1 = bet[f1];
        const float bb0 = bias[f0],       bb1 = bias[f1];
        float sum0 = 0.f, sum1 = 0.f, mx0 = -INFINITY, mx1 = -INFINITY;
        for (int dl = warp; dl < NPG; dl += AW) {
            float d = dsm[dl];
            if (d == 0.f) continue;         // dropped dst
            int e1 = eoff3[nb + dl];
            int e0 = dl ? eoff3[nb + dl - 1] : 0;
            float a0 = ysm[dl * H + lane];
            float a1 = ysm[dl * H + lane + 32];
            gather_row(gb, gw, ysm, e0, e1, lane, a0, a1);  // all edges survive
            float v0 = fmaf(d, a0, bb0);
            float v1 = fmaf(d, a1, bb1);
            v0 = fmaxf(fmaf(v0, s0, t0), 0.f);
            v1 = fmaxf(fmaf(v1, s1, t1), 0.f);
            sum0 += v0; sum1 += v1;
            mx0 = fmaxf(mx0, v0); mx1 = fmaxf(mx1, v1);
        }
        psum[warp * 64 + lane]      = sum0;
        psum[warp * 64 + lane + 32] = sum1;
        pmax[warp * 64 + lane]      = mx0;
        pmax[warp * 64 + lane + 32] = mx1;
        __syncthreads();
        if (tid < 64) {   // deterministic fixed-order combine, kept in registers
            float s = 0.f, m = -INFINITY;
            #pragma unroll
            for (int w = 0; w < AW; w++) {
                s += psum[w * 64 + tid];
                m = fmaxf(m, pmax[w * 64 + tid]);
            }
            hmean[hf] = s * (1.f / KEEP);
            hmax[hf]  = m;
        }
    }
    __syncthreads();   // partial arrays now dead

    // ---- fused MLP head ----
    float* semb = psum;          // [256] emb = [mean0|mean1|max0|max1]
    float* zz   = pmax;          // [64]
    if (tid < 64) {
        semb[tid]       = hmean[0];
        semb[64 + tid]  = hmean[1];
        semb[128 + tid] = hmax[0];
        semb[192 + tid] = hmax[1];
    }
    __syncthreads();
    if (tid < 64) {
        float acc = f1b[tid];
        #pragma unroll 8
        for (int k = 0; k < 256; k++)
            acc = fmaf(semb[k], f1w[k * 64 + tid], acc);
        acc = fmaf(acc, gfc[tid] * BN_RS, bfc[tid]);
        zz[tid] = fmaxf(acc, 0.f);
    }
    __syncthreads();
    if (tid < 2) {
        float o = f2b[tid];
        #pragma unroll 8
        for (int k = 0; k < 64; k++)
            o = fmaf(zz[k], f2w[k * 2 + tid], o);
        outp[g * 2 + tid] = o;
    }
}

// ---------------- launch ----------------
extern "C" void kernel_launch(void* const* d_in, const int* in_sizes, int n_in,
                              void* d_out, int out_size) {
    const float* x   = (const float*)d_in[0];
    const int*   ei  = (const int*)  d_in[1];
    const float* ew  = (const float*)d_in[2];
    const float* W1  = (const float*)d_in[4];
    const float* b1  = (const float*)d_in[5];
    const float* g1  = (const float*)d_in[6];
    const float* bt1 = (const float*)d_in[7];
    const float* W2  = (const float*)d_in[8];
    const float* b2  = (const float*)d_in[9];
    const float* g2  = (const float*)d_in[10];
    const float* bt2 = (const float*)d_in[11];
    const float* pp  = (const float*)d_in[12];
    const float* W3  = (const float*)d_in[13];
    const float* b3  = (const float*)d_in[14];
    const float* g3  = (const float*)d_in[15];
    const float* bt3 = (const float*)d_in[16];
    const float* f1w = (const float*)d_in[17];
    const float* f1b = (const float*)d_in[18];
    const float* gfc = (const float*)d_in[19];
    const float* bfc = (const float*)d_in[20];
    const float* f2w = (const float*)d_in[21];
    const float* f2b = (const float*)d_in[22];
    float* out = (float*)d_out;

    const int* src = ei;
    const int* dst = ei + Etot;

    float *p_xw1, *p_h1, *p_xw2, *p_h2, *p_xw3;
    float *p_dis, *p_dis3, *p_mask, *p_gate, *p_ebw, *p_eb3w;
    unsigned short *p_ebsrc, *p_eb3src;
    int *p_eoff, *p_eoff3;
    __nv_bfloat16 *p_w1h, *p_w1l, *p_w2h, *p_w2l, *p_w3h, *p_w3l;
    cudaGetSymbolAddress((void**)&p_xw1,  g_xw1);
    cudaGetSymbolAddress((void**)&p_h1,   g_h1);
    cudaGetSymbolAddress((void**)&p_xw2,  g_xw2);
    cudaGetSymbolAddress((void**)&p_h2,   g_h2);
    cudaGetSymbolAddress((void**)&p_xw3,  g_xw3);
    cudaGetSymbolAddress((void**)&p_dis,  g_dis);
    cudaGetSymbolAddress((void**)&p_dis3, g_dis3);
    cudaGetSymbolAddress((void**)&p_mask, g_mask);
    cudaGetSymbolAddress((void**)&p_gate, g_gate);
    cudaGetSymbolAddress((void**)&p_ebsrc,g_ebsrc);
    cudaGetSymbolAddress((void**)&p_ebw,  g_ebw);
    cudaGetSymbolAddress((void**)&p_eoff, g_eoff);
    cudaGetSymbolAddress((void**)&p_eb3src,g_eb3src);
    cudaGetSymbolAddress((void**)&p_eb3w, g_eb3w);
    cudaGetSymbolAddress((void**)&p_eoff3,g_eoff3);
    cudaGetSymbolAddress((void**)&p_w1h,  g_w1h);
    cudaGetSymbolAddress((void**)&p_w1l,  g_w1l);
    cudaGetSymbolAddress((void**)&p_w2h,  g_w2h);
    cudaGetSymbolAddress((void**)&p_w2l,  g_w2l);
    cudaGetSymbolAddress((void**)&p_w3h,  g_w3h);
    cudaGetSymbolAddress((void**)&p_w3l,  g_w3l);

    constexpr int SM1 = wg_smem(64);
    constexpr int SM3 = wg_smem(128);
    cudaFuncSetAttribute((const void*)wgemm_kernel<64, 400, false>,
                         cudaFuncAttributeMaxDynamicSharedMemorySize, SM1);
    cudaFuncSetAttribute((const void*)wgemm_kernel<64, 64, false>,
                         cudaFuncAttributeMaxDynamicSharedMemorySize, SM1);
    cudaFuncSetAttribute((const void*)wgemm_kernel<128, 64, true>,
                         cudaFuncAttributeMaxDynamicSharedMemorySize, SM3);
    cudaFuncSetAttribute(agg1_kernel, cudaFuncAttributeMaxDynamicSharedMemorySize, SMEM_AGG1);
    cudaFuncSetAttribute(agg2_kernel, cudaFuncAttributeMaxDynamicSharedMemorySize, SMEM_AGG2);
    cudaFuncSetAttribute(agg3_kernel, cudaFuncAttributeMaxDynamicSharedMemorySize, SMEM_AGG3);

    // 0: weight split
    wconv_all_kernel<<<(448*64 + 64*64 + 64*128 + 255) / 256, 256>>>(
        W1, W2, W3, p_w1h, p_w1l, p_w2h, p_w2l, p_w3h, p_w3l);

    // 1: GCN1 GEMM (batched A loads)
    wgemm_kernel<64, 400, false><<<Ntot / 128, 256, SM1>>>(x, p_w1h, p_w1l, nullptr, p_xw1);
    // 2: GCN1 aggregation (smem-union CSR build + global-CSR gather)
    agg1_kernel<<<Bg, AT, SMEM_AGG1>>>(p_xw1, src, dst, ew, b1, g1, bt1, p_h1,
                                       p_dis, p_ebsrc, p_ebw, p_eoff);
    // 3: GCN2 GEMM
    wgemm_kernel<64, 64, false><<<Ntot / 128, 256, SM1>>>(p_h1, p_w2h, p_w2l, nullptr, p_xw2);
    // 4: GCN2 aggregation (fused score + topk + compacted layer-3 CSR + dis3)
    agg2_kernel<<<Bg, AT, SMEM_AGG2>>>(p_xw2, p_dis, p_ebsrc, p_ebw, p_eoff, pp,
                                       b2, g2, bt2, p_h2, p_mask, p_gate,
                                       p_eb3src, p_eb3w, p_eoff3, p_dis3);
    // 5: GCN3 GEMM (rows gated by score*mask)
    wgemm_kernel<128, 64, true><<<Ntot / 128, 256, SM3>>>(p_h2, p_w3h, p_w3l, p_gate, p_xw3);
    // 6: GCN3 aggregation on compacted CSR + readout + FUSED head
    agg3_kernel<<<Bg, AT, SMEM_AGG3>>>(p_xw3, p_dis3, p_eb3src, p_eb3w, p_eoff3,
                                       b3, g3, bt3, f1w, f1b, gfc, bfc, f2w, f2b, out);
}

// round 17
// speedup vs baseline: 1.4350x; 1.0762x over previous
#include <cuda_runtime.h>
#include <cuda_bf16.h>
#include <mma.h>
#include <math.h>
#include <stdint.h>

using namespace nvcuda;

// ---------------- problem constants ----------------
constexpr int Bg   = 256;     // graphs
constexpr int NPG  = 400;     // nodes per graph
constexpr int Ntot = Bg * NPG;        // 102400
constexpr int EPG  = 8000;    // edges per graph
constexpr int Etot = Bg * EPG;        // 2048000
constexpr int CIN  = 400;
constexpr int H    = 64;
constexpr int H3   = 128;
constexpr int KEEP = 200;
constexpr int NK   = Bg * KEEP;       // 51200 compacted rows
constexpr int AT   = 512;     // agg kernel threads
constexpr int AW   = AT / 32; // 16 warps
#define BN_RS 0.99999500003749968f  /* rsqrt(1+1e-5) */

// ---------------- scratch (device globals; no allocation allowed) ----------------
__device__ float g_xw1[Ntot * H];
__device__ float g_h1 [Ntot * H];     // also reused as compacted gated h2c [NK*H]
__device__ float g_xw2[Ntot * H];
__device__ float g_h2 [Ntot * H];
__device__ float g_xw3[Ntot * H3];    // holds compacted xw3c [NK*H3]
__device__ float g_dis [Ntot];
__device__ float g_dis3[NK];          // compacted
// prebuilt per-graph CSR buckets (built by agg1, reused by agg2)
__device__ unsigned short g_ebsrc[Etot];
__device__ float g_ebw[Etot];
__device__ int   g_eoff[Ntot];        // inclusive per-graph-local offsets
// compacted layer-3 CSR (built by agg2; rank-space srcs, surviving edges)
__device__ unsigned short g_eb3src[Etot];
__device__ float g_eb3w[Etot];
__device__ int   g_eoff3[NK];
// split bf16 weights, row-major [KPAD][CO]
__device__ __nv_bfloat16 g_w1h[448 * 64];
__device__ __nv_bfloat16 g_w1l[448 * 64];
__device__ __nv_bfloat16 g_w2h[64 * 64];
__device__ __nv_bfloat16 g_w2l[64 * 64];
__device__ __nv_bfloat16 g_w3h[64 * 128];
__device__ __nv_bfloat16 g_w3l[64 * 128];

__device__ __forceinline__ uint32_t pack_bf2(__nv_bfloat16 a, __nv_bfloat16 b) {
    __nv_bfloat162 t = __halves2bfloat162(a, b);
    return *reinterpret_cast<uint32_t*>(&t);
}

// ---------------- all-weights bf16 split (single launch) ----------------
__global__ void wconv_all_kernel(const float* __restrict__ W1, const float* __restrict__ W2,
                                 const float* __restrict__ W3,
                                 __nv_bfloat16* __restrict__ w1h, __nv_bfloat16* __restrict__ w1l,
                                 __nv_bfloat16* __restrict__ w2h, __nv_bfloat16* __restrict__ w2l,
                                 __nv_bfloat16* __restrict__ w3h, __nv_bfloat16* __restrict__ w3l) {
    int i = blockIdx.x * 256 + threadIdx.x;
    const float* W; __nv_bfloat16 *hi, *lo; int idx; int kdim, co;
    if (i < 448 * 64)            { W = W1; hi = w1h; lo = w1l; idx = i;             kdim = 400; co = 64; }
    else if (i < 448*64 + 64*64) { W = W2; hi = w2h; lo = w2l; idx = i - 448*64;    kdim = 64;  co = 64; }
    else if (i < 448*64 + 64*64 + 64*128)
                                 { W = W3; hi = w3h; lo = w3l; idx = i - 448*64 - 64*64; kdim = 64; co = 128; }
    else return;
    int k = idx / co;
    float v = (k < kdim) ? W[idx] : 0.f;
    __nv_bfloat16 h = __float2bfloat16(v);
    hi[idx] = h;
    lo[idx] = __float2bfloat16(v - __bfloat162float(h));
}

// ---------------- wmma bf16x3 GEMM: out[M,CO] = X[M,KDIM] @ W[KDIM,CO] ----------------
template<int CO, int KDIM>
__global__ void __launch_bounds__(256) wgemm_kernel(
        const float* __restrict__ X,
        const __nv_bfloat16* __restrict__ wh,
        const __nv_bfloat16* __restrict__ wl,
        float* __restrict__ out) {
    constexpr int KCH = (KDIM + 63) / 64;
    constexpr int LDA = 72;
    constexpr int LDB = CO + 8;
    constexpr int NT  = CO / 16;

    extern __shared__ char smraw[];
    __nv_bfloat16* Ah = (__nv_bfloat16*)smraw;      // 128*LDA
    __nv_bfloat16* Al = Ah + 128 * LDA;
    __nv_bfloat16* Bh = Al + 128 * LDA;             // 64*LDB
    __nv_bfloat16* Bl = Bh + 64 * LDB;
    float* sOut = (float*)smraw;                    // union: 128*LDB floats

    const int tid  = threadIdx.x;
    const int warp = tid >> 5;
    const int rb   = blockIdx.x * 128;

    wmma::fragment<wmma::accumulator, 16, 16, 16, float> acc[NT];
    #pragma unroll
    for (int t = 0; t < NT; t++) wmma::fill_fragment(acc[t], 0.f);

    for (int ch = 0; ch < KCH; ch++) {
        const int kb = ch * 64;
        __syncthreads();
        // A chunk: batch ALL 8 LDG.128s first (amortize DRAM latency), then convert
        {
            float4 v[8];
            #pragma unroll
            for (int u = 0; u < 8; u++) {
                int i = tid * 4 + u * 1024;
                int r = i >> 6, c = i & 63;
                if ((KDIM & 63) == 0 || kb + c < KDIM)
                    v[u] = *(const float4*)&X[(size_t)(rb + r) * KDIM + kb + c];
                else
                    v[u] = make_float4(0.f, 0.f, 0.f, 0.f);
            }
            #pragma unroll
            for (int u = 0; u < 8; u++) {
                int i = tid * 4 + u * 1024;
                int r = i >> 6, c = i & 63;
                __nv_bfloat16 h0 = __float2bfloat16(v[u].x);
                __nv_bfloat16 h1 = __float2bfloat16(v[u].y);
                __nv_bfloat16 h2 = __float2bfloat16(v[u].z);
                __nv_bfloat16 h3 = __float2bfloat16(v[u].w);
                __nv_bfloat16 l0 = __float2bfloat16(v[u].x - __bfloat162float(h0));
                __nv_bfloat16 l1 = __float2bfloat16(v[u].y - __bfloat162float(h1));
                __nv_bfloat16 l2 = __float2bfloat16(v[u].z - __bfloat162float(h2));
                __nv_bfloat16 l3 = __float2bfloat16(v[u].w - __bfloat162float(h3));
                *(uint2*)&Ah[r * LDA + c] = make_uint2(pack_bf2(h0, h1), pack_bf2(h2, h3));
                *(uint2*)&Al[r * LDA + c] = make_uint2(pack_bf2(l0, l1), pack_bf2(l2, l3));
            }
        }
        // B chunk: 64 x CO bf16 (pre-split; L2-resident after first CTAs)
        #pragma unroll 2
        for (int i = tid * 4; i < 64 * CO; i += 1024) {
            int r = i / CO, c = i & (CO - 1);
            *(uint2*)&Bh[r * LDB + c] = *(const uint2*)&wh[(size_t)(kb + r) * CO + c];
            *(uint2*)&Bl[r * LDB + c] = *(const uint2*)&wl[(size_t)(kb + r) * CO + c];
        }
        __syncthreads();

        const __nv_bfloat16* arow_h = Ah + (warp * 16) * LDA;
        const __nv_bfloat16* arow_l = Al + (warp * 16) * LDA;
        #pragma unroll
        for (int k16 = 0; k16 < 4; k16++) {
            wmma::fragment<wmma::matrix_a, 16, 16, 16, __nv_bfloat16, wmma::row_major> fa_h, fa_l;
            wmma::load_matrix_sync(fa_h, arow_h + k16 * 16, LDA);
            wmma::load_matrix_sync(fa_l, arow_l + k16 * 16, LDA);
            #pragma unroll
            for (int t = 0; t < NT; t++) {
                wmma::fragment<wmma::matrix_b, 16, 16, 16, __nv_bfloat16, wmma::row_major> fb_h, fb_l;
                wmma::load_matrix_sync(fb_h, Bh + (k16 * 16) * LDB + t * 16, LDB);
                wmma::load_matrix_sync(fb_l, Bl + (k16 * 16) * LDB + t * 16, LDB);
                wmma::mma_sync(acc[t], fa_h, fb_h, acc[t]);
                wmma::mma_sync(acc[t], fa_h, fb_l, acc[t]);
                wmma::mma_sync(acc[t], fa_l, fb_h, acc[t]);
            }
        }
    }
    __syncthreads();
    #pragma unroll
    for (int t = 0; t < NT; t++)
        wmma::store_matrix_sync(sOut + (warp * 16) * LDB + t * 16, acc[t], LDB,
                                wmma::mem_row_major);
    __syncthreads();
    #pragma unroll 2
    for (int i = tid * 4; i < 128 * CO; i += 1024) {
        int r = i / CO, c = i & (CO - 1);
        float4 v = *(float4*)&sOut[r * LDB + c];
        *(float4*)&out[(size_t)(rb + r) * CO + c] = v;
    }
}

constexpr int wg_smem(int CO) {
    int lda = 72, ldb = CO + 8;
    int ab = (2 * 128 * lda + 2 * 64 * ldb) * 2;
    int os = 128 * ldb * 4;
    return ab > os ? ab : os;
}

// ---------------- shared gather helper: 4x-unrolled CSR edge accumulation ----------------
__device__ __forceinline__ void gather_row(const unsigned short* __restrict__ bsrc,
                                           const float* __restrict__ bw,
                                           const float* __restrict__ ysm,
                                           int e0, int e1, int lane,
                                           float& a0, float& a1) {
    int j = e0;
    for (; j + 4 <= e1; j += 4) {
        int s0 = bsrc[j], s1 = bsrc[j + 1], s2 = bsrc[j + 2], s3 = bsrc[j + 3];
        float w0 = bw[j], w1 = bw[j + 1], w2 = bw[j + 2], w3 = bw[j + 3];
        float y00 = ysm[s0 * H + lane],      y01 = ysm[s0 * H + lane + 32];
        float y10 = ysm[s1 * H + lane],      y11 = ysm[s1 * H + lane + 32];
        float y20 = ysm[s2 * H + lane],      y21 = ysm[s2 * H + lane + 32];
        float y30 = ysm[s3 * H + lane],      y31 = ysm[s3 * H + lane + 32];
        a0 = fmaf(w0, y00, a0); a1 = fmaf(w0, y01, a1);
        a0 = fmaf(w1, y10, a0); a1 = fmaf(w1, y11, a1);
        a0 = fmaf(w2, y20, a0); a1 = fmaf(w2, y21, a1);
        a0 = fmaf(w3, y30, a0); a1 = fmaf(w3, y31, a1);
    }
    for (; j < e1; j++) {
        int sl = bsrc[j];
        float w = bw[j];
        a0 = fmaf(w, ysm[sl * H + lane],      a0);
        a1 = fmaf(w, ysm[sl * H + lane + 32], a1);
    }
}

// ======================================================================
// agg1: CSR build in smem (bucket region UNIONed with ysm) -> persist to
//       global -> reload region as ysm -> gather from GLOBAL CSR.
// ======================================================================
constexpr int SMEM_AGG1 = NPG*H*4 + NPG*4 + NPG*4 + 512*4;
constexpr int EPT = (EPG + AT - 1) / AT;   // 16 edges max per thread

__global__ void __launch_bounds__(AT, 2) agg1_kernel(
                            const float* __restrict__ xw,
                            const int* __restrict__ src, const int* __restrict__ dstp,
                            const float* __restrict__ ew,
                            const float* __restrict__ bias, const float* __restrict__ gam,
                            const float* __restrict__ bet, float* __restrict__ out,
                            float* __restrict__ dis_out,
                            unsigned short* __restrict__ ebsrc_out,
                            float* __restrict__ ebw_out, int* __restrict__ eoff_out) {
    extern __shared__ float smf[];
    float* ysm = smf;                         // [NPG*H]; FIRST used as bucket space
    float* dsm = ysm + NPG * H;
    int*   cn  = (int*)(dsm + NPG);
    int*   sc  = cn + NPG;
    float* bw  = ysm;                         // [EPG] 32000B
    unsigned short* bsrc = (unsigned short*)(ysm + EPG);  // [EPG] 16000B

    const int g = blockIdx.x;
    const int nb = g * NPG;
    const int eb = g * EPG;
    const int tid = threadIdx.x;
    const int lane = tid & 31;
    const int warp = tid >> 5;

    for (int i = tid; i < NPG; i += AT) cn[i] = 0;
    __syncthreads();

    int pk[EPT];
    #pragma unroll
    for (int u = 0; u < EPT; u++) {
        int e = tid + u * AT;
        pk[u] = -1;
        if (e < EPG) {
            int sl = src[eb + e] - nb;
            int dl = dstp[eb + e] - nb;
            int r  = atomicAdd(&cn[dl], 1);
            pk[u] = sl | (dl << 9) | (r << 18);
        }
    }
    __syncthreads();

    sc[tid] = (tid < NPG) ? cn[tid] : 0;
    __syncthreads();
    #pragma unroll
    for (int off = 1; off < 512; off <<= 1) {
        int v = sc[tid];
        int a = (tid >= off) ? sc[tid - off] : 0;
        __syncthreads();
        sc[tid] = v + a;
        __syncthreads();
    }
    for (int i = tid; i < NPG; i += AT) eoff_out[nb + i] = sc[i];
    __syncthreads();

    #pragma unroll
    for (int u = 0; u < EPT; u++) {
        int e = tid + u * AT;
        if (pk[u] >= 0) {
            int sl = pk[u] & 511;
            int dl = (pk[u] >> 9) & 511;
            int r  = pk[u] >> 18;
            int pos = (dl ? sc[dl - 1] : 0) + r;
            bsrc[pos] = (unsigned short)sl;
            bw[pos]   = ew[eb + e];
        }
    }
    __syncthreads();

    for (int dl = warp; dl < NPG; dl += AW) {
        int e0 = dl ? sc[dl - 1] : 0;
        int e1 = sc[dl];
        float s = 0.f;
        for (int j = e0 + lane; j < e1; j += 32) s += bw[j];
        #pragma unroll
        for (int o = 16; o; o >>= 1) s += __shfl_xor_sync(0xffffffffu, s, o);
        if (lane == 0) {
            float d = rsqrtf(1.f + s);
            dsm[dl] = d;
            dis_out[nb + dl] = d;
        }
    }
    __syncthreads();

    for (int i = tid * 8; i < EPG; i += AT * 8)
        *(uint4*)&ebsrc_out[eb + i] = *(const uint4*)&bsrc[i];
    for (int i = tid * 4; i < EPG; i += AT * 4)
        *(float4*)&ebw_out[eb + i] = *(const float4*)&bw[i];
    __syncthreads();

    for (int i = tid * 4; i < NPG * H; i += AT * 4) {
        int node = i >> 6;
        float4 v = *(const float4*)&xw[(size_t)(nb + node) * H + (i & 63)];
        float d = dsm[node];
        v.x *= d; v.y *= d; v.z *= d; v.w *= d;
        *(float4*)&ysm[i] = v;
    }
    __syncthreads();

    const unsigned short* gb = ebsrc_out + eb;
    const float* gw = ebw_out + eb;
    const float s0 = gam[lane] * BN_RS,      s1 = gam[lane + 32] * BN_RS;
    const float t0 = bet[lane],              t1 = bet[lane + 32];
    const float bb0 = bias[lane],            bb1 = bias[lane + 32];
    for (int dl = warp; dl < NPG; dl += AW) {
        int e0 = dl ? sc[dl - 1] : 0;
        int e1 = sc[dl];
        float a0 = ysm[dl * H + lane];
        float a1 = ysm[dl * H + lane + 32];
        gather_row(gb, gw, ysm, e0, e1, lane, a0, a1);
        float d = dsm[dl];
        float v0 = fmaf(d, a0, bb0);
        float v1 = fmaf(d, a1, bb1);
        v0 = fmaxf(fmaf(v0, s0, t0), 0.f);
        v1 = fmaxf(fmaf(v1, s1, t1), 0.f);
        size_t o = (size_t)(nb + dl) * H;
        out[o + lane] = v0;
        out[o + lane + 32] = v1;
    }
}

// ======================================================================
// agg2: gather + bias/BN/ReLU + fused score + fused top-k, then
//       NODE-COMPACTED layer-3: rank scan, gated h2c [Bg*KEEP,64],
//       rank-space compacted CSR + eoff3c + dis3c
// ======================================================================
constexpr int SMEM_AGG2 = (NPG*H + 2*NPG)*4;

__global__ void __launch_bounds__(AT, 2) agg2_kernel(
                            const float* __restrict__ xw, const float* __restrict__ dis,
                            const unsigned short* __restrict__ ebsrc,
                            const float* __restrict__ ebw, const int* __restrict__ eoff,
                            const float* __restrict__ ew_p,   // pool vector
                            const float* __restrict__ bias, const float* __restrict__ gam,
                            const float* __restrict__ bet, float* __restrict__ out,
                            float* __restrict__ h2c,
                            unsigned short* __restrict__ eb3src_out,
                            float* __restrict__ eb3w_out, int* __restrict__ eoff3_out,
                            float* __restrict__ dis3_out) {
    extern __shared__ float smf[];
    float* ysm = smf;
    float* dsm = ysm + NPG * H;
    float* ssc = dsm + NPG;               // [NPG] scores

    const int g = blockIdx.x;
    const int nb = g * NPG;
    const int eb = g * EPG;
    const int kb = g * KEEP;
    const int tid = threadIdx.x;

    for (int i = tid; i < NPG; i += AT) dsm[i] = dis[nb + i];
    __syncthreads();

    for (int i = tid * 4; i < NPG * H; i += AT * 4) {
        int node = i >> 6;
        float4 v = *(const float4*)&xw[(size_t)(nb + node) * H + (i & 63)];
        float d = dsm[node];
        v.x *= d; v.y *= d; v.z *= d; v.w *= d;
        *(float4*)&ysm[i] = v;
    }
    __syncthreads();

    const int lane = tid & 31;
    const int warp = tid >> 5;
    const float s0 = gam[lane] * BN_RS,      s1 = gam[lane + 32] * BN_RS;
    const float t0 = bet[lane],              t1 = bet[lane + 32];
    const float bb0 = bias[lane],            bb1 = bias[lane + 32];
    const float p0 = ew_p[lane], p1 = ew_p[lane + 32];
    float pn = p0 * p0 + p1 * p1;
    #pragma unroll
    for (int o = 16; o; o >>= 1) pn += __shfl_xor_sync(0xffffffffu, pn, o);
    const float ipn = rsqrtf(pn);

    const unsigned short* gb = ebsrc + eb;
    const float* gw = ebw + eb;
    for (int dl = warp; dl < NPG; dl += AW) {
        int e1 = eoff[nb + dl];
        int e0 = dl ? eoff[nb + dl - 1] : 0;
        float a0 = ysm[dl * H + lane];
        float a1 = ysm[dl * H + lane + 32];
        gather_row(gb, gw, ysm, e0, e1, lane, a0, a1);
        float d = dsm[dl];
        float v0 = fmaf(d, a0, bb0);
        float v1 = fmaf(d, a1, bb1);
        v0 = fmaxf(fmaf(v0, s0, t0), 0.f);
        v1 = fmaxf(fmaf(v1, s1, t1), 0.f);
        size_t o = (size_t)(nb + dl) * H;
        out[o + lane] = v0;
        out[o + lane + 32] = v1;
        float dsc = v0 * p0 + v1 * p1;
        #pragma unroll
        for (int of = 16; of; of >>= 1) dsc += __shfl_xor_sync(0xffffffffu, dsc, of);
        if (lane == 0) ssc[dl] = tanhf(dsc * ipn);
    }
    __syncthreads();   // scores done; ysm now dead -> reuse

    float* sortb = ysm;                                // [512]
    unsigned char* km = (unsigned char*)(ysm + 512);   // [NPG]
    int* cntp = (int*)(ysm + 1024);
    int* rks  = (int*)(ysm + 1536);                    // [512] rank scan
    int* cn3  = (int*)(ysm + 2048);                    // [512]
    float* deg3 = ysm + 2688;                          // [NPG]

    for (int i = tid; i < 512; i += AT) sortb[i] = (i < NPG) ? ssc[i] : -INFINITY;
    if (tid == 0) *cntp = 0;
    __syncthreads();
    // bitonic sort ascending
    #pragma unroll
    for (int k = 2; k <= 512; k <<= 1) {
        #pragma unroll
        for (int j = k >> 1; j > 0; j >>= 1) {
            int ixj = tid ^ j;
            if (ixj > tid) {
                float a = sortb[tid], b = sortb[ixj];
                bool sw = ((tid & k) == 0) ? (a > b) : (a < b);
                if (sw) { sortb[tid] = b; sortb[ixj] = a; }
            }
            __syncthreads();
        }
    }
    float thr = sortb[512 - KEEP];
    int local = 0;
    for (int i = tid; i < NPG; i += AT)
        if (ssc[i] > thr) local++;
    atomicAdd(cntp, local);
    __syncthreads();
    if (tid == 0) {   // tie-break: lowest index first (matches lax.top_k)
        int rem = KEEP - *cntp;
        for (int i = 0; i < NPG; i++) {
            unsigned char m = (ssc[i] > thr) ? 1 : 0;
            if (!m && ssc[i] == thr && rem > 0) { m = 1; rem--; }
            km[i] = m;
        }
    }
    __syncthreads();

    // rank scan: rk[dl] = # kept before dl (exclusive)
    rks[tid] = (tid < NPG && km[tid]) ? 1 : 0;
    __syncthreads();
    #pragma unroll
    for (int off = 1; off < 512; off <<= 1) {
        int v = rks[tid];
        int a = (tid >= off) ? rks[tid - off] : 0;
        __syncthreads();
        rks[tid] = v + a;
        __syncthreads();
    }
    // compacted gated h2c: row kb + rk[dl] = h2[dl] * score[dl]
    for (int dl = warp; dl < NPG; dl += AW) {
        if (!km[dl]) continue;
        int rk = rks[dl] - 1;           // inclusive - self = exclusive for kept
        float sg = ssc[dl];
        size_t si = (size_t)(nb + dl) * H;
        size_t di = (size_t)(kb + rk) * H;
        h2c[di + lane]      = out[si + lane] * sg;
        h2c[di + lane + 32] = out[si + lane + 32] * sg;
    }

    // ---- compacted layer-3 CSR build (rank space) ----
    // phase A: surviving count + degree per kept dst
    for (int dl = warp; dl < NPG; dl += AW) {
        int cnt = 0; float s = 0.f;
        if (km[dl]) {
            int e1 = eoff[nb + dl];
            int e0 = dl ? eoff[nb + dl - 1] : 0;
            for (int j = e0 + lane; j < e1; j += 32) {
                if (km[gb[j]]) { cnt++; s += gw[j]; }
            }
        }
        #pragma unroll
        for (int o = 16; o; o >>= 1) {
            cnt += __shfl_xor_sync(0xffffffffu, cnt, o);
            s   += __shfl_xor_sync(0xffffffffu, s,   o);
        }
        if (lane == 0) { cn3[dl] = cnt; deg3[dl] = s; }
    }
    if (tid >= NPG && tid < 512) cn3[tid] = 0;
    __syncthreads();
    #pragma unroll
    for (int off = 1; off < 512; off <<= 1) {
        int v = cn3[tid];
        int a = (tid >= off) ? cn3[tid - off] : 0;
        __syncthreads();
        cn3[tid] = v + a;
        __syncthreads();
    }
    for (int i = tid; i < NPG; i += AT) {
        if (km[i]) {
            int rk = rks[i] - 1;
            eoff3_out[kb + rk] = cn3[i];
            dis3_out[kb + rk]  = rsqrtf(1.f + deg3[i]);
        }
    }
    __syncthreads();
    // phase B: ballot compaction; srcs stored as RANKS
    unsigned short* c3s = eb3src_out + eb;
    float* c3w = eb3w_out + eb;
    for (int dl = warp; dl < NPG; dl += AW) {
        if (!km[dl]) continue;
        int e1 = eoff[nb + dl];
        int e0 = dl ? eoff[nb + dl - 1] : 0;
        int pos = dl ? cn3[dl - 1] : 0;
        for (int j0 = e0; j0 < e1; j0 += 32) {
            int j = j0 + lane;
            bool act = false; int sl = 0; float w = 0.f;
            if (j < e1) {
                sl = gb[j]; w = gw[j];
                act = (km[sl] != 0);
            }
            unsigned m = __ballot_sync(0xffffffffu, act);
            int off = __popc(m & ((1u << lane) - 1u));
            if (act) {
                c3s[pos + off] = (unsigned short)(rks[sl] - 1);
                c3w[pos + off] = w;
            }
            pos += __popc(m);
        }
    }
}

// ======================================================================
// agg3: fully COMPACTED node space (KEEP=200 rows/graph); gather +
//       BN/ReLU + mean/max readout + FUSED MLP head
// ======================================================================
constexpr int SMEM_AGG3 = (KEEP*H + KEEP)*4 + 2 * AW * 64 * 4;

__global__ void __launch_bounds__(AT, 2) agg3_kernel(
                            const float* __restrict__ xw,      // compacted [NK, 128]
                            const float* __restrict__ dis3,    // compacted [NK]
                            const unsigned short* __restrict__ eb3src,
                            const float* __restrict__ eb3w, const int* __restrict__ eoff3,
                            const float* __restrict__ bias, const float* __restrict__ gam,
                            const float* __restrict__ bet,
                            const float* __restrict__ f1w, const float* __restrict__ f1b,
                            const float* __restrict__ gfc, const float* __restrict__ bfc,
                            const float* __restrict__ f2w, const float* __restrict__ f2b,
                            float* __restrict__ outp) {
    extern __shared__ float smf[];
    float* ysm = smf;                    // [KEEP*H]
    float* dsm = ysm + KEEP * H;         // [KEEP]
    float* psum = dsm + KEEP;            // [AW][64]
    float* pmax = psum + AW * 64;        // [AW][64]

    const int g = blockIdx.x;
    const int kb = g * KEEP;
    const int eb = g * EPG;
    const int tid = threadIdx.x;
    const int lane = tid & 31;
    const int warp = tid >> 5;

    for (int i = tid; i < KEEP; i += AT) dsm[i] = dis3[kb + i];
    __syncthreads();

    const unsigned short* gb = eb3src + eb;
    const float* gw = eb3w + eb;

    float hmean[2], hmax[2];
    #pragma unroll
    for (int hf = 0; hf < 2; hf++) {
        if (hf) __syncthreads();
        // ysm = dis3 * xw3c half
        for (int i = tid * 4; i < KEEP * H; i += AT * 4) {
            int r = i >> 6;
            float4 v = *(const float4*)&xw[(size_t)(kb + r) * H3 + hf * H + (i & 63)];
            float d = dsm[r];
            v.x *= d; v.y *= d; v.z *= d; v.w *= d;
            *(float4*)&ysm[i] = v;
        }
        __syncthreads();
        const int f0 = hf * H + lane, f1 = hf * H + lane + 32;
        const float s0 = gam[f0] * BN_RS, s1 = gam[f1] * BN_RS;
        const float t0 = bet[f0],         t1 = bet[f1];
        const float bb0 = bias[f0],       bb1 = bias[f1];
        float sum0 = 0.f, sum1 = 0.f, mx0 = -INFINITY, mx1 = -INFINITY;
        for (int r = warp; r < KEEP; r += AW) {
            int e1 = eoff3[kb + r];
            int e0 = r ? eoff3[kb + r - 1] : 0;
            float a0 = ysm[r * H + lane];
            float a1 = ysm[r * H + lane + 32];
            gather_row(gb, gw, ysm, e0, e1, lane, a0, a1);
            float d = dsm[r];
            float v0 = fmaf(d, a0, bb0);
            float v1 = fmaf(d, a1, bb1);
            v0 = fmaxf(fmaf(v0, s0, t0), 0.f);
            v1 = fmaxf(fmaf(v1, s1, t1), 0.f);
            sum0 += v0; sum1 += v1;
            mx0 = fmaxf(mx0, v0); mx1 = fmaxf(mx1, v1);
        }
        psum[warp * 64 + lane]      = sum0;
        psum[warp * 64 + lane + 32] = sum1;
        pmax[warp * 64 + lane]      = mx0;
        pmax[warp * 64 + lane + 32] = mx1;
        __syncthreads();
        if (tid < 64) {   // deterministic fixed-order combine, kept in registers
            float s = 0.f, m = -INFINITY;
            #pragma unroll
            for (int w = 0; w < AW; w++) {
                s += psum[w * 64 + tid];
                m = fmaxf(m, pmax[w * 64 + tid]);
            }
            hmean[hf] = s * (1.f / KEEP);
            hmax[hf]  = m;
        }
    }
    __syncthreads();   // partial arrays now dead

    // ---- fused MLP head ----
    float* semb = psum;          // [256] emb = [mean0|mean1|max0|max1]
    float* zz   = pmax;          // [64]
    if (tid < 64) {
        semb[tid]       = hmean[0];
        semb[64 + tid]  = hmean[1];
        semb[128 + tid] = hmax[0];
        semb[192 + tid] = hmax[1];
    }
    __syncthreads();
    if (tid < 64) {
        float acc = f1b[tid];
        #pragma unroll 8
        for (int k = 0; k < 256; k++)
            acc = fmaf(semb[k], f1w[k * 64 + tid], acc);
        acc = fmaf(acc, gfc[tid] * BN_RS, bfc[tid]);
        zz[tid] = fmaxf(acc, 0.f);
    }
    __syncthreads();
    if (tid < 2) {
        float o = f2b[tid];
        #pragma unroll 8
        for (int k = 0; k < 64; k++)
            o = fmaf(zz[k], f2w[k * 2 + tid], o);
        outp[g * 2 + tid] = o;
    }
}

// ---------------- launch ----------------
extern "C" void kernel_launch(void* const* d_in, const int* in_sizes, int n_in,
                              void* d_out, int out_size) {
    const float* x   = (const float*)d_in[0];
    const int*   ei  = (const int*)  d_in[1];
    const float* ew  = (const float*)d_in[2];
    const float* W1  = (const float*)d_in[4];
    const float* b1  = (const float*)d_in[5];
    const float* g1  = (const float*)d_in[6];
    const float* bt1 = (const float*)d_in[7];
    const float* W2  = (const float*)d_in[8];
    const float* b2  = (const float*)d_in[9];
    const float* g2  = (const float*)d_in[10];
    const float* bt2 = (const float*)d_in[11];
    const float* pp  = (const float*)d_in[12];
    const float* W3  = (const float*)d_in[13];
    const float* b3  = (const float*)d_in[14];
    const float* g3  = (const float*)d_in[15];
    const float* bt3 = (const float*)d_in[16];
    const float* f1w = (const float*)d_in[17];
    const float* f1b = (const float*)d_in[18];
    const float* gfc = (const float*)d_in[19];
    const float* bfc = (const float*)d_in[20];
    const float* f2w = (const float*)d_in[21];
    const float* f2b = (const float*)d_in[22];
    float* out = (float*)d_out;

    const int* src = ei;
    const int* dst = ei + Etot;

    float *p_xw1, *p_h1, *p_xw2, *p_h2, *p_xw3;
    float *p_dis, *p_dis3, *p_ebw, *p_eb3w;
    unsigned short *p_ebsrc, *p_eb3src;
    int *p_eoff, *p_eoff3;
    __nv_bfloat16 *p_w1h, *p_w1l, *p_w2h, *p_w2l, *p_w3h, *p_w3l;
    cudaGetSymbolAddress((void**)&p_xw1,  g_xw1);
    cudaGetSymbolAddress((void**)&p_h1,   g_h1);
    cudaGetSymbolAddress((void**)&p_xw2,  g_xw2);
    cudaGetSymbolAddress((void**)&p_h2,   g_h2);
    cudaGetSymbolAddress((void**)&p_xw3,  g_xw3);
    cudaGetSymbolAddress((void**)&p_dis,  g_dis);
    cudaGetSymbolAddress((void**)&p_dis3, g_dis3);
    cudaGetSymbolAddress((void**)&p_ebsrc,g_ebsrc);
    cudaGetSymbolAddress((void**)&p_ebw,  g_ebw);
    cudaGetSymbolAddress((void**)&p_eoff, g_eoff);
    cudaGetSymbolAddress((void**)&p_eb3src,g_eb3src);
    cudaGetSymbolAddress((void**)&p_eb3w, g_eb3w);
    cudaGetSymbolAddress((void**)&p_eoff3,g_eoff3);
    cudaGetSymbolAddress((void**)&p_w1h,  g_w1h);
    cudaGetSymbolAddress((void**)&p_w1l,  g_w1l);
    cudaGetSymbolAddress((void**)&p_w2h,  g_w2h);
    cudaGetSymbolAddress((void**)&p_w2l,  g_w2l);
    cudaGetSymbolAddress((void**)&p_w3h,  g_w3h);
    cudaGetSymbolAddress((void**)&p_w3l,  g_w3l);

    constexpr int SM1 = wg_smem(64);
    constexpr int SM3 = wg_smem(128);
    cudaFuncSetAttribute((const void*)wgemm_kernel<64, 400>,
                         cudaFuncAttributeMaxDynamicSharedMemorySize, SM1);
    cudaFuncSetAttribute((const void*)wgemm_kernel<64, 64>,
                         cudaFuncAttributeMaxDynamicSharedMemorySize, SM1);
    cudaFuncSetAttribute((const void*)wgemm_kernel<128, 64>,
                         cudaFuncAttributeMaxDynamicSharedMemorySize, SM3);
    cudaFuncSetAttribute(agg1_kernel, cudaFuncAttributeMaxDynamicSharedMemorySize, SMEM_AGG1);
    cudaFuncSetAttribute(agg2_kernel, cudaFuncAttributeMaxDynamicSharedMemorySize, SMEM_AGG2);
    cudaFuncSetAttribute(agg3_kernel, cudaFuncAttributeMaxDynamicSharedMemorySize, SMEM_AGG3);

    // 0: weight split
    wconv_all_kernel<<<(448*64 + 64*64 + 64*128 + 255) / 256, 256>>>(
        W1, W2, W3, p_w1h, p_w1l, p_w2h, p_w2l, p_w3h, p_w3l);

    // 1: GCN1 GEMM
    wgemm_kernel<64, 400><<<Ntot / 128, 256, SM1>>>(x, p_w1h, p_w1l, p_xw1);
    // 2: GCN1 aggregation
    agg1_kernel<<<Bg, AT, SMEM_AGG1>>>(p_xw1, src, dst, ew, b1, g1, bt1, p_h1,
                                       p_dis, p_ebsrc, p_ebw, p_eoff);
    // 3: GCN2 GEMM
    wgemm_kernel<64, 64><<<Ntot / 128, 256, SM1>>>(p_h1, p_w2h, p_w2l, p_xw2);
    // 4: GCN2 aggregation (score + topk + node-compacted h2c + rank CSR)
    //    h2c overwrites g_h1 (dead after launch 3)
    agg2_kernel<<<Bg, AT, SMEM_AGG2>>>(p_xw2, p_dis, p_ebsrc, p_ebw, p_eoff, pp,
                                       b2, g2, bt2, p_h2, p_h1,
                                       p_eb3src, p_eb3w, p_eoff3, p_dis3);
    // 5: GCN3 GEMM on COMPACTED rows (half the work)
    wgemm_kernel<128, 64><<<NK / 128, 256, SM3>>>(p_h1, p_w3h, p_w3l, p_xw3);
    // 6: GCN3 aggregation in compacted space + readout + FUSED head
    agg3_kernel<<<Bg, AT, SMEM_AGG3>>>(p_xw3, p_dis3, p_eb3src, p_eb3w, p_eoff3,
                                       b3, g3, bt3, f1w, f1b, gfc, bfc, f2w, f2b, out);
}